// round 1
// baseline (speedup 1.0000x reference)
#include <cuda_runtime.h>

#define BATCH   8192
#define CAR     8
#define NAGENT  64
#define HID     256
#define ENC_OUT 257
#define QIN     265
#define ADIM    30

// scratch: x = concat(self(8), enc_sum(257)) per batch row
__device__ float g_x[BATCH * QIN];

// ---------------------------------------------------------------------------
// Kernel 1: per-batch-element encoder.
//   H = relu(surr @ W1 + b1)           (64 x 256), kept in smem
//   E = relu(H @ W2 + b2)              (64 x 257)
//   x[b] = [self(8), sum_n(E * valid)] (265)
// ---------------------------------------------------------------------------
__global__ void __launch_bounds__(256, 1) enc_kernel(
    const float* __restrict__ s, const float* __restrict__ W1,
    const float* __restrict__ b1, const float* __restrict__ W2,
    const float* __restrict__ b2)
{
    extern __shared__ float sm[];
    float* shH     = sm;                        // 64*256  = 16384
    float* shB     = shH + NAGENT * HID;        // 256*64  = 16384
    float* shW1    = shB + HID * 64;            // 8*256   = 2048
    float* shSurr  = shW1 + CAR * HID;          // 64*8    = 512
    float* shValid = shSurr + NAGENT * CAR;     // 64
    float* shB1    = shValid + NAGENT;          // 256
    float* shRed   = shB1 + HID;                // 16*64   = 1024
    // total 36672 floats = 146688 bytes

    const int b   = blockIdx.x;
    const int tid = threadIdx.x;
    const float* srow = s + (size_t)b * (CAR + NAGENT * CAR);

    for (int i = tid; i < NAGENT * CAR; i += 256) shSurr[i] = srow[CAR + i];
    for (int i = tid; i < CAR * HID;   i += 256) shW1[i]   = W1[i];
    shB1[tid] = b1[tid];
    __syncthreads();

    // validity mask: agent invalid if any feature == -1.0
    if (tid < NAGENT) {
        float v = 1.0f;
        #pragma unroll
        for (int c = 0; c < CAR; c++)
            if (shSurr[tid * CAR + c] == -1.0f) v = 0.0f;
        shValid[tid] = v;
    }

    // H: thread tid owns hidden unit tid for all 64 agents
    {
        float w[CAR];
        #pragma unroll
        for (int c = 0; c < CAR; c++) w[c] = shW1[c * HID + tid];
        const float bb = shB1[tid];
        for (int n = 0; n < NAGENT; n++) {
            float acc = bb;
            #pragma unroll
            for (int c = 0; c < CAR; c++)
                acc = fmaf(shSurr[n * CAR + c], w[c], acc);
            shH[n * HID + tid] = fmaxf(acc, 0.0f);
        }
    }
    __syncthreads();   // H + valid ready

    const int tx = tid & 15;       // col group (4 cols)
    const int ty = tid >> 4;       // row group (4 rows)
    const float* Hp0 = shH + (ty * 4 + 0) * HID;
    const float* Hp1 = Hp0 + HID;
    const float* Hp2 = Hp1 + HID;
    const float* Hp3 = Hp2 + HID;
    const float v0 = shValid[ty * 4 + 0];
    const float v1 = shValid[ty * 4 + 1];
    const float v2 = shValid[ty * 4 + 2];
    const float v3 = shValid[ty * 4 + 3];

    // main GEMM over cols [0,256) in 4 chunks of 64
    for (int nb = 0; nb < 256; nb += 64) {
        __syncthreads();   // prior shB readers / shRed readers done
        for (int i = tid; i < HID * 64; i += 256) {
            int k = i >> 6, j = i & 63;
            shB[i] = W2[k * ENC_OUT + nb + j];
        }
        __syncthreads();

        float acc[4][4];
        #pragma unroll
        for (int r = 0; r < 4; r++)
            #pragma unroll
            for (int c = 0; c < 4; c++) acc[r][c] = 0.0f;

        #pragma unroll 8
        for (int k = 0; k < HID; k++) {
            float4 bv = *(const float4*)(shB + (k << 6) + (tx << 2));
            float h0 = Hp0[k], h1 = Hp1[k], h2 = Hp2[k], h3 = Hp3[k];
            acc[0][0] = fmaf(h0, bv.x, acc[0][0]);
            acc[0][1] = fmaf(h0, bv.y, acc[0][1]);
            acc[0][2] = fmaf(h0, bv.z, acc[0][2]);
            acc[0][3] = fmaf(h0, bv.w, acc[0][3]);
            acc[1][0] = fmaf(h1, bv.x, acc[1][0]);
            acc[1][1] = fmaf(h1, bv.y, acc[1][1]);
            acc[1][2] = fmaf(h1, bv.z, acc[1][2]);
            acc[1][3] = fmaf(h1, bv.w, acc[1][3]);
            acc[2][0] = fmaf(h2, bv.x, acc[2][0]);
            acc[2][1] = fmaf(h2, bv.y, acc[2][1]);
            acc[2][2] = fmaf(h2, bv.z, acc[2][2]);
            acc[2][3] = fmaf(h2, bv.w, acc[2][3]);
            acc[3][0] = fmaf(h3, bv.x, acc[3][0]);
            acc[3][1] = fmaf(h3, bv.y, acc[3][1]);
            acc[3][2] = fmaf(h3, bv.z, acc[3][2]);
            acc[3][3] = fmaf(h3, bv.w, acc[3][3]);
        }

        // epilogue: bias -> relu -> mask -> partial sum over 4 rows
        const int colb = nb + (tx << 2);
        #pragma unroll
        for (int c = 0; c < 4; c++) {
            float e = b2[colb + c];
            float p = fmaxf(acc[0][c] + e, 0.0f) * v0
                    + fmaxf(acc[1][c] + e, 0.0f) * v1
                    + fmaxf(acc[2][c] + e, 0.0f) * v2
                    + fmaxf(acc[3][c] + e, 0.0f) * v3;
            shRed[ty * 64 + (tx << 2) + c] = p;
        }
        __syncthreads();
        if (tid < 64) {
            float t = 0.0f;
            #pragma unroll
            for (int q = 0; q < 16; q++) t += shRed[q * 64 + tid];
            g_x[(size_t)b * QIN + CAR + nb + tid] = t;
        }
    }

    // final column 256: warp-per-row dot products
    __syncthreads();
    if (tid < HID) shB[tid] = W2[tid * ENC_OUT + 256];
    __syncthreads();
    {
        const int lane = tid & 31;
        const int w    = tid >> 5;
        const float blast = b2[256];
        float wsum = 0.0f;
        #pragma unroll
        for (int rr = 0; rr < 8; rr++) {
            int row = w * 8 + rr;
            const float* hp = shH + row * HID;
            float d = 0.0f;
            for (int k = lane; k < HID; k += 32) d = fmaf(hp[k], shB[k], d);
            #pragma unroll
            for (int off = 16; off > 0; off >>= 1)
                d += __shfl_down_sync(0xffffffffu, d, off);
            if (lane == 0) wsum += fmaxf(d + blast, 0.0f) * shValid[row];
        }
        if (lane == 0) shRed[w] = wsum;
    }
    __syncthreads();
    if (tid == 0) {
        float t = 0.0f;
        #pragma unroll
        for (int q = 0; q < 8; q++) t += shRed[q];
        g_x[(size_t)b * QIN + CAR + 256] = t;
    }
    if (tid < CAR) g_x[(size_t)b * QIN + tid] = srow[tid];
}

// ---------------------------------------------------------------------------
// Kernel 2: Q head, 8 batch rows per CTA.
//   hq = relu(x @ Qw1 + Qb1); q = hq @ Qw2 + Qb2
// ---------------------------------------------------------------------------
__global__ void __launch_bounds__(256) qhead_kernel(
    const float* __restrict__ Qw1, const float* __restrict__ Qb1,
    const float* __restrict__ Qw2, const float* __restrict__ Qb2,
    float* __restrict__ out)
{
    __shared__ float shX[8 * QIN];       // 8480 B
    __shared__ float shHq[8 * HID];      // 8192 B
    __shared__ float shW2[HID * ADIM];   // 30720 B

    const int b0  = blockIdx.x * 8;
    const int tid = threadIdx.x;

    for (int i = tid; i < 8 * QIN;    i += 256) shX[i]  = g_x[(size_t)b0 * QIN + i];
    for (int i = tid; i < HID * ADIM; i += 256) shW2[i] = Qw2[i];
    __syncthreads();

    // layer 1: thread tid owns hidden unit tid for all 8 rows
    float acc[8];
    {
        const float qb = Qb1[tid];
        #pragma unroll
        for (int r = 0; r < 8; r++) acc[r] = qb;
        #pragma unroll 5
        for (int k = 0; k < QIN; k++) {
            float wv = Qw1[k * HID + tid];
            #pragma unroll
            for (int r = 0; r < 8; r++)
                acc[r] = fmaf(shX[r * QIN + k], wv, acc[r]);
        }
        #pragma unroll
        for (int r = 0; r < 8; r++) shHq[r * HID + tid] = fmaxf(acc[r], 0.0f);
    }
    __syncthreads();

    // layer 2: 240 outputs (8 rows x 30 cols)
    if (tid < 8 * ADIM) {
        int r = tid / ADIM, c = tid - r * ADIM;
        float a = Qb2[c];
        const float* hp = shHq + r * HID;
        #pragma unroll 8
        for (int k = 0; k < HID; k++)
            a = fmaf(hp[k], shW2[k * ADIM + c], a);
        out[(size_t)(b0 + r) * ADIM + c] = a;
    }
}

// ---------------------------------------------------------------------------
extern "C" void kernel_launch(void* const* d_in, const int* in_sizes, int n_in,
                              void* d_out, int out_size)
{
    const float* s   = (const float*)d_in[0];
    const float* W1  = (const float*)d_in[1];
    const float* b1  = (const float*)d_in[2];
    const float* W2  = (const float*)d_in[3];
    const float* b2  = (const float*)d_in[4];
    const float* Qw1 = (const float*)d_in[5];
    const float* Qb1 = (const float*)d_in[6];
    const float* Qw2 = (const float*)d_in[7];
    const float* Qb2 = (const float*)d_in[8];
    float* out = (float*)d_out;

    const int smem_bytes = 36672 * (int)sizeof(float);  // 146688
    cudaFuncSetAttribute(enc_kernel,
                         cudaFuncAttributeMaxDynamicSharedMemorySize, smem_bytes);

    enc_kernel<<<BATCH, 256, smem_bytes>>>(s, W1, b1, W2, b2);
    qhead_kernel<<<BATCH / 8, 256>>>(Qw1, Qb1, Qw2, Qb2, out);
}

// round 2
// speedup vs baseline: 1.0005x; 1.0005x over previous
#include <cuda_runtime.h>

#define BATCH   8192
#define CAR     8
#define NAGENT  64
#define HID     256
#define ENC_OUT 257
#define QIN     265
#define ADIM    30

// scratch: x = concat(self(8), enc_sum(257)) per batch row
__device__ float g_x[BATCH * QIN];

// ---------------------------------------------------------------------------
// Kernel 1: per-batch-element encoder.
//   H = relu(surr @ W1 + b1)           (64 x 256), kept in smem
//   E = relu(H @ W2 + b2)              (64 x 257)
//   x[b] = [self(8), sum_n(E * valid)] (265)
// ---------------------------------------------------------------------------
__global__ void __launch_bounds__(256, 1) enc_kernel(
    const float* __restrict__ s, const float* __restrict__ W1,
    const float* __restrict__ b1, const float* __restrict__ W2,
    const float* __restrict__ b2)
{
    extern __shared__ float sm[];
    float* shH     = sm;                        // 64*256  = 16384
    float* shB     = shH + NAGENT * HID;        // 256*64  = 16384
    float* shW1    = shB + HID * 64;            // 8*256   = 2048
    float* shSurr  = shW1 + CAR * HID;          // 64*8    = 512
    float* shValid = shSurr + NAGENT * CAR;     // 64
    float* shB1    = shValid + NAGENT;          // 256
    float* shRed   = shB1 + HID;                // 16*64   = 1024
    // total 36672 floats = 146688 bytes

    const int b   = blockIdx.x;
    const int tid = threadIdx.x;
    const float* srow = s + (size_t)b * (CAR + NAGENT * CAR);

    for (int i = tid; i < NAGENT * CAR; i += 256) shSurr[i] = srow[CAR + i];
    for (int i = tid; i < CAR * HID;   i += 256) shW1[i]   = W1[i];
    shB1[tid] = b1[tid];
    __syncthreads();

    // validity mask: agent invalid if any feature == -1.0
    if (tid < NAGENT) {
        float v = 1.0f;
        #pragma unroll
        for (int c = 0; c < CAR; c++)
            if (shSurr[tid * CAR + c] == -1.0f) v = 0.0f;
        shValid[tid] = v;
    }

    // H: thread tid owns hidden unit tid for all 64 agents
    {
        float w[CAR];
        #pragma unroll
        for (int c = 0; c < CAR; c++) w[c] = shW1[c * HID + tid];
        const float bb = shB1[tid];
        for (int n = 0; n < NAGENT; n++) {
            float acc = bb;
            #pragma unroll
            for (int c = 0; c < CAR; c++)
                acc = fmaf(shSurr[n * CAR + c], w[c], acc);
            shH[n * HID + tid] = fmaxf(acc, 0.0f);
        }
    }
    __syncthreads();   // H + valid ready

    const int tx = tid & 15;       // col group (4 cols)
    const int ty = tid >> 4;       // row group (4 rows)
    const float* Hp0 = shH + (ty * 4 + 0) * HID;
    const float* Hp1 = Hp0 + HID;
    const float* Hp2 = Hp1 + HID;
    const float* Hp3 = Hp2 + HID;
    const float v0 = shValid[ty * 4 + 0];
    const float v1 = shValid[ty * 4 + 1];
    const float v2 = shValid[ty * 4 + 2];
    const float v3 = shValid[ty * 4 + 3];

    // main GEMM over cols [0,256) in 4 chunks of 64
    for (int nb = 0; nb < 256; nb += 64) {
        __syncthreads();   // prior shB readers / shRed readers done
        for (int i = tid; i < HID * 64; i += 256) {
            int k = i >> 6, j = i & 63;
            shB[i] = W2[k * ENC_OUT + nb + j];
        }
        __syncthreads();

        float acc[4][4];
        #pragma unroll
        for (int r = 0; r < 4; r++)
            #pragma unroll
            for (int c = 0; c < 4; c++) acc[r][c] = 0.0f;

        #pragma unroll 8
        for (int k = 0; k < HID; k++) {
            float4 bv = *(const float4*)(shB + (k << 6) + (tx << 2));
            float h0 = Hp0[k], h1 = Hp1[k], h2 = Hp2[k], h3 = Hp3[k];
            acc[0][0] = fmaf(h0, bv.x, acc[0][0]);
            acc[0][1] = fmaf(h0, bv.y, acc[0][1]);
            acc[0][2] = fmaf(h0, bv.z, acc[0][2]);
            acc[0][3] = fmaf(h0, bv.w, acc[0][3]);
            acc[1][0] = fmaf(h1, bv.x, acc[1][0]);
            acc[1][1] = fmaf(h1, bv.y, acc[1][1]);
            acc[1][2] = fmaf(h1, bv.z, acc[1][2]);
            acc[1][3] = fmaf(h1, bv.w, acc[1][3]);
            acc[2][0] = fmaf(h2, bv.x, acc[2][0]);
            acc[2][1] = fmaf(h2, bv.y, acc[2][1]);
            acc[2][2] = fmaf(h2, bv.z, acc[2][2]);
            acc[2][3] = fmaf(h2, bv.w, acc[2][3]);
            acc[3][0] = fmaf(h3, bv.x, acc[3][0]);
            acc[3][1] = fmaf(h3, bv.y, acc[3][1]);
            acc[3][2] = fmaf(h3, bv.z, acc[3][2]);
            acc[3][3] = fmaf(h3, bv.w, acc[3][3]);
        }

        // epilogue: bias -> relu -> mask -> partial sum over 4 rows
        const int colb = nb + (tx << 2);
        #pragma unroll
        for (int c = 0; c < 4; c++) {
            float e = b2[colb + c];
            float p = fmaxf(acc[0][c] + e, 0.0f) * v0
                    + fmaxf(acc[1][c] + e, 0.0f) * v1
                    + fmaxf(acc[2][c] + e, 0.0f) * v2
                    + fmaxf(acc[3][c] + e, 0.0f) * v3;
            shRed[ty * 64 + (tx << 2) + c] = p;
        }
        __syncthreads();
        if (tid < 64) {
            float t = 0.0f;
            #pragma unroll
            for (int q = 0; q < 16; q++) t += shRed[q * 64 + tid];
            g_x[(size_t)b * QIN + CAR + nb + tid] = t;
        }
    }

    // final column 256: warp-per-row dot products
    __syncthreads();
    if (tid < HID) shB[tid] = W2[tid * ENC_OUT + 256];
    __syncthreads();
    {
        const int lane = tid & 31;
        const int w    = tid >> 5;
        const float blast = b2[256];
        float wsum = 0.0f;
        #pragma unroll
        for (int rr = 0; rr < 8; rr++) {
            int row = w * 8 + rr;
            const float* hp = shH + row * HID;
            float d = 0.0f;
            for (int k = lane; k < HID; k += 32) d = fmaf(hp[k], shB[k], d);
            #pragma unroll
            for (int off = 16; off > 0; off >>= 1)
                d += __shfl_down_sync(0xffffffffu, d, off);
            if (lane == 0) wsum += fmaxf(d + blast, 0.0f) * shValid[row];
        }
        if (lane == 0) shRed[w] = wsum;
    }
    __syncthreads();
    if (tid == 0) {
        float t = 0.0f;
        #pragma unroll
        for (int q = 0; q < 8; q++) t += shRed[q];
        g_x[(size_t)b * QIN + CAR + 256] = t;
    }
    if (tid < CAR) g_x[(size_t)b * QIN + tid] = srow[tid];
}

// ---------------------------------------------------------------------------
// Kernel 2: Q head, 8 batch rows per CTA.
//   hq = relu(x @ Qw1 + Qb1); q = hq @ Qw2 + Qb2
// ---------------------------------------------------------------------------
__global__ void __launch_bounds__(256) qhead_kernel(
    const float* __restrict__ Qw1, const float* __restrict__ Qb1,
    const float* __restrict__ Qw2, const float* __restrict__ Qb2,
    float* __restrict__ out)
{
    __shared__ float shX[8 * QIN];       // 8480 B
    __shared__ float shHq[8 * HID];      // 8192 B
    __shared__ float shW2[HID * ADIM];   // 30720 B

    const int b0  = blockIdx.x * 8;
    const int tid = threadIdx.x;

    for (int i = tid; i < 8 * QIN;    i += 256) shX[i]  = g_x[(size_t)b0 * QIN + i];
    for (int i = tid; i < HID * ADIM; i += 256) shW2[i] = Qw2[i];
    __syncthreads();

    // layer 1: thread tid owns hidden unit tid for all 8 rows
    float acc[8];
    {
        const float qb = Qb1[tid];
        #pragma unroll
        for (int r = 0; r < 8; r++) acc[r] = qb;
        #pragma unroll 5
        for (int k = 0; k < QIN; k++) {
            float wv = Qw1[k * HID + tid];
            #pragma unroll
            for (int r = 0; r < 8; r++)
                acc[r] = fmaf(shX[r * QIN + k], wv, acc[r]);
        }
        #pragma unroll
        for (int r = 0; r < 8; r++) shHq[r * HID + tid] = fmaxf(acc[r], 0.0f);
    }
    __syncthreads();

    // layer 2: 240 outputs (8 rows x 30 cols)
    if (tid < 8 * ADIM) {
        int r = tid / ADIM, c = tid - r * ADIM;
        float a = Qb2[c];
        const float* hp = shHq + r * HID;
        #pragma unroll 8
        for (int k = 0; k < HID; k++)
            a = fmaf(hp[k], shW2[k * ADIM + c], a);
        out[(size_t)(b0 + r) * ADIM + c] = a;
    }
}

// ---------------------------------------------------------------------------
extern "C" void kernel_launch(void* const* d_in, const int* in_sizes, int n_in,
                              void* d_out, int out_size)
{
    const float* s   = (const float*)d_in[0];
    const float* W1  = (const float*)d_in[1];
    const float* b1  = (const float*)d_in[2];
    const float* W2  = (const float*)d_in[3];
    const float* b2  = (const float*)d_in[4];
    const float* Qw1 = (const float*)d_in[5];
    const float* Qb1 = (const float*)d_in[6];
    const float* Qw2 = (const float*)d_in[7];
    const float* Qb2 = (const float*)d_in[8];
    float* out = (float*)d_out;

    const int smem_bytes = 36672 * (int)sizeof(float);  // 146688
    cudaFuncSetAttribute(enc_kernel,
                         cudaFuncAttributeMaxDynamicSharedMemorySize, smem_bytes);

    enc_kernel<<<BATCH, 256, smem_bytes>>>(s, W1, b1, W2, b2);
    qhead_kernel<<<BATCH / 8, 256>>>(Qw1, Qb1, Qw2, Qb2, out);
}

// round 4
// speedup vs baseline: 2.4327x; 2.4315x over previous
#include <cuda_runtime.h>
#include <cuda_bf16.h>
#include <cstdint>

#define BATCH 8192
#define CAR   8
#define HID   256
#define QIN   265
#define ADIM  30
#define SROW  520

// ---- smem offsets (bytes) ----
#define SM_BHI   0         // 128n x 272halfs bf16  = 69632
#define SM_BLO   69632     // 69632
#define SM_HHI   139264    // 128r x 144halfs bf16  = 36864 (one K-half)
#define SM_HLO   176128    // 36864
#define SM_W1T   212992    // 256k x 8c fp32        = 8192
#define SM_B1    221184    // 1024
#define SM_B2    222208    // 129 floats (pad 528)
#define SM_WLAST 222736    // 1024
#define SM_SURR  223760    // 4096
#define SM_VALID 227856    // 512
#define SM_DOTP  228368    // 1024 (low 512 aliased as sCol)
#define SM_PART  229392    // 2048
#define SM_TOTAL 231440

__device__ float g_x[BATCH * QIN];
__device__ __align__(16) uint32_t g_Bhi[2 * 128 * 128];  // [nh][n][kword-permuted]
__device__ __align__(16) uint32_t g_Blo[2 * 128 * 128];

// ---------------------------------------------------------------------------
__device__ __forceinline__ uint32_t cvt_bf2(float lo, float hi) {
    uint32_t u;
    asm("cvt.rn.satfinite.bf16x2.f32 %0, %1, %2;" : "=r"(u) : "f"(hi), "f"(lo));
    return u;
}
__device__ __forceinline__ void mma_bf16(float& c0, float& c1, float& c2, float& c3,
                                         uint32_t a0, uint32_t a1, uint32_t a2, uint32_t a3,
                                         uint32_t b0, uint32_t b1) {
    asm volatile(
        "mma.sync.aligned.m16n8k16.row.col.f32.bf16.bf16.f32 "
        "{%0,%1,%2,%3}, {%4,%5,%6,%7}, {%8,%9}, {%0,%1,%2,%3};"
        : "+f"(c0), "+f"(c1), "+f"(c2), "+f"(c3)
        : "r"(a0), "r"(a1), "r"(a2), "r"(a3), "r"(b0), "r"(b1));
}

// ---------------------------------------------------------------------------
// prep: W2 -> bf16 hi/lo, [nh][n][k] with k permuted so word (s*8 + q*2 + h2)
// holds k pair { s*16 + 2*(h2*4+q), +1 }.  One uint2 = one mma B fragment.
// ---------------------------------------------------------------------------
__global__ void prep_kernel(const float* __restrict__ W2) {
    int idx = blockIdx.x * 256 + threadIdx.x;   // [0, 32768)
    int nh = idx >> 14;
    int n  = (idx >> 7) & 127;
    int wd = idx & 127;
    int s  = wd >> 3;
    int rem = wd & 7;
    int q = rem >> 1, h2 = rem & 1;
    int k0 = s * 16 + 2 * (h2 * 4 + q);
    int ncol = nh * 128 + n;
    float f0 = W2[(size_t)k0 * 257 + ncol];
    float f1 = W2[(size_t)(k0 + 1) * 257 + ncol];
    uint32_t wh = cvt_bf2(f0, f1);
    float r0 = f0 - __uint_as_float(wh << 16);
    float r1 = f1 - __uint_as_float(wh & 0xffff0000u);
    g_Bhi[idx] = wh;
    g_Blo[idx] = cvt_bf2(r0, r1);
}

// ---------------------------------------------------------------------------
// encoder: CTA = (group of 16 batch elems) x (N-half). 8 tiles of M=128 rows.
// ---------------------------------------------------------------------------
__global__ void __launch_bounds__(256, 1) enc_kernel(
    const float* __restrict__ s, const float* __restrict__ W1,
    const float* __restrict__ b1, const float* __restrict__ W2,
    const float* __restrict__ b2)
{
    extern __shared__ char smem[];
    const int tid = threadIdx.x;
    const int nh  = blockIdx.x & 1;
    const int grp = blockIdx.x >> 1;
    const int w    = tid >> 5, lane = tid & 31;
    const int wr   = w & 3,   wc   = w >> 2;
    const int tq   = lane >> 2, tm = lane & 3;
    const int r    = tid & 127, sub = tid >> 7;

    float* sW1t   = (float*)(smem + SM_W1T);
    float* sB1    = (float*)(smem + SM_B1);
    float* sB2    = (float*)(smem + SM_B2);
    float* sWlast = (float*)(smem + SM_WLAST);
    float* sSurr  = (float*)(smem + SM_SURR);
    float* sValid = (float*)(smem + SM_VALID);
    float* sDotp  = (float*)(smem + SM_DOTP);
    float* sCol   = (float*)(smem + SM_DOTP);   // alias (safe: see epilogue)
    float* sPart  = (float*)(smem + SM_PART);

    // ---- prologue: resident B slab (padded rows: 272 halfs = 34 uint4) ----
    {
        const uint4* srcH = (const uint4*)(g_Bhi + nh * 16384);
        const uint4* srcL = (const uint4*)(g_Blo + nh * 16384);
        uint4* dH = (uint4*)(smem + SM_BHI);
        uint4* dL = (uint4*)(smem + SM_BLO);
        #pragma unroll
        for (int i = tid; i < 4096; i += 256) {
            int n = i >> 5, w4 = i & 31;
            dH[n * 34 + w4] = srcH[i];
            dL[n * 34 + w4] = srcL[i];
        }
    }
    for (int i = tid; i < CAR * HID; i += 256) {
        int c = i >> 8, k = i & 255;
        sW1t[k * 8 + c] = W1[i];
    }
    sB1[tid] = b1[tid];
    for (int i = tid; i < 129; i += 256)
        sB2[i] = (i < 128) ? b2[nh * 128 + i] : b2[256];
    sWlast[tid] = W2[(size_t)tid * 257 + 256];
    __syncthreads();

    for (int t = 0; t < 8; t++) {
        const int b0 = grp * 16 + t * 2;

        // ---- surr load (2 elems x 512 floats) ----
        {
            int e = tid >> 7, j = tid & 127;
            ((float4*)sSurr)[e * 128 + j] =
                ((const float4*)(s + (size_t)(b0 + e) * SROW + CAR))[j];
        }
        __syncthreads();

        const float4 s0 = ((const float4*)sSurr)[r * 2];
        const float4 s1 = ((const float4*)sSurr)[r * 2 + 1];
        if (tid < 128) {
            float v = 1.0f;
            if (s0.x == -1.f || s0.y == -1.f || s0.z == -1.f || s0.w == -1.f ||
                s1.x == -1.f || s1.y == -1.f || s1.z == -1.f || s1.w == -1.f) v = 0.f;
            sValid[tid] = v;
        }

        float acc[8][2][4];
        #pragma unroll
        for (int nt = 0; nt < 8; nt++)
            #pragma unroll
            for (int mt = 0; mt < 2; mt++)
                #pragma unroll
                for (int c = 0; c < 4; c++) acc[nt][mt][c] = 0.f;
        float dotl = 0.f;

        for (int p = 0; p < 2; p++) {
            // ---- H phase: thread (r, sub) computes k in [p*128+sub*64, +64) ----
            #pragma unroll 4
            for (int jj = 0; jj < 32; jj++) {
                int kl = sub * 64 + 2 * jj;
                int kg = p * 128 + kl;
                float4 wa0 = *(const float4*)(sW1t + kg * 8);
                float4 wa1 = *(const float4*)(sW1t + kg * 8 + 4);
                float4 wb0 = *(const float4*)(sW1t + kg * 8 + 8);
                float4 wb1 = *(const float4*)(sW1t + kg * 8 + 12);
                float f0 = sB1[kg], f1 = sB1[kg + 1];
                f0 = fmaf(wa0.x, s0.x, f0); f0 = fmaf(wa0.y, s0.y, f0);
                f0 = fmaf(wa0.z, s0.z, f0); f0 = fmaf(wa0.w, s0.w, f0);
                f0 = fmaf(wa1.x, s1.x, f0); f0 = fmaf(wa1.y, s1.y, f0);
                f0 = fmaf(wa1.z, s1.z, f0); f0 = fmaf(wa1.w, s1.w, f0);
                f1 = fmaf(wb0.x, s0.x, f1); f1 = fmaf(wb0.y, s0.y, f1);
                f1 = fmaf(wb0.z, s0.z, f1); f1 = fmaf(wb0.w, s0.w, f1);
                f1 = fmaf(wb1.x, s1.x, f1); f1 = fmaf(wb1.y, s1.y, f1);
                f1 = fmaf(wb1.z, s1.z, f1); f1 = fmaf(wb1.w, s1.w, f1);
                f0 = fmaxf(f0, 0.f); f1 = fmaxf(f1, 0.f);
                if (nh) {
                    dotl = fmaf(f0, sWlast[kg], dotl);
                    dotl = fmaf(f1, sWlast[kg + 1], dotl);
                }
                uint32_t wh = cvt_bf2(f0, f1);
                float r0 = f0 - __uint_as_float(wh << 16);
                float r1 = f1 - __uint_as_float(wh & 0xffff0000u);
                uint32_t wl = cvt_bf2(r0, r1);
                int sL = kl >> 4;
                int j8 = (kl & 15) >> 1;
                int woff = (sL * 8 + (j8 & 3) * 2 + (j8 >> 2)) * 4;
                *(uint32_t*)(smem + SM_HHI + r * 288 + woff) = wh;
                *(uint32_t*)(smem + SM_HLO + r * 288 + woff) = wl;
            }
            if (p == 1 && nh) sDotp[sub * 128 + r] = dotl;
            __syncthreads();

            // ---- MMA phase: 8 ksteps over this K-half ----
            #pragma unroll 2
            for (int ss = 0; ss < 8; ss++) {
                const int sg = p * 8 + ss;
                uint2 Bh[8], Bl[8];
                #pragma unroll
                for (int nt = 0; nt < 8; nt++) {
                    int n = wc * 64 + nt * 8 + tq;
                    int boff = n * 544 + sg * 32 + tm * 8;
                    Bh[nt] = *(const uint2*)(smem + SM_BHI + boff);
                    Bl[nt] = *(const uint2*)(smem + SM_BLO + boff);
                }
                uint2 Ah[2][2], Al[2][2];
                #pragma unroll
                for (int mt = 0; mt < 2; mt++) {
                    int aoff0 = (wr * 32 + mt * 16 + tq) * 288 + ss * 32 + tm * 8;
                    int aoff1 = aoff0 + 8 * 288;
                    Ah[mt][0] = *(const uint2*)(smem + SM_HHI + aoff0);
                    Ah[mt][1] = *(const uint2*)(smem + SM_HHI + aoff1);
                    Al[mt][0] = *(const uint2*)(smem + SM_HLO + aoff0);
                    Al[mt][1] = *(const uint2*)(smem + SM_HLO + aoff1);
                }
                #pragma unroll
                for (int nt = 0; nt < 8; nt++)
                    #pragma unroll
                    for (int mt = 0; mt < 2; mt++) {
                        float* c = acc[nt][mt];
                        mma_bf16(c[0], c[1], c[2], c[3],
                                 Ah[mt][0].x, Ah[mt][1].x, Ah[mt][0].y, Ah[mt][1].y,
                                 Bh[nt].x, Bh[nt].y);
                        mma_bf16(c[0], c[1], c[2], c[3],
                                 Al[mt][0].x, Al[mt][1].x, Al[mt][0].y, Al[mt][1].y,
                                 Bh[nt].x, Bh[nt].y);
                        mma_bf16(c[0], c[1], c[2], c[3],
                                 Ah[mt][0].x, Ah[mt][1].x, Ah[mt][0].y, Ah[mt][1].y,
                                 Bl[nt].x, Bl[nt].y);
                    }
            }
            __syncthreads();
        }

        // ---- epilogue: bias -> relu -> mask -> row sums ----
        {
            const float vA = sValid[wr * 32 + tq];
            const float vB = sValid[wr * 32 + tq + 8];
            const float vC = sValid[wr * 32 + tq + 16];
            const float vD = sValid[wr * 32 + tq + 24];
            #pragma unroll
            for (int nt = 0; nt < 8; nt++) {
                int c0 = wc * 64 + nt * 8 + tm * 2;
                float e0 = sB2[c0], e1 = sB2[c0 + 1];
                float* a0 = acc[nt][0];
                float* a1 = acc[nt][1];
                float p0 = fmaxf(a0[0] + e0, 0.f) * vA + fmaxf(a0[2] + e0, 0.f) * vB
                         + fmaxf(a1[0] + e0, 0.f) * vC + fmaxf(a1[2] + e0, 0.f) * vD;
                float p1 = fmaxf(a0[1] + e1, 0.f) * vA + fmaxf(a0[3] + e1, 0.f) * vB
                         + fmaxf(a1[1] + e1, 0.f) * vC + fmaxf(a1[3] + e1, 0.f) * vD;
                p0 += __shfl_down_sync(0xffffffffu, p0, 16);
                p0 += __shfl_down_sync(0xffffffffu, p0, 8);
                p0 += __shfl_down_sync(0xffffffffu, p0, 4);
                p1 += __shfl_down_sync(0xffffffffu, p1, 16);
                p1 += __shfl_down_sync(0xffffffffu, p1, 8);
                p1 += __shfl_down_sync(0xffffffffu, p1, 4);
                if (tq == 0) {
                    sPart[wr * 128 + c0]     = p0;
                    sPart[wr * 128 + c0 + 1] = p1;
                }
            }
        }
        __syncthreads();

        {   // combine row-groups -> g_x
            int e = tid >> 7, col = tid & 127;
            float val = sPart[(2 * e) * 128 + col] + sPart[(2 * e + 1) * 128 + col];
            g_x[(size_t)(b0 + e) * QIN + 8 + nh * 128 + col] = val;
        }
        if (nh) {
            if (tid < 128)
                sCol[tid] = fmaxf(sDotp[tid] + sDotp[128 + tid] + sB2[128], 0.f) * sValid[tid];
            __syncthreads();
            if (w < 2) {
                float tt = sCol[w * 64 + lane] + sCol[w * 64 + 32 + lane];
                #pragma unroll
                for (int off = 16; off > 0; off >>= 1)
                    tt += __shfl_down_sync(0xffffffffu, tt, off);
                if (lane == 0) g_x[(size_t)(b0 + w) * QIN + 264] = tt;
            }
            if (tid < 16)
                g_x[(size_t)(b0 + (tid >> 3)) * QIN + (tid & 7)] =
                    s[(size_t)(b0 + (tid >> 3)) * SROW + (tid & 7)];
        }
        __syncthreads();
    }
}

// ---------------------------------------------------------------------------
// Q head: 8 rows per CTA
// ---------------------------------------------------------------------------
__global__ void __launch_bounds__(256) qhead_kernel(
    const float* __restrict__ Qw1, const float* __restrict__ Qb1,
    const float* __restrict__ Qw2, const float* __restrict__ Qb2,
    float* __restrict__ out)
{
    __shared__ float shX[8 * QIN];
    __shared__ float shHq[8 * HID];
    __shared__ float shW2[HID * ADIM];

    const int b0  = blockIdx.x * 8;
    const int tid = threadIdx.x;

    for (int i = tid; i < 8 * QIN;    i += 256) shX[i]  = g_x[(size_t)b0 * QIN + i];
    for (int i = tid; i < HID * ADIM; i += 256) shW2[i] = Qw2[i];
    __syncthreads();

    float acc[8];
    {
        const float qb = Qb1[tid];
        #pragma unroll
        for (int r = 0; r < 8; r++) acc[r] = qb;
        #pragma unroll 5
        for (int k = 0; k < QIN; k++) {
            float wv = Qw1[k * HID + tid];
            #pragma unroll
            for (int r = 0; r < 8; r++)
                acc[r] = fmaf(shX[r * QIN + k], wv, acc[r]);
        }
        #pragma unroll
        for (int r = 0; r < 8; r++) shHq[r * HID + tid] = fmaxf(acc[r], 0.0f);
    }
    __syncthreads();

    if (tid < 8 * ADIM) {
        int r = tid / ADIM, c = tid - r * ADIM;
        float a = Qb2[c];
        const float* hp = shHq + r * HID;
        #pragma unroll 8
        for (int k = 0; k < HID; k++)
            a = fmaf(hp[k], shW2[k * ADIM + c], a);
        out[(size_t)(b0 + r) * ADIM + c] = a;
    }
}

// ---------------------------------------------------------------------------
extern "C" void kernel_launch(void* const* d_in, const int* in_sizes, int n_in,
                              void* d_out, int out_size)
{
    const float* s   = (const float*)d_in[0];
    const float* W1  = (const float*)d_in[1];
    const float* b1  = (const float*)d_in[2];
    const float* W2  = (const float*)d_in[3];
    const float* b2  = (const float*)d_in[4];
    const float* Qw1 = (const float*)d_in[5];
    const float* Qb1 = (const float*)d_in[6];
    const float* Qw2 = (const float*)d_in[7];
    const float* Qb2 = (const float*)d_in[8];
    float* out = (float*)d_out;

    cudaFuncSetAttribute(enc_kernel,
                         cudaFuncAttributeMaxDynamicSharedMemorySize, SM_TOTAL);

    prep_kernel<<<128, 256>>>(W2);
    enc_kernel<<<1024, 256, SM_TOTAL>>>(s, W1, b1, W2, b2);
    qhead_kernel<<<BATCH / 8, 256>>>(Qw1, Qb1, Qw2, Qb2, out);
}

// round 5
// speedup vs baseline: 2.5482x; 1.0475x over previous
#include <cuda_runtime.h>
#include <cuda_bf16.h>
#include <cstdint>

#define BATCH 8192
#define CAR   8
#define HID   256
#define QIN   265
#define ADIM  30
#define SROW  520

// ---- smem offsets (bytes) ----
#define SM_BHI   0         // 128n x 544B (136 words, conflict-free per phase)
#define SM_BLO   69632
#define SM_HHI   139264    // 128r x 288B (one K-half)
#define SM_HLO   176128
#define SM_W1T   212992    // 128kp x 16 floats (pairs)          = 8192
#define SM_B1    221184    // 1024
#define SM_B2    222208    // 129 floats -> 528
#define SM_WLAST 222736    // 1024
#define SM_SURR  223760    // 4096 ; aliases: sDotp @ +0 (2048), sPart @ +2048 (2048)
#define SM_VALID 227856    // 512
#define SM_TOTAL 228368

__device__ float g_x[BATCH * QIN];
__device__ __align__(16) uint32_t g_Bhi[2 * 128 * 128];  // [nh][n][kword-permuted]
__device__ __align__(16) uint32_t g_Blo[2 * 128 * 128];

// ---------------------------------------------------------------------------
__device__ __forceinline__ uint32_t cvt_bf2(float lo, float hi) {
    uint32_t u;
    asm("cvt.rn.satfinite.bf16x2.f32 %0, %1, %2;" : "=r"(u) : "f"(hi), "f"(lo));
    return u;
}
__device__ __forceinline__ unsigned long long packf2(float a, float b) {
    unsigned long long u;
    asm("mov.b64 %0, {%1,%2};" : "=l"(u) : "f"(a), "f"(b));
    return u;
}
__device__ __forceinline__ void unpackf2(float& a, float& b, unsigned long long u) {
    asm("mov.b64 {%0,%1}, %2;" : "=f"(a), "=f"(b) : "l"(u));
}
__device__ __forceinline__ void fma2(unsigned long long& d, unsigned long long a,
                                     unsigned long long b) {
    asm("fma.rn.f32x2 %0, %1, %2, %0;" : "+l"(d) : "l"(a), "l"(b));
}
__device__ __forceinline__ void mma_bf16(float& c0, float& c1, float& c2, float& c3,
                                         uint32_t a0, uint32_t a1, uint32_t a2, uint32_t a3,
                                         uint32_t b0, uint32_t b1) {
    asm volatile(
        "mma.sync.aligned.m16n8k16.row.col.f32.bf16.bf16.f32 "
        "{%0,%1,%2,%3}, {%4,%5,%6,%7}, {%8,%9}, {%0,%1,%2,%3};"
        : "+f"(c0), "+f"(c1), "+f"(c2), "+f"(c3)
        : "r"(a0), "r"(a1), "r"(a2), "r"(a3), "r"(b0), "r"(b1));
}

// ---------------------------------------------------------------------------
// prep: W2 -> bf16 hi/lo, [nh][n][k-permuted]; one uint2 = one mma B fragment.
// ---------------------------------------------------------------------------
__global__ void prep_kernel(const float* __restrict__ W2) {
    int idx = blockIdx.x * 256 + threadIdx.x;   // [0, 32768)
    int nh = idx >> 14;
    int n  = (idx >> 7) & 127;
    int wd = idx & 127;
    int s  = wd >> 3;
    int rem = wd & 7;
    int q = rem >> 1, h2 = rem & 1;
    int k0 = s * 16 + 2 * (h2 * 4 + q);
    int ncol = nh * 128 + n;
    float f0 = W2[(size_t)k0 * 257 + ncol];
    float f1 = W2[(size_t)(k0 + 1) * 257 + ncol];
    uint32_t wh = cvt_bf2(f0, f1);
    float r0 = f0 - __uint_as_float(wh << 16);
    float r1 = f1 - __uint_as_float(wh & 0xffff0000u);
    g_Bhi[idx] = wh;
    g_Blo[idx] = cvt_bf2(r0, r1);
}

// ---------------------------------------------------------------------------
// encoder: CTA = (group of 16 batch elems) x (N-half). 8 tiles of M=128 rows.
// 512 threads, warp grid 4M x 4N (32x32 per warp).
// ---------------------------------------------------------------------------
__global__ void __launch_bounds__(512, 1) enc_kernel(
    const float* __restrict__ s, const float* __restrict__ W1,
    const float* __restrict__ b1, const float* __restrict__ W2,
    const float* __restrict__ b2)
{
    extern __shared__ char smem[];
    const int tid = threadIdx.x;
    const int nh  = blockIdx.x & 1;
    const int grp = blockIdx.x >> 1;
    const int w    = tid >> 5, lane = tid & 31;
    const int wr   = w & 3,   wc   = w >> 2;
    const int tq   = lane >> 2, tm = lane & 3;
    const int r    = tid & 127, sub = tid >> 7;   // sub uniform per warp

    float* sW1t   = (float*)(smem + SM_W1T);
    float* sB1    = (float*)(smem + SM_B1);
    float* sB2    = (float*)(smem + SM_B2);
    float* sWlast = (float*)(smem + SM_WLAST);
    float* sSurr  = (float*)(smem + SM_SURR);
    float* sDotp  = (float*)(smem + SM_SURR);          // alias (surr consumed)
    float* sPart  = (float*)(smem + SM_SURR + 2048);   // alias
    float* sValid = (float*)(smem + SM_VALID);

    // ---- prologue: resident B slab ----
    {
        const uint4* srcH = (const uint4*)(g_Bhi + nh * 16384);
        const uint4* srcL = (const uint4*)(g_Blo + nh * 16384);
        uint4* dH = (uint4*)(smem + SM_BHI);
        uint4* dL = (uint4*)(smem + SM_BLO);
        #pragma unroll
        for (int i = tid; i < 4096; i += 512) {
            int n = i >> 5, w4 = i & 31;
            dH[n * 34 + w4] = srcH[i];
            dL[n * 34 + w4] = srcL[i];
        }
    }
    // W1 pair-packed: sW1t[kp*16 + c*2 + h] = W1[c*256 + kp*2 + h]
    for (int i = tid; i < 2048; i += 512) {
        int kp = i >> 4, rem = i & 15, c = rem >> 1, h = rem & 1;
        sW1t[i] = W1[c * HID + kp * 2 + h];
    }
    if (tid < 256) {
        sB1[tid] = b1[tid];
        sWlast[tid] = W2[(size_t)tid * 257 + 256];
    }
    for (int i = tid; i < 129; i += 512)
        sB2[i] = (i < 128) ? b2[nh * 128 + i] : b2[256];
    __syncthreads();

    for (int t = 0; t < 8; t++) {
        const int b0 = grp * 16 + t * 2;

        // ---- surr load (2 elems x 512 floats) ----
        if (tid < 256) {
            int e = tid >> 7, j = tid & 127;
            ((float4*)sSurr)[e * 128 + j] =
                ((const float4*)(s + (size_t)(b0 + e) * SROW + CAR))[j];
        }
        __syncthreads();

        const float4 s0 = ((const float4*)sSurr)[r * 2];
        const float4 s1 = ((const float4*)sSurr)[r * 2 + 1];
        if (tid < 128) {
            float v = 1.0f;
            if (s0.x == -1.f || s0.y == -1.f || s0.z == -1.f || s0.w == -1.f ||
                s1.x == -1.f || s1.y == -1.f || s1.z == -1.f || s1.w == -1.f) v = 0.f;
            sValid[tid] = v;
        }
        const unsigned long long sp0 = packf2(s0.x, s0.x), sp1 = packf2(s0.y, s0.y);
        const unsigned long long sp2 = packf2(s0.z, s0.z), sp3 = packf2(s0.w, s0.w);
        const unsigned long long sp4 = packf2(s1.x, s1.x), sp5 = packf2(s1.y, s1.y);
        const unsigned long long sp6 = packf2(s1.z, s1.z), sp7 = packf2(s1.w, s1.w);

        float acc[4][2][4];
        #pragma unroll
        for (int nt = 0; nt < 4; nt++)
            #pragma unroll
            for (int mt = 0; mt < 2; mt++)
                #pragma unroll
                for (int c = 0; c < 4; c++) acc[nt][mt][c] = 0.f;
        unsigned long long dot2 = packf2(0.f, 0.f);

        for (int p = 0; p < 2; p++) {
            // ---- H phase: thread (r, sub) computes k in [p*128+sub*32, +32) ----
            #pragma unroll 4
            for (int jj = 0; jj < 16; jj++) {
                const int kl = sub * 32 + 2 * jj;
                const int kg = p * 128 + kl;
                const int kp = kg >> 1;
                ulonglong2 wA = *(const ulonglong2*)(sW1t + kp * 16);
                ulonglong2 wB = *(const ulonglong2*)(sW1t + kp * 16 + 4);
                ulonglong2 wC = *(const ulonglong2*)(sW1t + kp * 16 + 8);
                ulonglong2 wD = *(const ulonglong2*)(sW1t + kp * 16 + 12);
                unsigned long long acc2 = *(const unsigned long long*)(sB1 + kg);
                fma2(acc2, wA.x, sp0); fma2(acc2, wA.y, sp1);
                fma2(acc2, wB.x, sp2); fma2(acc2, wB.y, sp3);
                fma2(acc2, wC.x, sp4); fma2(acc2, wC.y, sp5);
                fma2(acc2, wD.x, sp6); fma2(acc2, wD.y, sp7);
                float f0, f1;
                unpackf2(f0, f1, acc2);
                f0 = fmaxf(f0, 0.f); f1 = fmaxf(f1, 0.f);
                if (nh) {
                    unsigned long long wl = *(const unsigned long long*)(sWlast + kg);
                    unsigned long long f2 = packf2(f0, f1);
                    fma2(dot2, f2, wl);
                }
                uint32_t wh = cvt_bf2(f0, f1);
                float r0 = f0 - __uint_as_float(wh << 16);
                float r1 = f1 - __uint_as_float(wh & 0xffff0000u);
                uint32_t wlo = cvt_bf2(r0, r1);
                const int sL = kl >> 4;
                const int j8 = (kl & 15) >> 1;
                const int woff = (sL * 8 + (j8 & 3) * 2 + (j8 >> 2)) * 4;
                *(uint32_t*)(smem + SM_HHI + r * 288 + woff) = wh;
                *(uint32_t*)(smem + SM_HLO + r * 288 + woff) = wlo;
            }
            if (p == 1 && nh) {
                float da, db;
                unpackf2(da, db, dot2);
                sDotp[sub * 128 + r] = da + db;
            }
            __syncthreads();

            // ---- MMA phase: 8 ksteps over this K-half ----
            #pragma unroll 2
            for (int ss = 0; ss < 8; ss++) {
                const int sg = p * 8 + ss;
                uint2 Bh[4], Bl[4];
                #pragma unroll
                for (int nt = 0; nt < 4; nt++) {
                    int n = wc * 32 + nt * 8 + tq;
                    int boff = n * 544 + sg * 32 + tm * 8;
                    Bh[nt] = *(const uint2*)(smem + SM_BHI + boff);
                    Bl[nt] = *(const uint2*)(smem + SM_BLO + boff);
                }
                uint2 Ah[2][2], Al[2][2];
                #pragma unroll
                for (int mt = 0; mt < 2; mt++) {
                    int aoff0 = (wr * 32 + mt * 16 + tq) * 288 + ss * 32 + tm * 8;
                    int aoff1 = aoff0 + 8 * 288;
                    Ah[mt][0] = *(const uint2*)(smem + SM_HHI + aoff0);
                    Ah[mt][1] = *(const uint2*)(smem + SM_HHI + aoff1);
                    Al[mt][0] = *(const uint2*)(smem + SM_HLO + aoff0);
                    Al[mt][1] = *(const uint2*)(smem + SM_HLO + aoff1);
                }
                #pragma unroll
                for (int nt = 0; nt < 4; nt++)
                    #pragma unroll
                    for (int mt = 0; mt < 2; mt++) {
                        float* c = acc[nt][mt];
                        mma_bf16(c[0], c[1], c[2], c[3],
                                 Ah[mt][0].x, Ah[mt][1].x, Ah[mt][0].y, Ah[mt][1].y,
                                 Bh[nt].x, Bh[nt].y);
                        mma_bf16(c[0], c[1], c[2], c[3],
                                 Al[mt][0].x, Al[mt][1].x, Al[mt][0].y, Al[mt][1].y,
                                 Bh[nt].x, Bh[nt].y);
                        mma_bf16(c[0], c[1], c[2], c[3],
                                 Ah[mt][0].x, Ah[mt][1].x, Ah[mt][0].y, Ah[mt][1].y,
                                 Bl[nt].x, Bl[nt].y);
                    }
            }
            __syncthreads();
        }

        // ---- epilogue: bias -> relu -> mask -> row sums ----
        {
            const float vA = sValid[wr * 32 + tq];
            const float vB = sValid[wr * 32 + tq + 8];
            const float vC = sValid[wr * 32 + tq + 16];
            const float vD = sValid[wr * 32 + tq + 24];
            #pragma unroll
            for (int nt = 0; nt < 4; nt++) {
                int c0 = wc * 32 + nt * 8 + tm * 2;
                float e0 = sB2[c0], e1 = sB2[c0 + 1];
                float* a0 = acc[nt][0];
                float* a1 = acc[nt][1];
                float p0 = fmaxf(a0[0] + e0, 0.f) * vA + fmaxf(a0[2] + e0, 0.f) * vB
                         + fmaxf(a1[0] + e0, 0.f) * vC + fmaxf(a1[2] + e0, 0.f) * vD;
                float p1 = fmaxf(a0[1] + e1, 0.f) * vA + fmaxf(a0[3] + e1, 0.f) * vB
                         + fmaxf(a1[1] + e1, 0.f) * vC + fmaxf(a1[3] + e1, 0.f) * vD;
                p0 += __shfl_down_sync(0xffffffffu, p0, 16);
                p0 += __shfl_down_sync(0xffffffffu, p0, 8);
                p0 += __shfl_down_sync(0xffffffffu, p0, 4);
                p1 += __shfl_down_sync(0xffffffffu, p1, 16);
                p1 += __shfl_down_sync(0xffffffffu, p1, 8);
                p1 += __shfl_down_sync(0xffffffffu, p1, 4);
                if (tq == 0) {
                    sPart[wr * 128 + c0]     = p0;
                    sPart[wr * 128 + c0 + 1] = p1;
                }
            }
        }
        __syncthreads();

        if (tid < 256) {   // combine row-groups -> g_x
            int e = tid >> 7, col = tid & 127;
            float val = sPart[(2 * e) * 128 + col] + sPart[(2 * e + 1) * 128 + col];
            g_x[(size_t)(b0 + e) * QIN + 8 + nh * 128 + col] = val;
        }
        if (nh) {
            if (tid < 128) {
                float dsum = sDotp[tid] + sDotp[128 + tid]
                           + sDotp[256 + tid] + sDotp[384 + tid];
                float vv = fmaxf(dsum + sB2[128], 0.f) * sValid[tid];
                sDotp[tid] = vv;   // self-slot overwrite, safe
            }
            __syncthreads();
            if (w < 2) {
                float tt = sDotp[w * 64 + lane] + sDotp[w * 64 + 32 + lane];
                #pragma unroll
                for (int off = 16; off > 0; off >>= 1)
                    tt += __shfl_down_sync(0xffffffffu, tt, off);
                if (lane == 0) g_x[(size_t)(b0 + w) * QIN + 264] = tt;
            }
            if (tid < 16)
                g_x[(size_t)(b0 + (tid >> 3)) * QIN + (tid & 7)] =
                    s[(size_t)(b0 + (tid >> 3)) * SROW + (tid & 7)];
        }
        __syncthreads();
    }
}

// ---------------------------------------------------------------------------
// Q head: 8 rows per CTA
// ---------------------------------------------------------------------------
__global__ void __launch_bounds__(256) qhead_kernel(
    const float* __restrict__ Qw1, const float* __restrict__ Qb1,
    const float* __restrict__ Qw2, const float* __restrict__ Qb2,
    float* __restrict__ out)
{
    __shared__ float shX[8 * QIN];
    __shared__ float shHq[8 * HID];
    __shared__ float shW2[HID * ADIM];

    const int b0  = blockIdx.x * 8;
    const int tid = threadIdx.x;

    for (int i = tid; i < 8 * QIN;    i += 256) shX[i]  = g_x[(size_t)b0 * QIN + i];
    for (int i = tid; i < HID * ADIM; i += 256) shW2[i] = Qw2[i];
    __syncthreads();

    float acc[8];
    {
        const float qb = Qb1[tid];
        #pragma unroll
        for (int r = 0; r < 8; r++) acc[r] = qb;
        #pragma unroll 5
        for (int k = 0; k < QIN; k++) {
            float wv = Qw1[k * HID + tid];
            #pragma unroll
            for (int r = 0; r < 8; r++)
                acc[r] = fmaf(shX[r * QIN + k], wv, acc[r]);
        }
        #pragma unroll
        for (int r = 0; r < 8; r++) shHq[r * HID + tid] = fmaxf(acc[r], 0.0f);
    }
    __syncthreads();

    if (tid < 8 * ADIM) {
        int r = tid / ADIM, c = tid - r * ADIM;
        float a = Qb2[c];
        const float* hp = shHq + r * HID;
        #pragma unroll 8
        for (int k = 0; k < HID; k++)
            a = fmaf(hp[k], shW2[k * ADIM + c], a);
        out[(size_t)(b0 + r) * ADIM + c] = a;
    }
}

// ---------------------------------------------------------------------------
extern "C" void kernel_launch(void* const* d_in, const int* in_sizes, int n_in,
                              void* d_out, int out_size)
{
    const float* s   = (const float*)d_in[0];
    const float* W1  = (const float*)d_in[1];
    const float* b1  = (const float*)d_in[2];
    const float* W2  = (const float*)d_in[3];
    const float* b2  = (const float*)d_in[4];
    const float* Qw1 = (const float*)d_in[5];
    const float* Qb1 = (const float*)d_in[6];
    const float* Qw2 = (const float*)d_in[7];
    const float* Qb2 = (const float*)d_in[8];
    float* out = (float*)d_out;

    cudaFuncSetAttribute(enc_kernel,
                         cudaFuncAttributeMaxDynamicSharedMemorySize, SM_TOTAL);

    prep_kernel<<<128, 256>>>(W2);
    enc_kernel<<<1024, 512, SM_TOTAL>>>(s, W1, b1, W2, b2);
    qhead_kernel<<<BATCH / 8, 256>>>(Qw1, Qb1, Qw2, Qb2, out);
}

// round 7
// speedup vs baseline: 4.1032x; 1.6102x over previous
#include <cuda_runtime.h>
#include <cuda_fp16.h>
#include <cstdint>

#define BATCH 8192
#define CAR   8
#define HID   256
#define QIN   265
#define ADIM  30
#define SROW  520

// ---- smem offsets (bytes) ----
#define SM_BHI   0         // 128n x 544B fp16 B-hi slab (word*4, permuted k)
#define SM_HHI   69632     // 128r x 544B fp16 H-hi, full K=256, rotated rows
#define SM_HLO   139264    // 128r x 544B fp16 H-lo
#define SM_W1T   208896    // 128kp x 16 floats (pair-packed)   = 8192
#define SM_B1    217088    // 1024
#define SM_B2    218112    // 129 floats -> pad 528 (keeps SURR 16B-aligned)
#define SM_WLAST 218640    // 1024
#define SM_SURR  219664    // 4096  (16B-aligned)
#define SM_VALID 223760    // 512
#define SM_TOTAL 224272
// aliases (valid only after MMA reads of H complete):
//   sDotp = SM_HHI + 0    (2048B)
//   sPart = SM_HHI + 2048 (2048B)

__device__ float g_x[BATCH * QIN];

// ---------------------------------------------------------------------------
__device__ __forceinline__ uint32_t cvt_f16x2(float lo, float hi) {
    uint32_t u;
    asm("cvt.rn.f16x2.f32 %0, %1, %2;" : "=r"(u) : "f"(hi), "f"(lo));
    return u;
}
__device__ __forceinline__ unsigned long long packf2(float a, float b) {
    unsigned long long u;
    asm("mov.b64 %0, {%1,%2};" : "=l"(u) : "f"(a), "f"(b));
    return u;
}
__device__ __forceinline__ void unpackf2(float& a, float& b, unsigned long long u) {
    asm("mov.b64 {%0,%1}, %2;" : "=f"(a), "=f"(b) : "l"(u));
}
__device__ __forceinline__ void fma2(unsigned long long& d, unsigned long long a,
                                     unsigned long long b) {
    asm("fma.rn.f32x2 %0, %1, %2, %0;" : "+l"(d) : "l"(a), "l"(b));
}
__device__ __forceinline__ void mma_f16(float& c0, float& c1, float& c2, float& c3,
                                        uint32_t a0, uint32_t a1, uint32_t a2, uint32_t a3,
                                        uint32_t b0, uint32_t b1) {
    asm volatile(
        "mma.sync.aligned.m16n8k16.row.col.f32.f16.f16.f32 "
        "{%0,%1,%2,%3}, {%4,%5,%6,%7}, {%8,%9}, {%0,%1,%2,%3};"
        : "+f"(c0), "+f"(c1), "+f"(c2), "+f"(c3)
        : "r"(a0), "r"(a1), "r"(a2), "r"(a3), "r"(b0), "r"(b1));
}

// ---------------------------------------------------------------------------
// encoder: CTA = (group of 16 batch elems) x (N-half). 8 tiles of M=128 rows.
// 512 threads, warp grid 4M x 4N (32x32 per warp). fp16 2-term split GEMM.
// ---------------------------------------------------------------------------
__global__ void __launch_bounds__(512, 1) enc_kernel(
    const float* __restrict__ s, const float* __restrict__ W1,
    const float* __restrict__ b1, const float* __restrict__ W2,
    const float* __restrict__ b2)
{
    extern __shared__ char smem[];
    const int tid = threadIdx.x;
    const int nh  = blockIdx.x & 1;
    const int grp = blockIdx.x >> 1;
    const int w    = tid >> 5, lane = tid & 31;
    const int wr   = w & 3,   wc   = w >> 2;
    const int tq   = lane >> 2, tm = lane & 3;
    const int r    = tid & 127, sub = tid >> 7;   // sub in 0..3, uniform per warp

    float* sW1t   = (float*)(smem + SM_W1T);
    float* sB1    = (float*)(smem + SM_B1);
    float* sB2    = (float*)(smem + SM_B2);
    float* sWlast = (float*)(smem + SM_WLAST);
    float* sSurr  = (float*)(smem + SM_SURR);
    float* sValid = (float*)(smem + SM_VALID);
    float* sDotp  = (float*)(smem + SM_HHI);          // alias, epilogue only
    float* sPart  = (float*)(smem + SM_HHI + 2048);   // alias, epilogue only

    // ---- prologue: build fp16 B-hi slab in permuted layout from W2 (L2-hot)
    for (int i = tid; i < 16384; i += 512) {
        int word = i >> 7;          // 0..127
        int n    = i & 127;
        int sL = word >> 3, rem = word & 7, q = rem >> 1, h2 = rem & 1;
        int k0 = sL * 16 + 2 * (h2 * 4 + q);
        float f0 = W2[(size_t)k0 * 257 + nh * 128 + n];
        float f1 = W2[(size_t)(k0 + 1) * 257 + nh * 128 + n];
        *(uint32_t*)(smem + SM_BHI + n * 544 + word * 4) = cvt_f16x2(f0, f1);
    }
    // W1 pair-packed: sW1t[kp*16 + c*2 + h] = W1[c*256 + kp*2 + h]
    for (int i = tid; i < 2048; i += 512) {
        int kp = i >> 4, rem = i & 15, c = rem >> 1, h = rem & 1;
        sW1t[i] = W1[c * HID + kp * 2 + h];
    }
    if (tid < 256) {
        sB1[tid] = b1[tid];
        sWlast[tid] = W2[(size_t)tid * 257 + 256];
    }
    for (int i = tid; i < 129; i += 512)
        sB2[i] = (i < 128) ? b2[nh * 128 + i] : b2[256];
    __syncthreads();

    // per-thread constant bases
    const int rrot    = ((r >> 2) & 7) * 4;
    const int rowbase = r * 544 + rrot;

    for (int t = 0; t < 8; t++) {
        const int b0 = grp * 16 + t * 2;

        // ---- surr load (2 elems x 512 floats) ----
        if (tid < 256) {
            int e = tid >> 7, j = tid & 127;
            ((float4*)sSurr)[e * 128 + j] =
                ((const float4*)(s + (size_t)(b0 + e) * SROW + CAR))[j];
        }
        __syncthreads();

        const float4 s0 = ((const float4*)sSurr)[r * 2];
        const float4 s1 = ((const float4*)sSurr)[r * 2 + 1];
        if (tid < 128) {
            float v = 1.0f;
            if (s0.x == -1.f || s0.y == -1.f || s0.z == -1.f || s0.w == -1.f ||
                s1.x == -1.f || s1.y == -1.f || s1.z == -1.f || s1.w == -1.f) v = 0.f;
            sValid[tid] = v;
        }
        const unsigned long long sp0 = packf2(s0.x, s0.x), sp1 = packf2(s0.y, s0.y);
        const unsigned long long sp2 = packf2(s0.z, s0.z), sp3 = packf2(s0.w, s0.w);
        const unsigned long long sp4 = packf2(s1.x, s1.x), sp5 = packf2(s1.y, s1.y);
        const unsigned long long sp6 = packf2(s1.z, s1.z), sp7 = packf2(s1.w, s1.w);

        // ---- H phase: thread (r, sub) computes k in [sub*64, sub*64+64) ----
        unsigned long long dot2 = packf2(0.f, 0.f);
        #pragma unroll 4
        for (int jj = 0; jj < 32; jj++) {
            const int kl = sub * 64 + 2 * jj;
            const int kp = kl >> 1;
            ulonglong2 wA = *(const ulonglong2*)(sW1t + kp * 16);
            ulonglong2 wB = *(const ulonglong2*)(sW1t + kp * 16 + 4);
            ulonglong2 wC = *(const ulonglong2*)(sW1t + kp * 16 + 8);
            ulonglong2 wD = *(const ulonglong2*)(sW1t + kp * 16 + 12);
            unsigned long long acc2 = *(const unsigned long long*)(sB1 + kl);
            fma2(acc2, wA.x, sp0); fma2(acc2, wA.y, sp1);
            fma2(acc2, wB.x, sp2); fma2(acc2, wB.y, sp3);
            fma2(acc2, wC.x, sp4); fma2(acc2, wC.y, sp5);
            fma2(acc2, wD.x, sp6); fma2(acc2, wD.y, sp7);
            float f0, f1;
            unpackf2(f0, f1, acc2);
            f0 = fmaxf(f0, 0.f); f1 = fmaxf(f1, 0.f);
            if (nh) {
                unsigned long long wl = *(const unsigned long long*)(sWlast + kl);
                fma2(dot2, packf2(f0, f1), wl);
            }
            uint32_t wh = cvt_f16x2(f0, f1);
            __half2 hh = *reinterpret_cast<__half2*>(&wh);
            float2 bb = __half22float2(hh);
            uint32_t wlo = cvt_f16x2(f0 - bb.x, f1 - bb.y);
            const int sL = kl >> 4;
            const int j8 = jj & 7;
            const int woff = (sL * 8 + (j8 & 3) * 2 + (j8 >> 2)) * 4;
            *(uint32_t*)(smem + SM_HHI + rowbase + woff) = wh;
            *(uint32_t*)(smem + SM_HLO + rowbase + woff) = wlo;
        }
        __syncthreads();

        // ---- MMA: 16 ksteps, fp16 2-term ----
        float acc[4][2][4];
        #pragma unroll
        for (int nt = 0; nt < 4; nt++)
            #pragma unroll
            for (int mt = 0; mt < 2; mt++)
                #pragma unroll
                for (int c = 0; c < 4; c++) acc[nt][mt][c] = 0.f;

        int abase[2][2];
        #pragma unroll
        for (int mt = 0; mt < 2; mt++)
            #pragma unroll
            for (int rr = 0; rr < 2; rr++) {
                int row = wr * 32 + mt * 16 + rr * 8 + tq;
                abase[mt][rr] = row * 544 + ((row >> 2) & 7) * 4 + tm * 8;
            }

        #pragma unroll 4
        for (int sg = 0; sg < 16; sg++) {
            uint2 Bh[4];
            #pragma unroll
            for (int nt = 0; nt < 4; nt++) {
                int n = wc * 32 + nt * 8 + tq;
                Bh[nt] = *(const uint2*)(smem + SM_BHI + n * 544 + sg * 32 + tm * 8);
            }
            uint32_t Ah[2][2][2], Al[2][2][2];   // [mt][rr][word]
            #pragma unroll
            for (int mt = 0; mt < 2; mt++)
                #pragma unroll
                for (int rr = 0; rr < 2; rr++) {
                    int off = abase[mt][rr] + sg * 32;
                    Ah[mt][rr][0] = *(const uint32_t*)(smem + SM_HHI + off);
                    Ah[mt][rr][1] = *(const uint32_t*)(smem + SM_HHI + off + 4);
                    Al[mt][rr][0] = *(const uint32_t*)(smem + SM_HLO + off);
                    Al[mt][rr][1] = *(const uint32_t*)(smem + SM_HLO + off + 4);
                }
            #pragma unroll
            for (int nt = 0; nt < 4; nt++)
                #pragma unroll
                for (int mt = 0; mt < 2; mt++) {
                    float* c = acc[nt][mt];
                    mma_f16(c[0], c[1], c[2], c[3],
                            Ah[mt][0][0], Ah[mt][1][0], Ah[mt][0][1], Ah[mt][1][1],
                            Bh[nt].x, Bh[nt].y);
                    mma_f16(c[0], c[1], c[2], c[3],
                            Al[mt][0][0], Al[mt][1][0], Al[mt][0][1], Al[mt][1][1],
                            Bh[nt].x, Bh[nt].y);
                }
        }
        __syncthreads();   // all H/B reads done; H area reusable as sDotp/sPart

        // ---- epilogue: bias -> relu -> mask -> row sums ----
        if (nh) {
            float da, db;
            unpackf2(da, db, dot2);
            sDotp[sub * 128 + r] = da + db;
        }
        {
            const float vA = sValid[wr * 32 + tq];
            const float vB = sValid[wr * 32 + tq + 8];
            const float vC = sValid[wr * 32 + tq + 16];
            const float vD = sValid[wr * 32 + tq + 24];
            #pragma unroll
            for (int nt = 0; nt < 4; nt++) {
                int c0 = wc * 32 + nt * 8 + tm * 2;
                float e0 = sB2[c0], e1 = sB2[c0 + 1];
                float* a0 = acc[nt][0];
                float* a1 = acc[nt][1];
                float p0 = fmaxf(a0[0] + e0, 0.f) * vA + fmaxf(a0[2] + e0, 0.f) * vB
                         + fmaxf(a1[0] + e0, 0.f) * vC + fmaxf(a1[2] + e0, 0.f) * vD;
                float p1 = fmaxf(a0[1] + e1, 0.f) * vA + fmaxf(a0[3] + e1, 0.f) * vB
                         + fmaxf(a1[1] + e1, 0.f) * vC + fmaxf(a1[3] + e1, 0.f) * vD;
                p0 += __shfl_down_sync(0xffffffffu, p0, 16);
                p0 += __shfl_down_sync(0xffffffffu, p0, 8);
                p0 += __shfl_down_sync(0xffffffffu, p0, 4);
                p1 += __shfl_down_sync(0xffffffffu, p1, 16);
                p1 += __shfl_down_sync(0xffffffffu, p1, 8);
                p1 += __shfl_down_sync(0xffffffffu, p1, 4);
                if (tq == 0) {
                    sPart[wr * 128 + c0]     = p0;
                    sPart[wr * 128 + c0 + 1] = p1;
                }
            }
        }
        __syncthreads();

        if (tid < 256) {   // combine row-groups -> g_x
            int e = tid >> 7, col = tid & 127;
            float val = sPart[(2 * e) * 128 + col] + sPart[(2 * e + 1) * 128 + col];
            g_x[(size_t)(b0 + e) * QIN + 8 + nh * 128 + col] = val;
        }
        if (nh) {
            if (tid < 128) {
                float dsum = sDotp[tid] + sDotp[128 + tid]
                           + sDotp[256 + tid] + sDotp[384 + tid];
                sDotp[tid] = fmaxf(dsum + sB2[128], 0.f) * sValid[tid];
            }
            __syncthreads();
            if (w < 2) {
                float tt = sDotp[w * 64 + lane] + sDotp[w * 64 + 32 + lane];
                #pragma unroll
                for (int off = 16; off > 0; off >>= 1)
                    tt += __shfl_down_sync(0xffffffffu, tt, off);
                if (lane == 0) g_x[(size_t)(b0 + w) * QIN + 264] = tt;
            }
            if (tid < 16)
                g_x[(size_t)(b0 + (tid >> 3)) * QIN + (tid & 7)] =
                    s[(size_t)(b0 + (tid >> 3)) * SROW + (tid & 7)];
        }
        __syncthreads();
    }
}

// ---------------------------------------------------------------------------
// Q head: 8 rows per CTA
// ---------------------------------------------------------------------------
__global__ void __launch_bounds__(256) qhead_kernel(
    const float* __restrict__ Qw1, const float* __restrict__ Qb1,
    const float* __restrict__ Qw2, const float* __restrict__ Qb2,
    float* __restrict__ out)
{
    __shared__ float shX[8 * QIN];
    __shared__ float shHq[8 * HID];
    __shared__ float shW2[HID * ADIM];

    const int b0  = blockIdx.x * 8;
    const int tid = threadIdx.x;

    for (int i = tid; i < 8 * QIN;    i += 256) shX[i]  = g_x[(size_t)b0 * QIN + i];
    for (int i = tid; i < HID * ADIM; i += 256) shW2[i] = Qw2[i];
    __syncthreads();

    float acc[8];
    {
        const float qb = Qb1[tid];
        #pragma unroll
        for (int r = 0; r < 8; r++) acc[r] = qb;
        #pragma unroll 5
        for (int k = 0; k < QIN; k++) {
            float wv = Qw1[k * HID + tid];
            #pragma unroll
            for (int r = 0; r < 8; r++)
                acc[r] = fmaf(shX[r * QIN + k], wv, acc[r]);
        }
        #pragma unroll
        for (int r = 0; r < 8; r++) shHq[r * HID + tid] = fmaxf(acc[r], 0.0f);
    }
    __syncthreads();

    if (tid < 8 * ADIM) {
        int r = tid / ADIM, c = tid - r * ADIM;
        float a = Qb2[c];
        const float* hp = shHq + r * HID;
        #pragma unroll 8
        for (int k = 0; k < HID; k++)
            a = fmaf(hp[k], shW2[k * ADIM + c], a);
        out[(size_t)(b0 + r) * ADIM + c] = a;
    }
}

// ---------------------------------------------------------------------------
extern "C" void kernel_launch(void* const* d_in, const int* in_sizes, int n_in,
                              void* d_out, int out_size)
{
    const float* s   = (const float*)d_in[0];
    const float* W1  = (const float*)d_in[1];
    const float* b1  = (const float*)d_in[2];
    const float* W2  = (const float*)d_in[3];
    const float* b2  = (const float*)d_in[4];
    const float* Qw1 = (const float*)d_in[5];
    const float* Qb1 = (const float*)d_in[6];
    const float* Qw2 = (const float*)d_in[7];
    const float* Qb2 = (const float*)d_in[8];
    float* out = (float*)d_out;

    cudaFuncSetAttribute(enc_kernel,
                         cudaFuncAttributeMaxDynamicSharedMemorySize, SM_TOTAL);

    enc_kernel<<<1024, 512, SM_TOTAL>>>(s, W1, b1, W2, b2);
    qhead_kernel<<<BATCH / 8, 256>>>(Qw1, Qb1, Qw2, Qb2, out);
}

// round 8
// speedup vs baseline: 4.9113x; 1.1970x over previous
#include <cuda_runtime.h>
#include <cuda_fp16.h>
#include <cstdint>

#define BATCH 8192
#define CAR   8
#define HID   256
#define QIN   265
#define ADIM  30
#define SROW  520

// ---- enc smem offsets (bytes) ----
#define SM_BHI   0         // 128n x 544B fp16 B slab (word*4, permuted k)
#define SM_HHI   69632     // 128r x 544B fp16 H, full K=256, rotated rows
#define SM_W1T   139264    // 128kp x 16 floats (pair-packed)   = 8192
#define SM_B1    147456    // 1024
#define SM_B2    148480    // 129 floats -> pad 528
#define SM_WLAST 149008    // 1024
#define SM_SURR  150032    // 4096  (16B-aligned)
#define SM_VALID 154128    // 512
#define SM_TOTAL 154640
// aliases (valid only after MMA reads of H complete):
//   sDotp = SM_HHI + 0    (2048B)
//   sPart = SM_HHI + 2048 (2048B)

// ---- qhead smem offsets (floats) ----
#define QS_X   0                    // 16*265 = 4240
#define QS_HQ  4240                 // 16*256 = 4096
#define QS_W2  8336                 // 256*30 = 7680
#define QS_TOT 16016                // *4 = 64064 B

__device__ float g_x[BATCH * QIN];

// ---------------------------------------------------------------------------
__device__ __forceinline__ uint32_t cvt_f16x2(float lo, float hi) {
    uint32_t u;
    asm("cvt.rn.f16x2.f32 %0, %1, %2;" : "=r"(u) : "f"(hi), "f"(lo));
    return u;
}
__device__ __forceinline__ unsigned long long packf2(float a, float b) {
    unsigned long long u;
    asm("mov.b64 %0, {%1,%2};" : "=l"(u) : "f"(a), "f"(b));
    return u;
}
__device__ __forceinline__ void unpackf2(float& a, float& b, unsigned long long u) {
    asm("mov.b64 {%0,%1}, %2;" : "=f"(a), "=f"(b) : "l"(u));
}
__device__ __forceinline__ void fma2(unsigned long long& d, unsigned long long a,
                                     unsigned long long b) {
    asm("fma.rn.f32x2 %0, %1, %2, %0;" : "+l"(d) : "l"(a), "l"(b));
}
__device__ __forceinline__ void mma_f16(float& c0, float& c1, float& c2, float& c3,
                                        uint32_t a0, uint32_t a1, uint32_t a2, uint32_t a3,
                                        uint32_t b0, uint32_t b1) {
    asm volatile(
        "mma.sync.aligned.m16n8k16.row.col.f32.f16.f16.f32 "
        "{%0,%1,%2,%3}, {%4,%5,%6,%7}, {%8,%9}, {%0,%1,%2,%3};"
        : "+f"(c0), "+f"(c1), "+f"(c2), "+f"(c3)
        : "r"(a0), "r"(a1), "r"(a2), "r"(a3), "r"(b0), "r"(b1));
}

// ---------------------------------------------------------------------------
// encoder: CTA = (group of 16 batch elems) x (N-half). 8 tiles of M=128 rows.
// 512 threads, warp grid 4M x 4N (32x32 per warp). pure fp16 GEMM.
// ---------------------------------------------------------------------------
__global__ void __launch_bounds__(512, 1) enc_kernel(
    const float* __restrict__ s, const float* __restrict__ W1,
    const float* __restrict__ b1, const float* __restrict__ W2,
    const float* __restrict__ b2)
{
    extern __shared__ char smem[];
    const int tid = threadIdx.x;
    const int nh  = blockIdx.x & 1;
    const int grp = blockIdx.x >> 1;
    const int w    = tid >> 5, lane = tid & 31;
    const int wr   = w & 3,   wc   = w >> 2;
    const int tq   = lane >> 2, tm = lane & 3;
    const int r    = tid & 127, sub = tid >> 7;   // sub in 0..3, uniform per warp

    float* sW1t   = (float*)(smem + SM_W1T);
    float* sB1    = (float*)(smem + SM_B1);
    float* sB2    = (float*)(smem + SM_B2);
    float* sWlast = (float*)(smem + SM_WLAST);
    float* sSurr  = (float*)(smem + SM_SURR);
    float* sValid = (float*)(smem + SM_VALID);
    float* sDotp  = (float*)(smem + SM_HHI);          // alias, epilogue only
    float* sPart  = (float*)(smem + SM_HHI + 2048);   // alias, epilogue only

    // ---- prologue: build fp16 B slab in permuted layout from W2 (L2-hot) ----
    for (int i = tid; i < 16384; i += 512) {
        int word = i >> 7;          // 0..127
        int n    = i & 127;
        int sL = word >> 3, rem = word & 7, q = rem >> 1, h2 = rem & 1;
        int k0 = sL * 16 + 2 * (h2 * 4 + q);
        float f0 = W2[(size_t)k0 * 257 + nh * 128 + n];
        float f1 = W2[(size_t)(k0 + 1) * 257 + nh * 128 + n];
        *(uint32_t*)(smem + SM_BHI + n * 544 + word * 4) = cvt_f16x2(f0, f1);
    }
    // W1 pair-packed: sW1t[kp*16 + c*2 + h] = W1[c*256 + kp*2 + h]
    for (int i = tid; i < 2048; i += 512) {
        int kp = i >> 4, rem = i & 15, c = rem >> 1, h = rem & 1;
        sW1t[i] = W1[c * HID + kp * 2 + h];
    }
    if (tid < 256) {
        sB1[tid] = b1[tid];
        sWlast[tid] = W2[(size_t)tid * 257 + 256];
    }
    for (int i = tid; i < 129; i += 512)
        sB2[i] = (i < 128) ? b2[nh * 128 + i] : b2[256];
    __syncthreads();

    // per-thread constant bases
    const int rrot    = ((r >> 2) & 7) * 4;
    const int rowbase = r * 544 + rrot;

    for (int t = 0; t < 8; t++) {
        const int b0 = grp * 16 + t * 2;

        // ---- surr load (2 elems x 512 floats) ----
        if (tid < 256) {
            int e = tid >> 7, j = tid & 127;
            ((float4*)sSurr)[e * 128 + j] =
                ((const float4*)(s + (size_t)(b0 + e) * SROW + CAR))[j];
        }
        __syncthreads();

        const float4 s0 = ((const float4*)sSurr)[r * 2];
        const float4 s1 = ((const float4*)sSurr)[r * 2 + 1];
        if (tid < 128) {
            float v = 1.0f;
            if (s0.x == -1.f || s0.y == -1.f || s0.z == -1.f || s0.w == -1.f ||
                s1.x == -1.f || s1.y == -1.f || s1.z == -1.f || s1.w == -1.f) v = 0.f;
            sValid[tid] = v;
        }
        const unsigned long long sp0 = packf2(s0.x, s0.x), sp1 = packf2(s0.y, s0.y);
        const unsigned long long sp2 = packf2(s0.z, s0.z), sp3 = packf2(s0.w, s0.w);
        const unsigned long long sp4 = packf2(s1.x, s1.x), sp5 = packf2(s1.y, s1.y);
        const unsigned long long sp6 = packf2(s1.z, s1.z), sp7 = packf2(s1.w, s1.w);

        // ---- H phase: thread (r, sub) computes k in [sub*64, sub*64+64) ----
        unsigned long long dot2 = packf2(0.f, 0.f);
        #pragma unroll 4
        for (int jj = 0; jj < 32; jj++) {
            const int kl = sub * 64 + 2 * jj;
            const int kp = kl >> 1;
            ulonglong2 wA = *(const ulonglong2*)(sW1t + kp * 16);
            ulonglong2 wB = *(const ulonglong2*)(sW1t + kp * 16 + 4);
            ulonglong2 wC = *(const ulonglong2*)(sW1t + kp * 16 + 8);
            ulonglong2 wD = *(const ulonglong2*)(sW1t + kp * 16 + 12);
            unsigned long long acc2 = *(const unsigned long long*)(sB1 + kl);
            fma2(acc2, wA.x, sp0); fma2(acc2, wA.y, sp1);
            fma2(acc2, wB.x, sp2); fma2(acc2, wB.y, sp3);
            fma2(acc2, wC.x, sp4); fma2(acc2, wC.y, sp5);
            fma2(acc2, wD.x, sp6); fma2(acc2, wD.y, sp7);
            float f0, f1;
            unpackf2(f0, f1, acc2);
            f0 = fmaxf(f0, 0.f); f1 = fmaxf(f1, 0.f);
            if (nh) {
                unsigned long long wl = *(const unsigned long long*)(sWlast + kl);
                fma2(dot2, packf2(f0, f1), wl);
            }
            const int sL = kl >> 4;
            const int j8 = jj & 7;
            const int woff = (sL * 8 + (j8 & 3) * 2 + (j8 >> 2)) * 4;
            *(uint32_t*)(smem + SM_HHI + rowbase + woff) = cvt_f16x2(f0, f1);
        }
        __syncthreads();

        // ---- MMA: 16 ksteps, single fp16 term ----
        float acc[4][2][4];
        #pragma unroll
        for (int nt = 0; nt < 4; nt++)
            #pragma unroll
            for (int mt = 0; mt < 2; mt++)
                #pragma unroll
                for (int c = 0; c < 4; c++) acc[nt][mt][c] = 0.f;

        int abase[2][2];
        #pragma unroll
        for (int mt = 0; mt < 2; mt++)
            #pragma unroll
            for (int rr = 0; rr < 2; rr++) {
                int row = wr * 32 + mt * 16 + rr * 8 + tq;
                abase[mt][rr] = row * 544 + ((row >> 2) & 7) * 4 + tm * 8;
            }

        #pragma unroll 4
        for (int sg = 0; sg < 16; sg++) {
            uint2 Bh[4];
            #pragma unroll
            for (int nt = 0; nt < 4; nt++) {
                int n = wc * 32 + nt * 8 + tq;
                Bh[nt] = *(const uint2*)(smem + SM_BHI + n * 544 + sg * 32 + tm * 8);
            }
            uint32_t Ah[2][2][2];   // [mt][rr][word]
            #pragma unroll
            for (int mt = 0; mt < 2; mt++)
                #pragma unroll
                for (int rr = 0; rr < 2; rr++) {
                    int off = abase[mt][rr] + sg * 32;
                    Ah[mt][rr][0] = *(const uint32_t*)(smem + SM_HHI + off);
                    Ah[mt][rr][1] = *(const uint32_t*)(smem + SM_HHI + off + 4);
                }
            #pragma unroll
            for (int nt = 0; nt < 4; nt++)
                #pragma unroll
                for (int mt = 0; mt < 2; mt++) {
                    float* c = acc[nt][mt];
                    mma_f16(c[0], c[1], c[2], c[3],
                            Ah[mt][0][0], Ah[mt][1][0], Ah[mt][0][1], Ah[mt][1][1],
                            Bh[nt].x, Bh[nt].y);
                }
        }
        __syncthreads();   // all H/B reads done; H area reusable as sDotp/sPart

        // ---- epilogue: bias -> relu -> mask -> row sums ----
        if (nh) {
            float da, db;
            unpackf2(da, db, dot2);
            sDotp[sub * 128 + r] = da + db;
        }
        {
            const float vA = sValid[wr * 32 + tq];
            const float vB = sValid[wr * 32 + tq + 8];
            const float vC = sValid[wr * 32 + tq + 16];
            const float vD = sValid[wr * 32 + tq + 24];
            #pragma unroll
            for (int nt = 0; nt < 4; nt++) {
                int c0 = wc * 32 + nt * 8 + tm * 2;
                float e0 = sB2[c0], e1 = sB2[c0 + 1];
                float* a0 = acc[nt][0];
                float* a1 = acc[nt][1];
                float p0 = fmaxf(a0[0] + e0, 0.f) * vA + fmaxf(a0[2] + e0, 0.f) * vB
                         + fmaxf(a1[0] + e0, 0.f) * vC + fmaxf(a1[2] + e0, 0.f) * vD;
                float p1 = fmaxf(a0[1] + e1, 0.f) * vA + fmaxf(a0[3] + e1, 0.f) * vB
                         + fmaxf(a1[1] + e1, 0.f) * vC + fmaxf(a1[3] + e1, 0.f) * vD;
                p0 += __shfl_down_sync(0xffffffffu, p0, 16);
                p0 += __shfl_down_sync(0xffffffffu, p0, 8);
                p0 += __shfl_down_sync(0xffffffffu, p0, 4);
                p1 += __shfl_down_sync(0xffffffffu, p1, 16);
                p1 += __shfl_down_sync(0xffffffffu, p1, 8);
                p1 += __shfl_down_sync(0xffffffffu, p1, 4);
                if (tq == 0) {
                    sPart[wr * 128 + c0]     = p0;
                    sPart[wr * 128 + c0 + 1] = p1;
                }
            }
        }
        __syncthreads();

        if (tid < 256) {   // combine row-groups -> g_x
            int e = tid >> 7, col = tid & 127;
            float val = sPart[(2 * e) * 128 + col] + sPart[(2 * e + 1) * 128 + col];
            g_x[(size_t)(b0 + e) * QIN + 8 + nh * 128 + col] = val;
        }
        if (nh) {
            if (tid < 128) {
                float dsum = sDotp[tid] + sDotp[128 + tid]
                           + sDotp[256 + tid] + sDotp[384 + tid];
                sDotp[tid] = fmaxf(dsum + sB2[128], 0.f) * sValid[tid];
            }
            __syncthreads();
            if (w < 2) {
                float tt = sDotp[w * 64 + lane] + sDotp[w * 64 + 32 + lane];
                #pragma unroll
                for (int off = 16; off > 0; off >>= 1)
                    tt += __shfl_down_sync(0xffffffffu, tt, off);
                if (lane == 0) g_x[(size_t)(b0 + w) * QIN + 264] = tt;
            }
            if (tid < 16)
                g_x[(size_t)(b0 + (tid >> 3)) * QIN + (tid & 7)] =
                    s[(size_t)(b0 + (tid >> 3)) * SROW + (tid & 7)];
        }
        __syncthreads();
    }
}

// ---------------------------------------------------------------------------
// Q head: 16 rows per CTA, 2 hidden units x 8 rows per thread.
// ---------------------------------------------------------------------------
__global__ void __launch_bounds__(256) qhead_kernel(
    const float* __restrict__ Qw1, const float* __restrict__ Qb1,
    const float* __restrict__ Qw2, const float* __restrict__ Qb2,
    float* __restrict__ out)
{
    extern __shared__ float qs[];
    float* shX  = qs + QS_X;     // [16][265]
    float* shHq = qs + QS_HQ;    // [16][256]
    float* shW2 = qs + QS_W2;    // [256][30]

    const int b0  = blockIdx.x * 16;
    const int tid = threadIdx.x;

    for (int i = tid; i < 16 * QIN; i += 256) shX[i] = g_x[(size_t)b0 * QIN + i];
    for (int i = tid; i < HID * ADIM; i += 256) shW2[i] = Qw2[i];
    __syncthreads();

    // layer 1: thread (hh, rg): hidden units {2hh, 2hh+1}, rows [rg*8, rg*8+8)
    {
        const int hh = tid & 127;
        const int rg = tid >> 7;
        const float* xb = shX + rg * 8 * QIN;
        float2 qb = *(const float2*)(Qb1 + 2 * hh);
        float a0[8], a1[8];
        #pragma unroll
        for (int r = 0; r < 8; r++) { a0[r] = qb.x; a1[r] = qb.y; }
        #pragma unroll 5
        for (int k = 0; k < QIN; k++) {
            float2 wv = *(const float2*)(Qw1 + (size_t)k * HID + 2 * hh);
            #pragma unroll
            for (int r = 0; r < 8; r++) {
                float xv = xb[r * QIN + k];
                a0[r] = fmaf(xv, wv.x, a0[r]);
                a1[r] = fmaf(xv, wv.y, a1[r]);
            }
        }
        float* hq = shHq + rg * 8 * HID + 2 * hh;
        #pragma unroll
        for (int r = 0; r < 8; r++) {
            float2 hv = make_float2(fmaxf(a0[r], 0.f), fmaxf(a1[r], 0.f));
            *(float2*)(hq + r * HID) = hv;
        }
    }
    __syncthreads();

    // layer 2: 480 outputs (16 rows x 30 cols)
    for (int o = tid; o < 16 * ADIM; o += 256) {
        int r = o / ADIM, c = o - r * ADIM;
        float a = Qb2[c];
        const float* hp = shHq + r * HID;
        #pragma unroll 8
        for (int k = 0; k < HID; k++)
            a = fmaf(hp[k], shW2[k * ADIM + c], a);
        out[(size_t)(b0 + r) * ADIM + c] = a;
    }
}

// ---------------------------------------------------------------------------
extern "C" void kernel_launch(void* const* d_in, const int* in_sizes, int n_in,
                              void* d_out, int out_size)
{
    const float* s   = (const float*)d_in[0];
    const float* W1  = (const float*)d_in[1];
    const float* b1  = (const float*)d_in[2];
    const float* W2  = (const float*)d_in[3];
    const float* b2  = (const float*)d_in[4];
    const float* Qw1 = (const float*)d_in[5];
    const float* Qb1 = (const float*)d_in[6];
    const float* Qw2 = (const float*)d_in[7];
    const float* Qb2 = (const float*)d_in[8];
    float* out = (float*)d_out;

    cudaFuncSetAttribute(enc_kernel,
                         cudaFuncAttributeMaxDynamicSharedMemorySize, SM_TOTAL);
    cudaFuncSetAttribute(qhead_kernel,
                         cudaFuncAttributeMaxDynamicSharedMemorySize, QS_TOT * 4);

    enc_kernel<<<1024, 512, SM_TOTAL>>>(s, W1, b1, W2, b2);
    qhead_kernel<<<BATCH / 16, 256, QS_TOT * 4>>>(Qw1, Qb1, Qw2, Qb2, out);
}

// round 9
// speedup vs baseline: 5.4012x; 1.0998x over previous
#include <cuda_runtime.h>
#include <cuda_fp16.h>
#include <cstdint>

#define BATCH 8192
#define CAR   8
#define HID   256
#define QIN   265
#define ADIM  30
#define SROW  520

// ---- enc smem offsets (bytes) ----
#define SM_BHI   0         // 128n x 544B fp16 B slab (word*4, permuted k)
#define SM_H0    69632     // H buffer 0: 128r x 544B fp16, rotated rows
#define SM_H1    139264    // H buffer 1
#define SM_W1T   208896    // 128kp x 16 floats (pair-packed) = 8192
#define SM_B1    217088    // 1024
#define SM_B2    218112    // 129 floats -> pad 528
#define SM_WLAST 218640    // 1024
#define SM_VALID 219664    // 2 bufs x 128 floats = 1024
#define SM_TOTAL 220688
// epilogue scratch aliases the just-consumed H buffer:
//   sDotp = hcur + 0 (2048B), sPart = hcur + 2048 (2048B)

__device__ float g_x[BATCH * QIN];

// ---------------------------------------------------------------------------
__device__ __forceinline__ uint32_t cvt_f16x2(float lo, float hi) {
    uint32_t u;
    asm("cvt.rn.f16x2.f32 %0, %1, %2;" : "=r"(u) : "f"(hi), "f"(lo));
    return u;
}
__device__ __forceinline__ unsigned long long packf2(float a, float b) {
    unsigned long long u;
    asm("mov.b64 %0, {%1,%2};" : "=l"(u) : "f"(a), "f"(b));
    return u;
}
__device__ __forceinline__ void unpackf2(float& a, float& b, unsigned long long u) {
    asm("mov.b64 {%0,%1}, %2;" : "=f"(a), "=f"(b) : "l"(u));
}
__device__ __forceinline__ void fma2(unsigned long long& d, unsigned long long a,
                                     unsigned long long b) {
    asm("fma.rn.f32x2 %0, %1, %2, %0;" : "+l"(d) : "l"(a), "l"(b));
}
__device__ __forceinline__ void mma_f16(float& c0, float& c1, float& c2, float& c3,
                                        uint32_t a0, uint32_t a1, uint32_t a2, uint32_t a3,
                                        uint32_t b0, uint32_t b1) {
    asm volatile(
        "mma.sync.aligned.m16n8k16.row.col.f32.f16.f16.f32 "
        "{%0,%1,%2,%3}, {%4,%5,%6,%7}, {%8,%9}, {%0,%1,%2,%3};"
        : "+f"(c0), "+f"(c1), "+f"(c2), "+f"(c3)
        : "r"(a0), "r"(a1), "r"(a2), "r"(a3), "r"(b0), "r"(b1));
}

// one H iteration: computes H[r][kl], H[r][kl+1] (kl = sub*64+2*jj),
// accumulates col-256 dot, stores fp16x2 into H buffer HOFF.
#define H_ITER(jj_, HOFF_) do {                                               \
    const int kl_ = sub * 64 + 2 * (jj_);                                     \
    const int kp_ = kl_ >> 1;                                                 \
    ulonglong2 wA_ = *(const ulonglong2*)(sW1t + kp_ * 16);                   \
    ulonglong2 wB_ = *(const ulonglong2*)(sW1t + kp_ * 16 + 4);               \
    ulonglong2 wC_ = *(const ulonglong2*)(sW1t + kp_ * 16 + 8);               \
    ulonglong2 wD_ = *(const ulonglong2*)(sW1t + kp_ * 16 + 12);              \
    unsigned long long acc2_ = *(const unsigned long long*)(sB1 + kl_);       \
    fma2(acc2_, wA_.x, sp0); fma2(acc2_, wA_.y, sp1);                         \
    fma2(acc2_, wB_.x, sp2); fma2(acc2_, wB_.y, sp3);                         \
    fma2(acc2_, wC_.x, sp4); fma2(acc2_, wC_.y, sp5);                         \
    fma2(acc2_, wD_.x, sp6); fma2(acc2_, wD_.y, sp7);                         \
    float f0_, f1_;                                                           \
    unpackf2(f0_, f1_, acc2_);                                                \
    f0_ = fmaxf(f0_, 0.f); f1_ = fmaxf(f1_, 0.f);                             \
    if (nh) {                                                                 \
        unsigned long long wl_ = *(const unsigned long long*)(sWlast + kl_);  \
        fma2(dot_nxt, packf2(f0_, f1_), wl_);                                 \
    }                                                                         \
    const int sL_ = kl_ >> 4;                                                 \
    const int j8_ = (jj_) & 7;                                                \
    const int woff_ = (sL_ * 8 + (j8_ & 3) * 2 + (j8_ >> 2)) * 4;             \
    *(uint32_t*)(smem + (HOFF_) + rowbase + woff_) = cvt_f16x2(f0_, f1_);     \
} while (0)

// ---------------------------------------------------------------------------
// encoder: CTA = (group of 16 batch elems) x (N-half). 8 tiles of M=128 rows.
// 512 threads, warp grid 4M x 4N. fp16 GEMM, H(t+1) pipelined under MMA(t).
// ---------------------------------------------------------------------------
__global__ void __launch_bounds__(512, 1) enc_kernel(
    const float* __restrict__ s, const float* __restrict__ W1,
    const float* __restrict__ b1, const float* __restrict__ W2,
    const float* __restrict__ b2)
{
    extern __shared__ char smem[];
    const int tid = threadIdx.x;
    const int nh  = blockIdx.x & 1;
    const int grp = blockIdx.x >> 1;
    const int w    = tid >> 5, lane = tid & 31;
    const int wr   = w & 3,   wc   = w >> 2;
    const int tq   = lane >> 2, tm = lane & 3;
    const int r    = tid & 127, sub = tid >> 7;   // sub uniform per warp
    const int e    = r >> 6;                      // batch elem within tile
    const int ro   = r & 63;                      // agent row within elem

    float* sW1t   = (float*)(smem + SM_W1T);
    float* sB1    = (float*)(smem + SM_B1);
    float* sB2    = (float*)(smem + SM_B2);
    float* sWlast = (float*)(smem + SM_WLAST);
    float* sValid = (float*)(smem + SM_VALID);

    // ---- prologue: fp16 B slab (permuted layout) from W2 (L2-hot) ----
    for (int i = tid; i < 16384; i += 512) {
        int word = i >> 7, n = i & 127;
        int sL = word >> 3, rem = word & 7, q = rem >> 1, h2 = rem & 1;
        int k0 = sL * 16 + 2 * (h2 * 4 + q);
        float f0 = W2[(size_t)k0 * 257 + nh * 128 + n];
        float f1 = W2[(size_t)(k0 + 1) * 257 + nh * 128 + n];
        *(uint32_t*)(smem + SM_BHI + n * 544 + word * 4) = cvt_f16x2(f0, f1);
    }
    for (int i = tid; i < 2048; i += 512) {   // W1 pair-packed
        int kp = i >> 4, rem = i & 15, c = rem >> 1, h = rem & 1;
        sW1t[i] = W1[c * HID + kp * 2 + h];
    }
    if (tid < 256) {
        sB1[tid] = b1[tid];
        sWlast[tid] = W2[(size_t)tid * 257 + 256];
    }
    for (int i = tid; i < 129; i += 512)
        sB2[i] = (i < 128) ? b2[nh * 128 + i] : b2[256];
    __syncthreads();

    const int rrot    = ((r >> 2) & 7) * 4;
    const int rowbase = r * 544 + rrot;
    int abase[2][2];
    #pragma unroll
    for (int mt = 0; mt < 2; mt++)
        #pragma unroll
        for (int rr = 0; rr < 2; rr++) {
            int row = wr * 32 + mt * 16 + rr * 8 + tq;
            abase[mt][rr] = row * 544 + ((row >> 2) & 7) * 4 + tm * 8;
        }

    // ---- preload tile 0: surr rows direct from global ----
    const float* srow0 = s + (size_t)(grp * 16 + e) * SROW + CAR + ro * 8;
    float4 c0 = *(const float4*)srow0;
    float4 c1 = *(const float4*)(srow0 + 4);
    unsigned long long sp0, sp1, sp2, sp3, sp4, sp5, sp6, sp7;
    unsigned long long dot_nxt = packf2(0.f, 0.f), dot_cur;

    {   // valid(0) + H(0) -> buffer H0
        if (sub == 0) {
            float v = 1.0f;
            if (c0.x == -1.f || c0.y == -1.f || c0.z == -1.f || c0.w == -1.f ||
                c1.x == -1.f || c1.y == -1.f || c1.z == -1.f || c1.w == -1.f) v = 0.f;
            sValid[r] = v;
        }
        sp0 = packf2(c0.x, c0.x); sp1 = packf2(c0.y, c0.y);
        sp2 = packf2(c0.z, c0.z); sp3 = packf2(c0.w, c0.w);
        sp4 = packf2(c1.x, c1.x); sp5 = packf2(c1.y, c1.y);
        sp6 = packf2(c1.z, c1.z); sp7 = packf2(c1.w, c1.w);
        #pragma unroll 4
        for (int jj = 0; jj < 32; jj++) H_ITER(jj, SM_H0);
    }
    __syncthreads();

    for (int t = 0; t < 8; t++) {
        const int b0   = grp * 16 + t * 2;
        const int hcur = (t & 1) ? SM_H1 : SM_H0;
        const int hnxt = (t & 1) ? SM_H0 : SM_H1;
        const int doH  = (t < 7);

        dot_cur = dot_nxt;
        dot_nxt = packf2(0.f, 0.f);

        // prefetch surr for tile t+1; build sp regs; write valid(t+1)
        if (doH) {
            const float* srn = s + (size_t)(b0 + 2 + e) * SROW + CAR + ro * 8;
            c0 = *(const float4*)srn;
            c1 = *(const float4*)(srn + 4);
            if (sub == 0) {
                float v = 1.0f;
                if (c0.x == -1.f || c0.y == -1.f || c0.z == -1.f || c0.w == -1.f ||
                    c1.x == -1.f || c1.y == -1.f || c1.z == -1.f || c1.w == -1.f) v = 0.f;
                sValid[(1 - (t & 1)) * 128 + r] = v;
            }
            sp0 = packf2(c0.x, c0.x); sp1 = packf2(c0.y, c0.y);
            sp2 = packf2(c0.z, c0.z); sp3 = packf2(c0.w, c0.w);
            sp4 = packf2(c1.x, c1.x); sp5 = packf2(c1.y, c1.y);
            sp6 = packf2(c1.z, c1.z); sp7 = packf2(c1.w, c1.w);
        }

        // ---- MMA(t) with H(t+1) interleaved ----
        float acc[4][2][4];
        #pragma unroll
        for (int nt = 0; nt < 4; nt++)
            #pragma unroll
            for (int mt = 0; mt < 2; mt++)
                #pragma unroll
                for (int c = 0; c < 4; c++) acc[nt][mt][c] = 0.f;

        #pragma unroll 4
        for (int sg = 0; sg < 16; sg++) {
            uint2 Bh[4];
            #pragma unroll
            for (int nt = 0; nt < 4; nt++) {
                int n = wc * 32 + nt * 8 + tq;
                Bh[nt] = *(const uint2*)(smem + SM_BHI + n * 544 + sg * 32 + tm * 8);
            }
            uint32_t Ah[2][2][2];
            #pragma unroll
            for (int mt = 0; mt < 2; mt++)
                #pragma unroll
                for (int rr = 0; rr < 2; rr++) {
                    int off = abase[mt][rr] + sg * 32;
                    Ah[mt][rr][0] = *(const uint32_t*)(smem + hcur + off);
                    Ah[mt][rr][1] = *(const uint32_t*)(smem + hcur + off + 4);
                }
            #pragma unroll
            for (int nt = 0; nt < 4; nt++)
                #pragma unroll
                for (int mt = 0; mt < 2; mt++) {
                    float* c = acc[nt][mt];
                    mma_f16(c[0], c[1], c[2], c[3],
                            Ah[mt][0][0], Ah[mt][1][0], Ah[mt][0][1], Ah[mt][1][1],
                            Bh[nt].x, Bh[nt].y);
                }
            if (doH) {
                H_ITER(2 * sg,     hnxt);
                H_ITER(2 * sg + 1, hnxt);
            }
        }
        __syncthreads();   // MMA reads of hcur + H writes to hnxt complete

        // ---- epilogue (scratch aliases hcur) ----
        float* sDotp = (float*)(smem + hcur);
        float* sPart = (float*)(smem + hcur + 2048);
        const float* sVal = sValid + (t & 1) * 128;

        if (nh) {
            float da, db;
            unpackf2(da, db, dot_cur);
            sDotp[sub * 128 + r] = da + db;
        }
        {
            const float vA = sVal[wr * 32 + tq];
            const float vB = sVal[wr * 32 + tq + 8];
            const float vC = sVal[wr * 32 + tq + 16];
            const float vD = sVal[wr * 32 + tq + 24];
            #pragma unroll
            for (int nt = 0; nt < 4; nt++) {
                int c0i = wc * 32 + nt * 8 + tm * 2;
                float e0 = sB2[c0i], e1 = sB2[c0i + 1];
                float* a0 = acc[nt][0];
                float* a1 = acc[nt][1];
                float p0 = fmaxf(a0[0] + e0, 0.f) * vA + fmaxf(a0[2] + e0, 0.f) * vB
                         + fmaxf(a1[0] + e0, 0.f) * vC + fmaxf(a1[2] + e0, 0.f) * vD;
                float p1 = fmaxf(a0[1] + e1, 0.f) * vA + fmaxf(a0[3] + e1, 0.f) * vB
                         + fmaxf(a1[1] + e1, 0.f) * vC + fmaxf(a1[3] + e1, 0.f) * vD;
                p0 += __shfl_down_sync(0xffffffffu, p0, 16);
                p0 += __shfl_down_sync(0xffffffffu, p0, 8);
                p0 += __shfl_down_sync(0xffffffffu, p0, 4);
                p1 += __shfl_down_sync(0xffffffffu, p1, 16);
                p1 += __shfl_down_sync(0xffffffffu, p1, 8);
                p1 += __shfl_down_sync(0xffffffffu, p1, 4);
                if (tq == 0) {
                    sPart[wr * 128 + c0i]     = p0;
                    sPart[wr * 128 + c0i + 1] = p1;
                }
            }
        }
        __syncthreads();

        if (tid < 256) {
            int ee = tid >> 7, col = tid & 127;
            float val = sPart[(2 * ee) * 128 + col] + sPart[(2 * ee + 1) * 128 + col];
            g_x[(size_t)(b0 + ee) * QIN + 8 + nh * 128 + col] = val;
        }
        if (nh) {
            if (tid < 128) {
                float dsum = sDotp[tid] + sDotp[128 + tid]
                           + sDotp[256 + tid] + sDotp[384 + tid];
                sDotp[tid] = fmaxf(dsum + sB2[128], 0.f) * sVal[tid];
            }
            __syncthreads();
            if (w < 2) {
                float tt = sDotp[w * 64 + lane] + sDotp[w * 64 + 32 + lane];
                #pragma unroll
                for (int off = 16; off > 0; off >>= 1)
                    tt += __shfl_down_sync(0xffffffffu, tt, off);
                if (lane == 0) g_x[(size_t)(b0 + w) * QIN + 264] = tt;
            }
            if (tid < 16)
                g_x[(size_t)(b0 + (tid >> 3)) * QIN + (tid & 7)] =
                    s[(size_t)(b0 + (tid >> 3)) * SROW + (tid & 7)];
        }
        __syncthreads();   // epilogue scratch (hcur) free before H(t+2) writes
    }
}

// ---------------------------------------------------------------------------
// Q head (R7 version, measured 95us): 8 rows per CTA
// ---------------------------------------------------------------------------
__global__ void __launch_bounds__(256) qhead_kernel(
    const float* __restrict__ Qw1, const float* __restrict__ Qb1,
    const float* __restrict__ Qw2, const float* __restrict__ Qb2,
    float* __restrict__ out)
{
    __shared__ float shX[8 * QIN];
    __shared__ float shHq[8 * HID];
    __shared__ float shW2[HID * ADIM];

    const int b0  = blockIdx.x * 8;
    const int tid = threadIdx.x;

    for (int i = tid; i < 8 * QIN;    i += 256) shX[i]  = g_x[(size_t)b0 * QIN + i];
    for (int i = tid; i < HID * ADIM; i += 256) shW2[i] = Qw2[i];
    __syncthreads();

    float acc[8];
    {
        const float qb = Qb1[tid];
        #pragma unroll
        for (int r = 0; r < 8; r++) acc[r] = qb;
        #pragma unroll 5
        for (int k = 0; k < QIN; k++) {
            float wv = Qw1[k * HID + tid];
            #pragma unroll
            for (int r = 0; r < 8; r++)
                acc[r] = fmaf(shX[r * QIN + k], wv, acc[r]);
        }
        #pragma unroll
        for (int r = 0; r < 8; r++) shHq[r * HID + tid] = fmaxf(acc[r], 0.0f);
    }
    __syncthreads();

    if (tid < 8 * ADIM) {
        int r = tid / ADIM, c = tid - r * ADIM;
        float a = Qb2[c];
        const float* hp = shHq + r * HID;
        #pragma unroll 8
        for (int k = 0; k < HID; k++)
            a = fmaf(hp[k], shW2[k * ADIM + c], a);
        out[(size_t)(b0 + r) * ADIM + c] = a;
    }
}

// ---------------------------------------------------------------------------
extern "C" void kernel_launch(void* const* d_in, const int* in_sizes, int n_in,
                              void* d_out, int out_size)
{
    const float* s   = (const float*)d_in[0];
    const float* W1  = (const float*)d_in[1];
    const float* b1  = (const float*)d_in[2];
    const float* W2  = (const float*)d_in[3];
    const float* b2  = (const float*)d_in[4];
    const float* Qw1 = (const float*)d_in[5];
    const float* Qb1 = (const float*)d_in[6];
    const float* Qw2 = (const float*)d_in[7];
    const float* Qb2 = (const float*)d_in[8];
    float* out = (float*)d_out;

    cudaFuncSetAttribute(enc_kernel,
                         cudaFuncAttributeMaxDynamicSharedMemorySize, SM_TOTAL);

    enc_kernel<<<1024, 512, SM_TOTAL>>>(s, W1, b1, W2, b2);
    qhead_kernel<<<BATCH / 8, 256>>>(Qw1, Qb1, Qw2, Qb2, out);
}

// round 10
// speedup vs baseline: 5.4379x; 1.0068x over previous
#include <cuda_runtime.h>
#include <cuda_fp16.h>
#include <cstdint>

#define BATCH 8192
#define CAR   8
#define HID   256
#define QIN   265
#define ADIM  30
#define SROW  520

// ---- enc smem offsets (bytes) ----
#define SM_BHI   0         // 128n x 544B fp16 B slab (word*4, permuted k)
#define SM_HHI   69632     // 128r x 544B fp16 H, full K=256, rotated rows
#define SM_W1T   139264    // 128kp x 16 floats (pair-packed)   = 8192
#define SM_B1    147456    // 1024
#define SM_B2    148480    // 129 floats -> pad 528
#define SM_WLAST 149008    // 1024
#define SM_SURR  150032    // 4096  (16B-aligned)
#define SM_VALID 154128    // 512
#define SM_TOTAL 154640
// aliases (valid only after MMA reads of H complete):
//   sDotp = SM_HHI + 0    (2048B)
//   sPart = SM_HHI + 2048 (2048B)

__device__ float g_x[BATCH * QIN];

// ---------------------------------------------------------------------------
__device__ __forceinline__ uint32_t cvt_f16x2(float lo, float hi) {
    uint32_t u;
    asm("cvt.rn.f16x2.f32 %0, %1, %2;" : "=r"(u) : "f"(hi), "f"(lo));
    return u;
}
__device__ __forceinline__ unsigned long long packf2(float a, float b) {
    unsigned long long u;
    asm("mov.b64 %0, {%1,%2};" : "=l"(u) : "f"(a), "f"(b));
    return u;
}
__device__ __forceinline__ void unpackf2(float& a, float& b, unsigned long long u) {
    asm("mov.b64 {%0,%1}, %2;" : "=f"(a), "=f"(b) : "l"(u));
}
__device__ __forceinline__ void fma2(unsigned long long& d, unsigned long long a,
                                     unsigned long long b) {
    asm("fma.rn.f32x2 %0, %1, %2, %0;" : "+l"(d) : "l"(a), "l"(b));
}
__device__ __forceinline__ void mma_f16(float& c0, float& c1, float& c2, float& c3,
                                        uint32_t a0, uint32_t a1, uint32_t a2, uint32_t a3,
                                        uint32_t b0, uint32_t b1) {
    asm volatile(
        "mma.sync.aligned.m16n8k16.row.col.f32.f16.f16.f32 "
        "{%0,%1,%2,%3}, {%4,%5,%6,%7}, {%8,%9}, {%0,%1,%2,%3};"
        : "+f"(c0), "+f"(c1), "+f"(c2), "+f"(c3)
        : "r"(a0), "r"(a1), "r"(a2), "r"(a3), "r"(b0), "r"(b1));
}

// ---------------------------------------------------------------------------
// encoder (R8 version, measured ~360us): CTA = 16 batch elems x N-half.
// 8 tiles of M=128 rows. 512 threads, warp grid 4Mx4N. pure fp16 GEMM.
// ---------------------------------------------------------------------------
__global__ void __launch_bounds__(512, 1) enc_kernel(
    const float* __restrict__ s, const float* __restrict__ W1,
    const float* __restrict__ b1, const float* __restrict__ W2,
    const float* __restrict__ b2)
{
    extern __shared__ char smem[];
    const int tid = threadIdx.x;
    const int nh  = blockIdx.x & 1;
    const int grp = blockIdx.x >> 1;
    const int w    = tid >> 5, lane = tid & 31;
    const int wr   = w & 3,   wc   = w >> 2;
    const int tq   = lane >> 2, tm = lane & 3;
    const int r    = tid & 127, sub = tid >> 7;

    float* sW1t   = (float*)(smem + SM_W1T);
    float* sB1    = (float*)(smem + SM_B1);
    float* sB2    = (float*)(smem + SM_B2);
    float* sWlast = (float*)(smem + SM_WLAST);
    float* sSurr  = (float*)(smem + SM_SURR);
    float* sValid = (float*)(smem + SM_VALID);
    float* sDotp  = (float*)(smem + SM_HHI);
    float* sPart  = (float*)(smem + SM_HHI + 2048);

    for (int i = tid; i < 16384; i += 512) {
        int word = i >> 7, n = i & 127;
        int sL = word >> 3, rem = word & 7, q = rem >> 1, h2 = rem & 1;
        int k0 = sL * 16 + 2 * (h2 * 4 + q);
        float f0 = W2[(size_t)k0 * 257 + nh * 128 + n];
        float f1 = W2[(size_t)(k0 + 1) * 257 + nh * 128 + n];
        *(uint32_t*)(smem + SM_BHI + n * 544 + word * 4) = cvt_f16x2(f0, f1);
    }
    for (int i = tid; i < 2048; i += 512) {
        int kp = i >> 4, rem = i & 15, c = rem >> 1, h = rem & 1;
        sW1t[i] = W1[c * HID + kp * 2 + h];
    }
    if (tid < 256) {
        sB1[tid] = b1[tid];
        sWlast[tid] = W2[(size_t)tid * 257 + 256];
    }
    for (int i = tid; i < 129; i += 512)
        sB2[i] = (i < 128) ? b2[nh * 128 + i] : b2[256];
    __syncthreads();

    const int rrot    = ((r >> 2) & 7) * 4;
    const int rowbase = r * 544 + rrot;

    for (int t = 0; t < 8; t++) {
        const int b0 = grp * 16 + t * 2;

        if (tid < 256) {
            int e = tid >> 7, j = tid & 127;
            ((float4*)sSurr)[e * 128 + j] =
                ((const float4*)(s + (size_t)(b0 + e) * SROW + CAR))[j];
        }
        __syncthreads();

        const float4 s0 = ((const float4*)sSurr)[r * 2];
        const float4 s1 = ((const float4*)sSurr)[r * 2 + 1];
        if (tid < 128) {
            float v = 1.0f;
            if (s0.x == -1.f || s0.y == -1.f || s0.z == -1.f || s0.w == -1.f ||
                s1.x == -1.f || s1.y == -1.f || s1.z == -1.f || s1.w == -1.f) v = 0.f;
            sValid[tid] = v;
        }
        const unsigned long long sp0 = packf2(s0.x, s0.x), sp1 = packf2(s0.y, s0.y);
        const unsigned long long sp2 = packf2(s0.z, s0.z), sp3 = packf2(s0.w, s0.w);
        const unsigned long long sp4 = packf2(s1.x, s1.x), sp5 = packf2(s1.y, s1.y);
        const unsigned long long sp6 = packf2(s1.z, s1.z), sp7 = packf2(s1.w, s1.w);

        unsigned long long dot2 = packf2(0.f, 0.f);
        #pragma unroll 4
        for (int jj = 0; jj < 32; jj++) {
            const int kl = sub * 64 + 2 * jj;
            const int kp = kl >> 1;
            ulonglong2 wA = *(const ulonglong2*)(sW1t + kp * 16);
            ulonglong2 wB = *(const ulonglong2*)(sW1t + kp * 16 + 4);
            ulonglong2 wC = *(const ulonglong2*)(sW1t + kp * 16 + 8);
            ulonglong2 wD = *(const ulonglong2*)(sW1t + kp * 16 + 12);
            unsigned long long acc2 = *(const unsigned long long*)(sB1 + kl);
            fma2(acc2, wA.x, sp0); fma2(acc2, wA.y, sp1);
            fma2(acc2, wB.x, sp2); fma2(acc2, wB.y, sp3);
            fma2(acc2, wC.x, sp4); fma2(acc2, wC.y, sp5);
            fma2(acc2, wD.x, sp6); fma2(acc2, wD.y, sp7);
            float f0, f1;
            unpackf2(f0, f1, acc2);
            f0 = fmaxf(f0, 0.f); f1 = fmaxf(f1, 0.f);
            if (nh) {
                unsigned long long wl = *(const unsigned long long*)(sWlast + kl);
                fma2(dot2, packf2(f0, f1), wl);
            }
            const int sL = kl >> 4;
            const int j8 = jj & 7;
            const int woff = (sL * 8 + (j8 & 3) * 2 + (j8 >> 2)) * 4;
            *(uint32_t*)(smem + SM_HHI + rowbase + woff) = cvt_f16x2(f0, f1);
        }
        __syncthreads();

        float acc[4][2][4];
        #pragma unroll
        for (int nt = 0; nt < 4; nt++)
            #pragma unroll
            for (int mt = 0; mt < 2; mt++)
                #pragma unroll
                for (int c = 0; c < 4; c++) acc[nt][mt][c] = 0.f;

        int abase[2][2];
        #pragma unroll
        for (int mt = 0; mt < 2; mt++)
            #pragma unroll
            for (int rr = 0; rr < 2; rr++) {
                int row = wr * 32 + mt * 16 + rr * 8 + tq;
                abase[mt][rr] = row * 544 + ((row >> 2) & 7) * 4 + tm * 8;
            }

        #pragma unroll 4
        for (int sg = 0; sg < 16; sg++) {
            uint2 Bh[4];
            #pragma unroll
            for (int nt = 0; nt < 4; nt++) {
                int n = wc * 32 + nt * 8 + tq;
                Bh[nt] = *(const uint2*)(smem + SM_BHI + n * 544 + sg * 32 + tm * 8);
            }
            uint32_t Ah[2][2][2];
            #pragma unroll
            for (int mt = 0; mt < 2; mt++)
                #pragma unroll
                for (int rr = 0; rr < 2; rr++) {
                    int off = abase[mt][rr] + sg * 32;
                    Ah[mt][rr][0] = *(const uint32_t*)(smem + SM_HHI + off);
                    Ah[mt][rr][1] = *(const uint32_t*)(smem + SM_HHI + off + 4);
                }
            #pragma unroll
            for (int nt = 0; nt < 4; nt++)
                #pragma unroll
                for (int mt = 0; mt < 2; mt++) {
                    float* c = acc[nt][mt];
                    mma_f16(c[0], c[1], c[2], c[3],
                            Ah[mt][0][0], Ah[mt][1][0], Ah[mt][0][1], Ah[mt][1][1],
                            Bh[nt].x, Bh[nt].y);
                }
        }
        __syncthreads();

        if (nh) {
            float da, db;
            unpackf2(da, db, dot2);
            sDotp[sub * 128 + r] = da + db;
        }
        {
            const float vA = sValid[wr * 32 + tq];
            const float vB = sValid[wr * 32 + tq + 8];
            const float vC = sValid[wr * 32 + tq + 16];
            const float vD = sValid[wr * 32 + tq + 24];
            #pragma unroll
            for (int nt = 0; nt < 4; nt++) {
                int c0 = wc * 32 + nt * 8 + tm * 2;
                float e0 = sB2[c0], e1 = sB2[c0 + 1];
                float* a0 = acc[nt][0];
                float* a1 = acc[nt][1];
                float p0 = fmaxf(a0[0] + e0, 0.f) * vA + fmaxf(a0[2] + e0, 0.f) * vB
                         + fmaxf(a1[0] + e0, 0.f) * vC + fmaxf(a1[2] + e0, 0.f) * vD;
                float p1 = fmaxf(a0[1] + e1, 0.f) * vA + fmaxf(a0[3] + e1, 0.f) * vB
                         + fmaxf(a1[1] + e1, 0.f) * vC + fmaxf(a1[3] + e1, 0.f) * vD;
                p0 += __shfl_down_sync(0xffffffffu, p0, 16);
                p0 += __shfl_down_sync(0xffffffffu, p0, 8);
                p0 += __shfl_down_sync(0xffffffffu, p0, 4);
                p1 += __shfl_down_sync(0xffffffffu, p1, 16);
                p1 += __shfl_down_sync(0xffffffffu, p1, 8);
                p1 += __shfl_down_sync(0xffffffffu, p1, 4);
                if (tq == 0) {
                    sPart[wr * 128 + c0]     = p0;
                    sPart[wr * 128 + c0 + 1] = p1;
                }
            }
        }
        __syncthreads();

        if (tid < 256) {
            int e = tid >> 7, col = tid & 127;
            float val = sPart[(2 * e) * 128 + col] + sPart[(2 * e + 1) * 128 + col];
            g_x[(size_t)(b0 + e) * QIN + 8 + nh * 128 + col] = val;
        }
        if (nh) {
            if (tid < 128) {
                float dsum = sDotp[tid] + sDotp[128 + tid]
                           + sDotp[256 + tid] + sDotp[384 + tid];
                sDotp[tid] = fmaxf(dsum + sB2[128], 0.f) * sValid[tid];
            }
            __syncthreads();
            if (w < 2) {
                float tt = sDotp[w * 64 + lane] + sDotp[w * 64 + 32 + lane];
                #pragma unroll
                for (int off = 16; off > 0; off >>= 1)
                    tt += __shfl_down_sync(0xffffffffu, tt, off);
                if (lane == 0) g_x[(size_t)(b0 + w) * QIN + 264] = tt;
            }
            if (tid < 16)
                g_x[(size_t)(b0 + (tid >> 3)) * QIN + (tid & 7)] =
                    s[(size_t)(b0 + (tid >> 3)) * SROW + (tid & 7)];
        }
        __syncthreads();
    }
}

// ---------------------------------------------------------------------------
// Q head v3: 8 rows per CTA, float4-vectorized smem traffic.
//   layer1: thread = hidden unit; x via broadcast LDS.128, Qw1 coalesced LDG.
//   layer2: Qw2 transposed in smem, padded rows (bank-conflict-free float4).
// ---------------------------------------------------------------------------
#define XPAD  268   // 265 -> 268 floats (1072B, 16B-aligned rows)
#define HPAD  260   // 256 -> 260 floats (bank-distinct float4 rows)

__global__ void __launch_bounds__(256) qhead_kernel(
    const float* __restrict__ Qw1, const float* __restrict__ Qb1,
    const float* __restrict__ Qw2, const float* __restrict__ Qb2,
    float* __restrict__ out)
{
    __shared__ float shX[8 * XPAD];      // 8576 B
    __shared__ float shHq[8 * HPAD];     // 8320 B
    __shared__ float shW2T[ADIM * HPAD]; // 31200 B  [c][k], padded

    const int b0  = blockIdx.x * 8;
    const int tid = threadIdx.x;

    for (int i = tid; i < 8 * XPAD; i += 256) {
        int r = i / XPAD, k = i - r * XPAD;
        shX[i] = (k < QIN) ? g_x[(size_t)(b0 + r) * QIN + k] : 0.f;
    }
    for (int i = tid; i < ADIM * HID; i += 256) {
        int c = i >> 8, k = i & 255;
        shW2T[c * HPAD + k] = Qw2[k * ADIM + c];
    }
    __syncthreads();

    // ---- layer 1: hidden unit tid, 8 rows; 66 float4 k-steps + 1 scalar ----
    {
        float acc[8];
        const float qb = Qb1[tid];
        #pragma unroll
        for (int r = 0; r < 8; r++) acc[r] = qb;

        #pragma unroll 3
        for (int kk = 0; kk < 66; kk++) {
            const float* wp = Qw1 + (size_t)(kk * 4) * HID + tid;
            float w0 = wp[0], w1 = wp[HID], w2 = wp[2 * HID], w3 = wp[3 * HID];
            #pragma unroll
            for (int r = 0; r < 8; r++) {
                float4 xv = *(const float4*)(shX + r * XPAD + kk * 4);
                acc[r] = fmaf(xv.x, w0, acc[r]);
                acc[r] = fmaf(xv.y, w1, acc[r]);
                acc[r] = fmaf(xv.z, w2, acc[r]);
                acc[r] = fmaf(xv.w, w3, acc[r]);
            }
        }
        {   // k = 264
            float w0 = Qw1[(size_t)264 * HID + tid];
            #pragma unroll
            for (int r = 0; r < 8; r++)
                acc[r] = fmaf(shX[r * XPAD + 264], w0, acc[r]);
        }
        #pragma unroll
        for (int r = 0; r < 8; r++)
            shHq[r * HPAD + tid] = fmaxf(acc[r], 0.f);
    }
    __syncthreads();

    // ---- layer 2: 240 outputs, float4 dot over padded rows ----
    if (tid < 8 * ADIM) {
        int r = tid / ADIM, c = tid - r * ADIM;
        const float* hp = shHq + r * HPAD;
        const float* wp = shW2T + c * HPAD;
        float a = Qb2[c];
        #pragma unroll 4
        for (int kk = 0; kk < 64; kk++) {
            float4 hv = *(const float4*)(hp + kk * 4);
            float4 wv = *(const float4*)(wp + kk * 4);
            a = fmaf(hv.x, wv.x, a);
            a = fmaf(hv.y, wv.y, a);
            a = fmaf(hv.z, wv.z, a);
            a = fmaf(hv.w, wv.w, a);
        }
        out[(size_t)(b0 + r) * ADIM + c] = a;
    }
}

// ---------------------------------------------------------------------------
extern "C" void kernel_launch(void* const* d_in, const int* in_sizes, int n_in,
                              void* d_out, int out_size)
{
    const float* s   = (const float*)d_in[0];
    const float* W1  = (const float*)d_in[1];
    const float* b1  = (const float*)d_in[2];
    const float* W2  = (const float*)d_in[3];
    const float* b2  = (const float*)d_in[4];
    const float* Qw1 = (const float*)d_in[5];
    const float* Qb1 = (const float*)d_in[6];
    const float* Qw2 = (const float*)d_in[7];
    const float* Qb2 = (const float*)d_in[8];
    float* out = (float*)d_out;

    cudaFuncSetAttribute(enc_kernel,
                         cudaFuncAttributeMaxDynamicSharedMemorySize, SM_TOTAL);

    enc_kernel<<<1024, 512, SM_TOTAL>>>(s, W1, b1, W2, b2);
    qhead_kernel<<<BATCH / 8, 256>>>(Qw1, Qb1, Qw2, Qb2, out);
}

// round 11
// speedup vs baseline: 7.5041x; 1.3800x over previous
#include <cuda_runtime.h>
#include <cuda_fp16.h>
#include <cstdint>

#define BATCH 8192
#define CAR   8
#define HID   256
#define QIN   265
#define ADIM  30
#define SROW  520
#define NCTA  456
#define NTILE 4096

// ---- enc smem offsets (bytes) ----
#define SM_BHI   0         // 256n x 544B fp16 B slab (word*4, permuted k) = 139264
#define SM_HHI   139264    // 128r x 544B fp16 H, full K=256, rotated rows = 69632
#define SM_W1T   208896    // 128kp x 16 floats (pair-packed) = 8192
#define SM_B1    217088    // 1024
#define SM_B2    218112    // 257 floats -> pad 1040
#define SM_WLAST 219152    // 1024
#define SM_SURR  220176    // 4096 (16B-aligned)
#define SM_VALID 224272    // 512
#define SM_TOTAL 224784
// aliases (valid only after MMA reads of H complete):
//   sDotp = SM_HHI + 0    (2048B)
//   sPart = SM_HHI + 2048 (4096B)

__device__ float g_x[BATCH * QIN];

// ---------------------------------------------------------------------------
__device__ __forceinline__ uint32_t cvt_f16x2(float lo, float hi) {
    uint32_t u;
    asm("cvt.rn.f16x2.f32 %0, %1, %2;" : "=r"(u) : "f"(hi), "f"(lo));
    return u;
}
__device__ __forceinline__ unsigned long long packf2(float a, float b) {
    unsigned long long u;
    asm("mov.b64 %0, {%1,%2};" : "=l"(u) : "f"(a), "f"(b));
    return u;
}
__device__ __forceinline__ void unpackf2(float& a, float& b, unsigned long long u) {
    asm("mov.b64 {%0,%1}, %2;" : "=f"(a), "=f"(b) : "l"(u));
}
__device__ __forceinline__ void fma2(unsigned long long& d, unsigned long long a,
                                     unsigned long long b) {
    asm("fma.rn.f32x2 %0, %1, %2, %0;" : "+l"(d) : "l"(a), "l"(b));
}
__device__ __forceinline__ void mma_f16(float& c0, float& c1, float& c2, float& c3,
                                        uint32_t a0, uint32_t a1, uint32_t a2, uint32_t a3,
                                        uint32_t b0, uint32_t b1) {
    asm volatile(
        "mma.sync.aligned.m16n8k16.row.col.f32.f16.f16.f32 "
        "{%0,%1,%2,%3}, {%4,%5,%6,%7}, {%8,%9}, {%0,%1,%2,%3};"
        : "+f"(c0), "+f"(c1), "+f"(c2), "+f"(c3)
        : "r"(a0), "r"(a1), "r"(a2), "r"(a3), "r"(b0), "r"(b1));
}

// ---------------------------------------------------------------------------
// encoder: CTA owns full N=256. Grid-stride over 4096 tiles (2 elems each).
// 512 threads, warp grid 4M x 4N (32 rows x 64 cols per warp). fp16 GEMM.
// ---------------------------------------------------------------------------
__global__ void __launch_bounds__(512, 1) enc_kernel(
    const float* __restrict__ s, const float* __restrict__ W1,
    const float* __restrict__ b1, const float* __restrict__ W2,
    const float* __restrict__ b2)
{
    extern __shared__ char smem[];
    const int tid = threadIdx.x;
    const int w    = tid >> 5, lane = tid & 31;
    const int wr   = w & 3,   wc   = w >> 2;
    const int tq   = lane >> 2, tm = lane & 3;
    const int r    = tid & 127, sub = tid >> 7;

    float* sW1t   = (float*)(smem + SM_W1T);
    float* sB1    = (float*)(smem + SM_B1);
    float* sB2    = (float*)(smem + SM_B2);
    float* sWlast = (float*)(smem + SM_WLAST);
    float* sSurr  = (float*)(smem + SM_SURR);
    float* sValid = (float*)(smem + SM_VALID);
    float* sDotp  = (float*)(smem + SM_HHI);
    float* sPart  = (float*)(smem + SM_HHI + 2048);

    // ---- prologue: fp16 B slab, full 256 cols, permuted layout ----
    for (int i = tid; i < 32768; i += 512) {
        int word = i >> 8, n = i & 255;
        int sL = word >> 3, rem = word & 7, q = rem >> 1, h2 = rem & 1;
        int k0 = sL * 16 + 2 * (h2 * 4 + q);
        float f0 = W2[(size_t)k0 * 257 + n];
        float f1 = W2[(size_t)(k0 + 1) * 257 + n];
        *(uint32_t*)(smem + SM_BHI + n * 544 + word * 4) = cvt_f16x2(f0, f1);
    }
    for (int i = tid; i < 2048; i += 512) {   // W1 pair-packed
        int kp = i >> 4, rem = i & 15, c = rem >> 1, h = rem & 1;
        sW1t[i] = W1[c * HID + kp * 2 + h];
    }
    if (tid < 256) {
        sB1[tid] = b1[tid];
        sWlast[tid] = W2[(size_t)tid * 257 + 256];
    }
    for (int i = tid; i < 257; i += 512) sB2[i] = b2[i];
    __syncthreads();

    const int rrot    = ((r >> 2) & 7) * 4;
    const int rowbase = r * 544 + rrot;
    int abase[2][2];
    #pragma unroll
    for (int mt = 0; mt < 2; mt++)
        #pragma unroll
        for (int rr = 0; rr < 2; rr++) {
            int row = wr * 32 + mt * 16 + rr * 8 + tq;
            abase[mt][rr] = row * 544 + ((row >> 2) & 7) * 4 + tm * 8;
        }

    for (int tt = blockIdx.x; tt < NTILE; tt += NCTA) {
        const int b0 = tt * 2;

        // ---- surr load (2 elems x 512 floats) ----
        if (tid < 256) {
            int e = tid >> 7, j = tid & 127;
            ((float4*)sSurr)[e * 128 + j] =
                ((const float4*)(s + (size_t)(b0 + e) * SROW + CAR))[j];
        }
        __syncthreads();

        const float4 s0 = ((const float4*)sSurr)[r * 2];
        const float4 s1 = ((const float4*)sSurr)[r * 2 + 1];
        if (tid < 128) {
            float v = 1.0f;
            if (s0.x == -1.f || s0.y == -1.f || s0.z == -1.f || s0.w == -1.f ||
                s1.x == -1.f || s1.y == -1.f || s1.z == -1.f || s1.w == -1.f) v = 0.f;
            sValid[tid] = v;
        }
        const unsigned long long sp0 = packf2(s0.x, s0.x), sp1 = packf2(s0.y, s0.y);
        const unsigned long long sp2 = packf2(s0.z, s0.z), sp3 = packf2(s0.w, s0.w);
        const unsigned long long sp4 = packf2(s1.x, s1.x), sp5 = packf2(s1.y, s1.y);
        const unsigned long long sp6 = packf2(s1.z, s1.z), sp7 = packf2(s1.w, s1.w);

        // ---- H phase: thread (r, sub) computes k in [sub*64, sub*64+64) ----
        unsigned long long dot2 = packf2(0.f, 0.f);
        #pragma unroll 4
        for (int jj = 0; jj < 32; jj++) {
            const int kl = sub * 64 + 2 * jj;
            const int kp = kl >> 1;
            ulonglong2 wA = *(const ulonglong2*)(sW1t + kp * 16);
            ulonglong2 wB = *(const ulonglong2*)(sW1t + kp * 16 + 4);
            ulonglong2 wC = *(const ulonglong2*)(sW1t + kp * 16 + 8);
            ulonglong2 wD = *(const ulonglong2*)(sW1t + kp * 16 + 12);
            unsigned long long acc2 = *(const unsigned long long*)(sB1 + kl);
            fma2(acc2, wA.x, sp0); fma2(acc2, wA.y, sp1);
            fma2(acc2, wB.x, sp2); fma2(acc2, wB.y, sp3);
            fma2(acc2, wC.x, sp4); fma2(acc2, wC.y, sp5);
            fma2(acc2, wD.x, sp6); fma2(acc2, wD.y, sp7);
            float f0, f1;
            unpackf2(f0, f1, acc2);
            f0 = fmaxf(f0, 0.f); f1 = fmaxf(f1, 0.f);
            {
                unsigned long long wl = *(const unsigned long long*)(sWlast + kl);
                fma2(dot2, packf2(f0, f1), wl);
            }
            const int sL = kl >> 4;
            const int j8 = jj & 7;
            const int woff = (sL * 8 + (j8 & 3) * 2 + (j8 >> 2)) * 4;
            *(uint32_t*)(smem + SM_HHI + rowbase + woff) = cvt_f16x2(f0, f1);
        }
        __syncthreads();

        // ---- MMA: 16 ksteps, warp = 32 rows x 64 cols ----
        float acc[8][2][4];
        #pragma unroll
        for (int nt = 0; nt < 8; nt++)
            #pragma unroll
            for (int mt = 0; mt < 2; mt++)
                #pragma unroll
                for (int c = 0; c < 4; c++) acc[nt][mt][c] = 0.f;

        #pragma unroll 2
        for (int sg = 0; sg < 16; sg++) {
            uint32_t Ah[2][2][2];
            #pragma unroll
            for (int mt = 0; mt < 2; mt++)
                #pragma unroll
                for (int rr = 0; rr < 2; rr++) {
                    int off = abase[mt][rr] + sg * 32;
                    Ah[mt][rr][0] = *(const uint32_t*)(smem + SM_HHI + off);
                    Ah[mt][rr][1] = *(const uint32_t*)(smem + SM_HHI + off + 4);
                }
            #pragma unroll
            for (int nt = 0; nt < 8; nt++) {
                int n = wc * 64 + nt * 8 + tq;
                uint2 Bh = *(const uint2*)(smem + SM_BHI + n * 544 + sg * 32 + tm * 8);
                #pragma unroll
                for (int mt = 0; mt < 2; mt++) {
                    float* c = acc[nt][mt];
                    mma_f16(c[0], c[1], c[2], c[3],
                            Ah[mt][0][0], Ah[mt][1][0], Ah[mt][0][1], Ah[mt][1][1],
                            Bh.x, Bh.y);
                }
            }
        }
        __syncthreads();   // all H/B reads done; H area reusable as sDotp/sPart

        // ---- epilogue: bias -> relu -> mask -> row sums ----
        {
            float da, db;
            unpackf2(da, db, dot2);
            sDotp[sub * 128 + r] = da + db;
        }
        {
            const float vA = sValid[wr * 32 + tq];
            const float vB = sValid[wr * 32 + tq + 8];
            const float vC = sValid[wr * 32 + tq + 16];
            const float vD = sValid[wr * 32 + tq + 24];
            #pragma unroll
            for (int nt = 0; nt < 8; nt++) {
                int c0 = wc * 64 + nt * 8 + tm * 2;
                float e0 = sB2[c0], e1 = sB2[c0 + 1];
                float* a0 = acc[nt][0];
                float* a1 = acc[nt][1];
                float p0 = fmaxf(a0[0] + e0, 0.f) * vA + fmaxf(a0[2] + e0, 0.f) * vB
                         + fmaxf(a1[0] + e0, 0.f) * vC + fmaxf(a1[2] + e0, 0.f) * vD;
                float p1 = fmaxf(a0[1] + e1, 0.f) * vA + fmaxf(a0[3] + e1, 0.f) * vB
                         + fmaxf(a1[1] + e1, 0.f) * vC + fmaxf(a1[3] + e1, 0.f) * vD;
                p0 += __shfl_down_sync(0xffffffffu, p0, 16);
                p0 += __shfl_down_sync(0xffffffffu, p0, 8);
                p0 += __shfl_down_sync(0xffffffffu, p0, 4);
                p1 += __shfl_down_sync(0xffffffffu, p1, 16);
                p1 += __shfl_down_sync(0xffffffffu, p1, 8);
                p1 += __shfl_down_sync(0xffffffffu, p1, 4);
                if (tq == 0) {
                    sPart[wr * 256 + c0]     = p0;
                    sPart[wr * 256 + c0 + 1] = p1;
                }
            }
        }
        __syncthreads();

        {   // combine row-groups -> g_x (512 threads: 2 elems x 256 cols)
            int e = tid >> 8, col = tid & 255;
            float val = sPart[(2 * e) * 256 + col] + sPart[(2 * e + 1) * 256 + col];
            g_x[(size_t)(b0 + e) * QIN + 8 + col] = val;
        }
        {
            if (tid < 128) {
                float dsum = sDotp[tid] + sDotp[128 + tid]
                           + sDotp[256 + tid] + sDotp[384 + tid];
                sDotp[tid] = fmaxf(dsum + sB2[256], 0.f) * sValid[tid];
            }
            __syncthreads();
            if (w < 2) {
                float tt2 = sDotp[w * 64 + lane] + sDotp[w * 64 + 32 + lane];
                #pragma unroll
                for (int off = 16; off > 0; off >>= 1)
                    tt2 += __shfl_down_sync(0xffffffffu, tt2, off);
                if (lane == 0) g_x[(size_t)(b0 + w) * QIN + 264] = tt2;
            }
            if (tid < 16)
                g_x[(size_t)(b0 + (tid >> 3)) * QIN + (tid & 7)] =
                    s[(size_t)(b0 + (tid >> 3)) * SROW + (tid & 7)];
        }
        __syncthreads();   // epilogue scratch (H alias) free before next H phase
    }
}

// ---------------------------------------------------------------------------
// Q head (R10 version, measured 72us): 8 rows per CTA, float4-vectorized.
// ---------------------------------------------------------------------------
#define XPAD  268
#define HPAD  260

__global__ void __launch_bounds__(256) qhead_kernel(
    const float* __restrict__ Qw1, const float* __restrict__ Qb1,
    const float* __restrict__ Qw2, const float* __restrict__ Qb2,
    float* __restrict__ out)
{
    __shared__ float shX[8 * XPAD];
    __shared__ float shHq[8 * HPAD];
    __shared__ float shW2T[ADIM * HPAD];

    const int b0  = blockIdx.x * 8;
    const int tid = threadIdx.x;

    for (int i = tid; i < 8 * XPAD; i += 256) {
        int r = i / XPAD, k = i - r * XPAD;
        shX[i] = (k < QIN) ? g_x[(size_t)(b0 + r) * QIN + k] : 0.f;
    }
    for (int i = tid; i < ADIM * HID; i += 256) {
        int c = i >> 8, k = i & 255;
        shW2T[c * HPAD + k] = Qw2[k * ADIM + c];
    }
    __syncthreads();

    {
        float acc[8];
        const float qb = Qb1[tid];
        #pragma unroll
        for (int r = 0; r < 8; r++) acc[r] = qb;

        #pragma unroll 3
        for (int kk = 0; kk < 66; kk++) {
            const float* wp = Qw1 + (size_t)(kk * 4) * HID + tid;
            float w0 = wp[0], w1 = wp[HID], w2 = wp[2 * HID], w3 = wp[3 * HID];
            #pragma unroll
            for (int r = 0; r < 8; r++) {
                float4 xv = *(const float4*)(shX + r * XPAD + kk * 4);
                acc[r] = fmaf(xv.x, w0, acc[r]);
                acc[r] = fmaf(xv.y, w1, acc[r]);
                acc[r] = fmaf(xv.z, w2, acc[r]);
                acc[r] = fmaf(xv.w, w3, acc[r]);
            }
        }
        {
            float w0 = Qw1[(size_t)264 * HID + tid];
            #pragma unroll
            for (int r = 0; r < 8; r++)
                acc[r] = fmaf(shX[r * XPAD + 264], w0, acc[r]);
        }
        #pragma unroll
        for (int r = 0; r < 8; r++)
            shHq[r * HPAD + tid] = fmaxf(acc[r], 0.f);
    }
    __syncthreads();

    if (tid < 8 * ADIM) {
        int r = tid / ADIM, c = tid - r * ADIM;
        const float* hp = shHq + r * HPAD;
        const float* wp = shW2T + c * HPAD;
        float a = Qb2[c];
        #pragma unroll 4
        for (int kk = 0; kk < 64; kk++) {
            float4 hv = *(const float4*)(hp + kk * 4);
            float4 wv = *(const float4*)(wp + kk * 4);
            a = fmaf(hv.x, wv.x, a);
            a = fmaf(hv.y, wv.y, a);
            a = fmaf(hv.z, wv.z, a);
            a = fmaf(hv.w, wv.w, a);
        }
        out[(size_t)(b0 + r) * ADIM + c] = a;
    }
}

// ---------------------------------------------------------------------------
extern "C" void kernel_launch(void* const* d_in, const int* in_sizes, int n_in,
                              void* d_out, int out_size)
{
    const float* s   = (const float*)d_in[0];
    const float* W1  = (const float*)d_in[1];
    const float* b1  = (const float*)d_in[2];
    const float* W2  = (const float*)d_in[3];
    const float* b2  = (const float*)d_in[4];
    const float* Qw1 = (const float*)d_in[5];
    const float* Qb1 = (const float*)d_in[6];
    const float* Qw2 = (const float*)d_in[7];
    const float* Qb2 = (const float*)d_in[8];
    float* out = (float*)d_out;

    cudaFuncSetAttribute(enc_kernel,
                         cudaFuncAttributeMaxDynamicSharedMemorySize, SM_TOTAL);

    enc_kernel<<<NCTA, 512, SM_TOTAL>>>(s, W1, b1, W2, b2);
    qhead_kernel<<<BATCH / 8, 256>>>(Qw1, Qb1, Qw2, Qb2, out);
}

// round 13
// speedup vs baseline: 8.5367x; 1.1376x over previous
#include <cuda_runtime.h>
#include <cuda_fp16.h>
#include <cstdint>

#define BATCH 8192
#define CAR   8
#define HID   256
#define QIN   265
#define ADIM  30
#define SROW  520
#define NCTA  456
#define NTILE 4096

// ---- enc smem offsets (bytes) ----
#define SM_BHI   0         // 256n x 544B fp16 B slab = 139264
#define SM_HHI   139264    // 128r x 544B fp16 H, rotated rows = 69632
#define SM_W1T   208896    // 8192
#define SM_B1    217088    // 1024
#define SM_B2    218112    // 257 floats -> pad 1040
#define SM_WLAST 219152    // 1024
#define SM_SURR  220176    // 4096
#define SM_VALID 224272    // 512
#define SM_X264  224784    // 16
#define SM_TOTAL 224800
// aliases after MMA: sDotp = SM_HHI (2048B), sPart = SM_HHI+2048 (4096B)

// ---- qhead smem offsets (bytes) ----
#define QSM_B1   0         // 256n x 544B fp16 Qw1 slab (17 ksteps) = 139264
#define QSM_A    139264    // 128r x 544B fp16 x main slab (k 0..255) = 69632
#define QSM_AUX  208896    // 128r x 40B fp16 x aux (k 256..271)     = 5120
#define QSM_B2   214016    // 31n x 544B fp16 Qw2 slab               = 16864
#define QSM_QB1  230880    // 1024
#define QSM_QB2  231904    // 128
#define QSM_TOT  232032

// x main: 64 blocks x 128 rows x 544B (k 0..255, rotated rows)
__device__ __align__(16) uint32_t g_xA[64 * 128 * 136];
// x aux: 64 blocks x 128 rows x 10 words (k 256..271 in words 0..7; zero-init pads)
__device__ __align__(16) uint32_t g_xAux[64 * 128 * 10];

// ---------------------------------------------------------------------------
__device__ __forceinline__ uint32_t cvt_f16x2(float lo, float hi) {
    uint32_t u;
    asm("cvt.rn.f16x2.f32 %0, %1, %2;" : "=r"(u) : "f"(hi), "f"(lo));
    return u;
}
__device__ __forceinline__ unsigned long long packf2(float a, float b) {
    unsigned long long u;
    asm("mov.b64 %0, {%1,%2};" : "=l"(u) : "f"(a), "f"(b));
    return u;
}
__device__ __forceinline__ void unpackf2(float& a, float& b, unsigned long long u) {
    asm("mov.b64 {%0,%1}, %2;" : "=f"(a), "=f"(b) : "l"(u));
}
__device__ __forceinline__ void fma2(unsigned long long& d, unsigned long long a,
                                     unsigned long long b) {
    asm("fma.rn.f32x2 %0, %1, %2, %0;" : "+l"(d) : "l"(a), "l"(b));
}
__device__ __forceinline__ void mma_f16(float& c0, float& c1, float& c2, float& c3,
                                        uint32_t a0, uint32_t a1, uint32_t a2, uint32_t a3,
                                        uint32_t b0, uint32_t b1) {
    asm volatile(
        "mma.sync.aligned.m16n8k16.row.col.f32.f16.f16.f32 "
        "{%0,%1,%2,%3}, {%4,%5,%6,%7}, {%8,%9}, {%0,%1,%2,%3};"
        : "+f"(c0), "+f"(c1), "+f"(c2), "+f"(c3)
        : "r"(a0), "r"(a1), "r"(a2), "r"(a3), "r"(b0), "r"(b1));
}
// word offset (bytes) within a row for even k index kl
__device__ __forceinline__ int kwoff(int kl) {
    int sL = kl >> 4, j8 = (kl & 15) >> 1;
    return (sL * 8 + (j8 & 3) * 2 + (j8 >> 2)) * 4;
}

// ---------------------------------------------------------------------------
// encoder: CTA owns full N=256, grid-stride over 4096 tiles (2 elems each).
// Epilogue emits x as fp16 mma-A fragments: main slab (k<256) + aux (k>=256).
// ---------------------------------------------------------------------------
__global__ void __launch_bounds__(512, 1) enc_kernel(
    const float* __restrict__ s, const float* __restrict__ W1,
    const float* __restrict__ b1, const float* __restrict__ W2,
    const float* __restrict__ b2)
{
    extern __shared__ char smem[];
    const int tid = threadIdx.x;
    const int w    = tid >> 5, lane = tid & 31;
    const int wr   = w & 3,   wc   = w >> 2;
    const int tq   = lane >> 2, tm = lane & 3;
    const int r    = tid & 127, sub = tid >> 7;

    float* sW1t   = (float*)(smem + SM_W1T);
    float* sB1    = (float*)(smem + SM_B1);
    float* sB2    = (float*)(smem + SM_B2);
    float* sWlast = (float*)(smem + SM_WLAST);
    float* sSurr  = (float*)(smem + SM_SURR);
    float* sValid = (float*)(smem + SM_VALID);
    float* sX264  = (float*)(smem + SM_X264);
    float* sDotp  = (float*)(smem + SM_HHI);
    float* sPart  = (float*)(smem + SM_HHI + 2048);

    for (int i = tid; i < 32768; i += 512) {
        int word = i >> 8, n = i & 255;
        int sL = word >> 3, rem = word & 7, q = rem >> 1, h2 = rem & 1;
        int k0 = sL * 16 + 2 * (h2 * 4 + q);
        float f0 = W2[(size_t)k0 * 257 + n];
        float f1 = W2[(size_t)(k0 + 1) * 257 + n];
        *(uint32_t*)(smem + SM_BHI + n * 544 + word * 4) = cvt_f16x2(f0, f1);
    }
    for (int i = tid; i < 2048; i += 512) {
        int kp = i >> 4, rem = i & 15, c = rem >> 1, h = rem & 1;
        sW1t[i] = W1[c * HID + kp * 2 + h];
    }
    if (tid < 256) {
        sB1[tid] = b1[tid];
        sWlast[tid] = W2[(size_t)tid * 257 + 256];
    }
    for (int i = tid; i < 257; i += 512) sB2[i] = b2[i];
    __syncthreads();

    const int rrot    = ((r >> 2) & 7) * 4;
    const int rowbase = r * 544 + rrot;
    int abase[2][2];
    #pragma unroll
    for (int mt = 0; mt < 2; mt++)
        #pragma unroll
        for (int rr = 0; rr < 2; rr++) {
            int row = wr * 32 + mt * 16 + rr * 8 + tq;
            abase[mt][rr] = row * 544 + ((row >> 2) & 7) * 4 + tm * 8;
        }

    for (int tt = blockIdx.x; tt < NTILE; tt += NCTA) {
        const int b0 = tt * 2;

        if (tid < 256) {
            int e = tid >> 7, j = tid & 127;
            ((float4*)sSurr)[e * 128 + j] =
                ((const float4*)(s + (size_t)(b0 + e) * SROW + CAR))[j];
        }
        __syncthreads();

        const float4 s0 = ((const float4*)sSurr)[r * 2];
        const float4 s1 = ((const float4*)sSurr)[r * 2 + 1];
        if (tid < 128) {
            float v = 1.0f;
            if (s0.x == -1.f || s0.y == -1.f || s0.z == -1.f || s0.w == -1.f ||
                s1.x == -1.f || s1.y == -1.f || s1.z == -1.f || s1.w == -1.f) v = 0.f;
            sValid[tid] = v;
        }
        const unsigned long long sp0 = packf2(s0.x, s0.x), sp1 = packf2(s0.y, s0.y);
        const unsigned long long sp2 = packf2(s0.z, s0.z), sp3 = packf2(s0.w, s0.w);
        const unsigned long long sp4 = packf2(s1.x, s1.x), sp5 = packf2(s1.y, s1.y);
        const unsigned long long sp6 = packf2(s1.z, s1.z), sp7 = packf2(s1.w, s1.w);

        unsigned long long dot2 = packf2(0.f, 0.f);
        #pragma unroll 4
        for (int jj = 0; jj < 32; jj++) {
            const int kl = sub * 64 + 2 * jj;
            const int kp = kl >> 1;
            ulonglong2 wA = *(const ulonglong2*)(sW1t + kp * 16);
            ulonglong2 wB = *(const ulonglong2*)(sW1t + kp * 16 + 4);
            ulonglong2 wC = *(const ulonglong2*)(sW1t + kp * 16 + 8);
            ulonglong2 wD = *(const ulonglong2*)(sW1t + kp * 16 + 12);
            unsigned long long acc2 = *(const unsigned long long*)(sB1 + kl);
            fma2(acc2, wA.x, sp0); fma2(acc2, wA.y, sp1);
            fma2(acc2, wB.x, sp2); fma2(acc2, wB.y, sp3);
            fma2(acc2, wC.x, sp4); fma2(acc2, wC.y, sp5);
            fma2(acc2, wD.x, sp6); fma2(acc2, wD.y, sp7);
            float f0, f1;
            unpackf2(f0, f1, acc2);
            f0 = fmaxf(f0, 0.f); f1 = fmaxf(f1, 0.f);
            {
                unsigned long long wl = *(const unsigned long long*)(sWlast + kl);
                fma2(dot2, packf2(f0, f1), wl);
            }
            *(uint32_t*)(smem + SM_HHI + rowbase + kwoff(kl)) = cvt_f16x2(f0, f1);
        }
        __syncthreads();

        float acc[8][2][4];
        #pragma unroll
        for (int nt = 0; nt < 8; nt++)
            #pragma unroll
            for (int mt = 0; mt < 2; mt++)
                #pragma unroll
                for (int c = 0; c < 4; c++) acc[nt][mt][c] = 0.f;

        #pragma unroll 2
        for (int sg = 0; sg < 16; sg++) {
            uint32_t Ah[2][2][2];
            #pragma unroll
            for (int mt = 0; mt < 2; mt++)
                #pragma unroll
                for (int rr = 0; rr < 2; rr++) {
                    int off = abase[mt][rr] + sg * 32;
                    Ah[mt][rr][0] = *(const uint32_t*)(smem + SM_HHI + off);
                    Ah[mt][rr][1] = *(const uint32_t*)(smem + SM_HHI + off + 4);
                }
            #pragma unroll
            for (int nt = 0; nt < 8; nt++) {
                int n = wc * 64 + nt * 8 + tq;
                uint2 Bh = *(const uint2*)(smem + SM_BHI + n * 544 + sg * 32 + tm * 8);
                #pragma unroll
                for (int mt = 0; mt < 2; mt++) {
                    float* c = acc[nt][mt];
                    mma_f16(c[0], c[1], c[2], c[3],
                            Ah[mt][0][0], Ah[mt][1][0], Ah[mt][0][1], Ah[mt][1][1],
                            Bh.x, Bh.y);
                }
            }
        }
        __syncthreads();

        // ---- epilogue ----
        {
            float da, db;
            unpackf2(da, db, dot2);
            sDotp[sub * 128 + r] = da + db;
        }
        {
            const float vA = sValid[wr * 32 + tq];
            const float vB = sValid[wr * 32 + tq + 8];
            const float vC = sValid[wr * 32 + tq + 16];
            const float vD = sValid[wr * 32 + tq + 24];
            #pragma unroll
            for (int nt = 0; nt < 8; nt++) {
                int c0 = wc * 64 + nt * 8 + tm * 2;
                float e0 = sB2[c0], e1 = sB2[c0 + 1];
                float* a0 = acc[nt][0];
                float* a1 = acc[nt][1];
                float p0 = fmaxf(a0[0] + e0, 0.f) * vA + fmaxf(a0[2] + e0, 0.f) * vB
                         + fmaxf(a1[0] + e0, 0.f) * vC + fmaxf(a1[2] + e0, 0.f) * vD;
                float p1 = fmaxf(a0[1] + e1, 0.f) * vA + fmaxf(a0[3] + e1, 0.f) * vB
                         + fmaxf(a1[1] + e1, 0.f) * vC + fmaxf(a1[3] + e1, 0.f) * vD;
                p0 += __shfl_down_sync(0xffffffffu, p0, 16);
                p0 += __shfl_down_sync(0xffffffffu, p0, 8);
                p0 += __shfl_down_sync(0xffffffffu, p0, 4);
                p1 += __shfl_down_sync(0xffffffffu, p1, 16);
                p1 += __shfl_down_sync(0xffffffffu, p1, 8);
                p1 += __shfl_down_sync(0xffffffffu, p1, 4);
                if (tq == 0) {
                    sPart[wr * 256 + c0]     = p0;
                    sPart[wr * 256 + c0 + 1] = p1;
                }
            }
        }
        __syncthreads();

        // enc-col x words -> g_xA main (k<256) or g_xAux (k>=256)
        if (tid < 256) {
            int e = tid >> 7, j = tid & 127;
            int c = 2 * j;
            int k = 8 + c;
            float v0 = sPart[(2 * e) * 256 + c]     + sPart[(2 * e + 1) * 256 + c];
            float v1 = sPart[(2 * e) * 256 + c + 1] + sPart[(2 * e + 1) * 256 + c + 1];
            int b = b0 + e;
            int R = b & 127;
            uint32_t word = cvt_f16x2(v0, v1);
            if (k < 256) {
                char* dst = (char*)g_xA + (size_t)(b >> 7) * 69632
                          + R * 544 + ((R >> 2) & 7) * 4 + kwoff(k);
                *(uint32_t*)dst = word;
            } else {
                char* dst = (char*)g_xAux + (size_t)(b >> 7) * 5120
                          + R * 40 + (kwoff(k) - 512);
                *(uint32_t*)dst = word;
            }
        }
        // col-256 reduce
        if (tid < 128) {
            float dsum = sDotp[tid] + sDotp[128 + tid]
                       + sDotp[256 + tid] + sDotp[384 + tid];
            sDotp[tid] = fmaxf(dsum + sB2[256], 0.f) * sValid[tid];
        }
        __syncthreads();
        if (w < 2) {
            float tt2 = sDotp[w * 64 + lane] + sDotp[w * 64 + 32 + lane];
            #pragma unroll
            for (int off = 16; off > 0; off >>= 1)
                tt2 += __shfl_down_sync(0xffffffffu, tt2, off);
            if (lane == 0) sX264[w] = tt2;
        }
        __syncthreads();
        // special x words: self pairs (k 0,2,4,6) -> main; (x264,0) -> aux word 1.
        // aux pad words (k 266..270) stay zero-initialized, never written.
        if (tid >= 256 && tid < 266) {
            int e = (tid - 256) >= 5 ? 1 : 0;
            int idx = (tid - 256) - e * 5;
            int b = b0 + e;
            int R = b & 127;
            if (idx < 4) {
                int kl = 2 * idx;
                float v0 = s[(size_t)b * SROW + kl];
                float v1 = s[(size_t)b * SROW + kl + 1];
                char* dst = (char*)g_xA + (size_t)(b >> 7) * 69632
                          + R * 544 + ((R >> 2) & 7) * 4 + kwoff(kl);
                *(uint32_t*)dst = cvt_f16x2(v0, v1);
            } else {
                char* dst = (char*)g_xAux + (size_t)(b >> 7) * 5120
                          + R * 40 + 4;   // word 1 = k pair (264, 265)
                *(uint32_t*)dst = cvt_f16x2(sX264[e], 0.f);
            }
        }
        __syncthreads();
    }
}

// ---------------------------------------------------------------------------
// Q head v4 (mma): 64 CTAs x 128 rows, 512 threads.
// layer1: 16 ksteps from main slab + 1 peeled kstep from aux slab.
// layer2: Hq fp16 in-place over main slab, Qw2 slab (31 rows).
// ---------------------------------------------------------------------------
__global__ void __launch_bounds__(512, 1) qhead_kernel(
    const float* __restrict__ Qw1, const float* __restrict__ Qb1,
    const float* __restrict__ Qw2, const float* __restrict__ Qb2,
    float* __restrict__ out)
{
    extern __shared__ char smem[];
    const int tid = threadIdx.x;
    const int w    = tid >> 5, lane = tid & 31;
    const int wr   = w & 3,   wc   = w >> 2;
    const int tq   = lane >> 2, tm = lane & 3;

    // B1 slab: Qw1 -> fp16 [n][word-permuted], 17 ksteps, k>=265 zero
    {
        const int n0 = tid >> 1, half = tid & 1;
        char* dst = smem + QSM_B1 + n0 * 544 + half * 68 * 4;
        #pragma unroll 4
        for (int ww = 0; ww < 68; ww++) {
            int wd = half * 68 + ww;
            int sL = wd >> 3, rem = wd & 7, q = rem >> 1, h2 = rem & 1;
            int k0 = sL * 16 + 2 * (h2 * 4 + q);
            float f0 = (k0 < QIN)     ? Qw1[(size_t)k0 * HID + n0]       : 0.f;
            float f1 = (k0 + 1 < QIN) ? Qw1[(size_t)(k0 + 1) * HID + n0] : 0.f;
            *(uint32_t*)(dst + ww * 4) = cvt_f16x2(f0, f1);
        }
    }
    // A main slab copy (69632 B) + aux copy (5120 B)
    {
        const uint4* src = (const uint4*)((const char*)g_xA + (size_t)blockIdx.x * 69632);
        uint4* dst = (uint4*)(smem + QSM_A);
        #pragma unroll
        for (int i = tid; i < 4352; i += 512) dst[i] = src[i];
        const uint4* srcX = (const uint4*)((const char*)g_xAux + (size_t)blockIdx.x * 5120);
        uint4* dstX = (uint4*)(smem + QSM_AUX);
        if (tid < 320) dstX[tid] = srcX[tid];
    }
    // B2 slab: Qw2 -> fp16 [31 rows][128 words], n>=30 zero
    for (int i = tid; i < 31 * 128; i += 512) {
        int n = i >> 7, wd = i & 127;
        int sL = wd >> 3, rem = wd & 7, q = rem >> 1, h2 = rem & 1;
        int k0 = sL * 16 + 2 * (h2 * 4 + q);
        float f0 = 0.f, f1 = 0.f;
        if (n < ADIM) {
            f0 = Qw2[(size_t)k0 * ADIM + n];
            f1 = Qw2[(size_t)(k0 + 1) * ADIM + n];
        }
        *(uint32_t*)(smem + QSM_B2 + n * 544 + wd * 4) = cvt_f16x2(f0, f1);
    }
    if (tid < 256) ((float*)(smem + QSM_QB1))[tid] = Qb1[tid];
    if (tid < 32)  ((float*)(smem + QSM_QB2))[tid] = (tid < ADIM) ? Qb2[tid] : 0.f;
    __syncthreads();

    int abase[2][2];
    #pragma unroll
    for (int mt = 0; mt < 2; mt++)
        #pragma unroll
        for (int rr = 0; rr < 2; rr++) {
            int row = wr * 32 + mt * 16 + rr * 8 + tq;
            abase[mt][rr] = row * 544 + ((row >> 2) & 7) * 4 + tm * 8;
        }

    // ---- layer 1 MMA: 16 main ksteps + 1 aux kstep ----
    float acc[8][2][4];
    #pragma unroll
    for (int nt = 0; nt < 8; nt++)
        #pragma unroll
        for (int mt = 0; mt < 2; mt++)
            #pragma unroll
            for (int c = 0; c < 4; c++) acc[nt][mt][c] = 0.f;

    #pragma unroll 2
    for (int sg = 0; sg < 16; sg++) {
        uint32_t Ah[2][2][2];
        #pragma unroll
        for (int mt = 0; mt < 2; mt++)
            #pragma unroll
            for (int rr = 0; rr < 2; rr++) {
                int off = abase[mt][rr] + sg * 32;
                Ah[mt][rr][0] = *(const uint32_t*)(smem + QSM_A + off);
                Ah[mt][rr][1] = *(const uint32_t*)(smem + QSM_A + off + 4);
            }
        #pragma unroll
        for (int nt = 0; nt < 8; nt++) {
            int n = wc * 64 + nt * 8 + tq;
            uint2 Bh = *(const uint2*)(smem + QSM_B1 + n * 544 + sg * 32 + tm * 8);
            #pragma unroll
            for (int mt = 0; mt < 2; mt++) {
                float* c = acc[nt][mt];
                mma_f16(c[0], c[1], c[2], c[3],
                        Ah[mt][0][0], Ah[mt][1][0], Ah[mt][0][1], Ah[mt][1][1],
                        Bh.x, Bh.y);
            }
        }
    }
    {   // aux kstep (sg = 16): A from aux slab (40B rows, no rotation)
        uint32_t Ah[2][2][2];
        #pragma unroll
        for (int mt = 0; mt < 2; mt++)
            #pragma unroll
            for (int rr = 0; rr < 2; rr++) {
                int row = wr * 32 + mt * 16 + rr * 8 + tq;
                int off = row * 40 + tm * 8;
                Ah[mt][rr][0] = *(const uint32_t*)(smem + QSM_AUX + off);
                Ah[mt][rr][1] = *(const uint32_t*)(smem + QSM_AUX + off + 4);
            }
        #pragma unroll
        for (int nt = 0; nt < 8; nt++) {
            int n = wc * 64 + nt * 8 + tq;
            uint2 Bh = *(const uint2*)(smem + QSM_B1 + n * 544 + 16 * 32 + tm * 8);
            #pragma unroll
            for (int mt = 0; mt < 2; mt++) {
                float* c = acc[nt][mt];
                mma_f16(c[0], c[1], c[2], c[3],
                        Ah[mt][0][0], Ah[mt][1][0], Ah[mt][0][1], Ah[mt][1][1],
                        Bh.x, Bh.y);
            }
        }
    }
    __syncthreads();   // all A reads done; main slab reusable as A2

    // ---- bias + relu -> fp16 A2 fragments (in place, K=256) ----
    {
        const float* qb1 = (const float*)(smem + QSM_QB1);
        #pragma unroll
        for (int nt = 0; nt < 8; nt++)
            #pragma unroll
            for (int mt = 0; mt < 2; mt++) {
                int c0 = wc * 64 + nt * 8 + tm * 2;
                float e0 = qb1[c0], e1 = qb1[c0 + 1];
                int R0 = wr * 32 + mt * 16 + tq;
                int R1 = R0 + 8;
                int wo = kwoff(c0);
                float* a = acc[nt][mt];
                *(uint32_t*)(smem + QSM_A + R0 * 544 + ((R0 >> 2) & 7) * 4 + wo) =
                    cvt_f16x2(fmaxf(a[0] + e0, 0.f), fmaxf(a[1] + e1, 0.f));
                *(uint32_t*)(smem + QSM_A + R1 * 544 + ((R1 >> 2) & 7) * 4 + wo) =
                    cvt_f16x2(fmaxf(a[2] + e0, 0.f), fmaxf(a[3] + e1, 0.f));
            }
    }
    __syncthreads();

    // ---- layer 2 MMA: 16 ksteps, warp = 32 rows x 8 cols ----
    float a2[2][4];
    #pragma unroll
    for (int mt = 0; mt < 2; mt++)
        #pragma unroll
        for (int c = 0; c < 4; c++) a2[mt][c] = 0.f;

    #pragma unroll 4
    for (int sg = 0; sg < 16; sg++) {
        uint32_t Ah[2][2][2];
        #pragma unroll
        for (int mt = 0; mt < 2; mt++)
            #pragma unroll
            for (int rr = 0; rr < 2; rr++) {
                int off = abase[mt][rr] + sg * 32;
                Ah[mt][rr][0] = *(const uint32_t*)(smem + QSM_A + off);
                Ah[mt][rr][1] = *(const uint32_t*)(smem + QSM_A + off + 4);
            }
        int n2 = wc * 8 + tq;
        uint2 Bh = *(const uint2*)(smem + QSM_B2 + n2 * 544 + sg * 32 + tm * 8);
        #pragma unroll
        for (int mt = 0; mt < 2; mt++) {
            float* c = a2[mt];
            mma_f16(c[0], c[1], c[2], c[3],
                    Ah[mt][0][0], Ah[mt][1][0], Ah[mt][0][1], Ah[mt][1][1],
                    Bh.x, Bh.y);
        }
    }

    // ---- epilogue: +Qb2, write out ----
    {
        const float* qb2 = (const float*)(smem + QSM_QB2);
        const int cg = wc * 8 + tm * 2;
        const size_t gb = (size_t)blockIdx.x * 128;
        #pragma unroll
        for (int mt = 0; mt < 2; mt++) {
            int row = wr * 32 + mt * 16 + tq;
            if (cg < ADIM) {
                out[(gb + row) * ADIM + cg]     = a2[mt][0] + qb2[cg];
                out[(gb + row + 8) * ADIM + cg] = a2[mt][2] + qb2[cg];
            }
            if (cg + 1 < ADIM) {
                out[(gb + row) * ADIM + cg + 1]     = a2[mt][1] + qb2[cg + 1];
                out[(gb + row + 8) * ADIM + cg + 1] = a2[mt][3] + qb2[cg + 1];
            }
        }
    }
}

// ---------------------------------------------------------------------------
extern "C" void kernel_launch(void* const* d_in, const int* in_sizes, int n_in,
                              void* d_out, int out_size)
{
    const float* s   = (const float*)d_in[0];
    const float* W1  = (const float*)d_in[1];
    const float* b1  = (const float*)d_in[2];
    const float* W2  = (const float*)d_in[3];
    const float* b2  = (const float*)d_in[4];
    const float* Qw1 = (const float*)d_in[5];
    const float* Qb1 = (const float*)d_in[6];
    const float* Qw2 = (const float*)d_in[7];
    const float* Qb2 = (const float*)d_in[8];
    float* out = (float*)d_out;

    cudaFuncSetAttribute(enc_kernel,
                         cudaFuncAttributeMaxDynamicSharedMemorySize, SM_TOTAL);
    cudaFuncSetAttribute(qhead_kernel,
                         cudaFuncAttributeMaxDynamicSharedMemorySize, QSM_TOT);

    enc_kernel<<<NCTA, 512, SM_TOTAL>>>(s, W1, b1, W2, b2);
    qhead_kernel<<<BATCH / 128, 512, QSM_TOT>>>(Qw1, Qb1, Qw2, Qb2, out);
}

// round 14
// speedup vs baseline: 9.0123x; 1.0557x over previous
#include <cuda_runtime.h>
#include <cuda_fp16.h>
#include <cstdint>

#define BATCH 8192
#define CAR   8
#define HID   256
#define QIN   265
#define ADIM  30
#define SROW  520
#define NCTA  152
#define NTILE 4096

// ---- enc smem offsets (bytes) ----
#define SM_BHI   0         // 256n x 544B fp16 B slab = 139264
#define SM_HHI   139264    // 128r x 544B fp16 H, rotated rows = 69632
#define SM_W1T   208896    // 8192
#define SM_B1    217088    // 1024
#define SM_B2    218112    // 257 floats -> pad 1040
#define SM_WLAST 219152    // 1024
#define SM_SURR  220176    // 2 bufs x 4096 = 8192 (16B-aligned)
#define SM_VALID 228368    // 512
#define SM_X264  228880    // 16
#define SM_TOTAL 228896
// aliases after MMA: sDotp = SM_HHI (2048B), sPart = SM_HHI+2048 (4096B)

// ---- qhead smem offsets (bytes) ----
#define QSM_B1   0         // 256n x 544B fp16 Qw1 slab (17 ksteps) = 139264
#define QSM_A    139264    // 128r x 544B fp16 x main slab (k 0..255) = 69632
#define QSM_AUX  208896    // 128r x 40B fp16 x aux (k 256..271)     = 5120
#define QSM_B2   214016    // 31n x 544B fp16 Qw2 slab               = 16864
#define QSM_QB1  230880    // 1024
#define QSM_QB2  231904    // 128
#define QSM_TOT  232032

// x main: 64 blocks x 128 rows x 544B (k 0..255, rotated rows)
__device__ __align__(16) uint32_t g_xA[64 * 128 * 136];
// x aux: 64 blocks x 128 rows x 10 words (k 256..271 in words 0..7; zero-init pads)
__device__ __align__(16) uint32_t g_xAux[64 * 128 * 10];

// ---------------------------------------------------------------------------
__device__ __forceinline__ uint32_t cvt_f16x2(float lo, float hi) {
    uint32_t u;
    asm("cvt.rn.f16x2.f32 %0, %1, %2;" : "=r"(u) : "f"(hi), "f"(lo));
    return u;
}
__device__ __forceinline__ unsigned long long packf2(float a, float b) {
    unsigned long long u;
    asm("mov.b64 %0, {%1,%2};" : "=l"(u) : "f"(a), "f"(b));
    return u;
}
__device__ __forceinline__ void unpackf2(float& a, float& b, unsigned long long u) {
    asm("mov.b64 {%0,%1}, %2;" : "=f"(a), "=f"(b) : "l"(u));
}
__device__ __forceinline__ void fma2(unsigned long long& d, unsigned long long a,
                                     unsigned long long b) {
    asm("fma.rn.f32x2 %0, %1, %2, %0;" : "+l"(d) : "l"(a), "l"(b));
}
__device__ __forceinline__ void add2(unsigned long long& d, unsigned long long a) {
    asm("add.rn.f32x2 %0, %0, %1;" : "+l"(d) : "l"(a));
}
__device__ __forceinline__ void mma_f16(float& c0, float& c1, float& c2, float& c3,
                                        uint32_t a0, uint32_t a1, uint32_t a2, uint32_t a3,
                                        uint32_t b0, uint32_t b1) {
    asm volatile(
        "mma.sync.aligned.m16n8k16.row.col.f32.f16.f16.f32 "
        "{%0,%1,%2,%3}, {%4,%5,%6,%7}, {%8,%9}, {%0,%1,%2,%3};"
        : "+f"(c0), "+f"(c1), "+f"(c2), "+f"(c3)
        : "r"(a0), "r"(a1), "r"(a2), "r"(a3), "r"(b0), "r"(b1));
}
__device__ __forceinline__ int kwoff(int kl) {
    int sL = kl >> 4, j8 = (kl & 15) >> 1;
    return (sL * 8 + (j8 & 3) * 2 + (j8 >> 2)) * 4;
}
__device__ __forceinline__ void cp_async16(uint32_t smem_addr, const void* gptr) {
    asm volatile("cp.async.ca.shared.global [%0], [%1], 16;"
                 :: "r"(smem_addr), "l"(gptr) : "memory");
}
__device__ __forceinline__ uint32_t smem_u32(const void* p) {
    uint32_t a;
    asm("{ .reg .u64 t; cvta.to.shared.u64 t, %1; cvt.u32.u64 %0, t; }"
        : "=r"(a) : "l"(p));
    return a;
}

// ---------------------------------------------------------------------------
// encoder: CTA owns full N=256, grid-stride over 4096 tiles (2 elems each).
// cp.async surr double-buffer; fp16 mma-A x output (main + aux slabs).
// ---------------------------------------------------------------------------
__global__ void __launch_bounds__(512, 1) enc_kernel(
    const float* __restrict__ s, const float* __restrict__ W1,
    const float* __restrict__ b1, const float* __restrict__ W2,
    const float* __restrict__ b2)
{
    extern __shared__ char smem[];
    const int tid = threadIdx.x;
    const int w    = tid >> 5, lane = tid & 31;
    const int wr   = w & 3,   wc   = w >> 2;
    const int tq   = lane >> 2, tm = lane & 3;
    const int r    = tid & 127, sub = tid >> 7;

    float* sW1t   = (float*)(smem + SM_W1T);
    float* sB1    = (float*)(smem + SM_B1);
    float* sB2    = (float*)(smem + SM_B2);
    float* sWlast = (float*)(smem + SM_WLAST);
    float* sValid = (float*)(smem + SM_VALID);
    float* sX264  = (float*)(smem + SM_X264);
    float* sDotp  = (float*)(smem + SM_HHI);
    float* sPart  = (float*)(smem + SM_HHI + 2048);
    const uint32_t surrBase = smem_u32(smem + SM_SURR);

    for (int i = tid; i < 32768; i += 512) {
        int word = i >> 8, n = i & 255;
        int sL = word >> 3, rem = word & 7, q = rem >> 1, h2 = rem & 1;
        int k0 = sL * 16 + 2 * (h2 * 4 + q);
        float f0 = W2[(size_t)k0 * 257 + n];
        float f1 = W2[(size_t)(k0 + 1) * 257 + n];
        *(uint32_t*)(smem + SM_BHI + n * 544 + word * 4) = cvt_f16x2(f0, f1);
    }
    for (int i = tid; i < 2048; i += 512) {
        int kp = i >> 4, rem = i & 15, c = rem >> 1, h = rem & 1;
        sW1t[i] = W1[c * HID + kp * 2 + h];
    }
    if (tid < 256) {
        sB1[tid] = b1[tid];
        sWlast[tid] = W2[(size_t)tid * 257 + 256];
    }
    for (int i = tid; i < 257; i += 512) sB2[i] = b2[i];

    // prefetch surr for first tile into buffer 0
    const int t0 = blockIdx.x;
    if (tid < 256 && t0 < NTILE) {
        int e = tid >> 7, j = tid & 127;
        cp_async16(surrBase + (e * 128 + j) * 16,
                   s + (size_t)(t0 * 2 + e) * SROW + CAR + j * 4);
    }
    asm volatile("cp.async.commit_group;" ::: "memory");
    asm volatile("cp.async.wait_group 0;" ::: "memory");
    __syncthreads();

    const int rrot    = ((r >> 2) & 7) * 4;
    const int rowbase = r * 544 + rrot;
    int abase[2][2];
    #pragma unroll
    for (int mt = 0; mt < 2; mt++)
        #pragma unroll
        for (int rr = 0; rr < 2; rr++) {
            int row = wr * 32 + mt * 16 + rr * 8 + tq;
            abase[mt][rr] = row * 544 + ((row >> 2) & 7) * 4 + tm * 8;
        }

    int bufc = 0;
    for (int tt = blockIdx.x; tt < NTILE; tt += NCTA) {
        const int b0 = tt * 2;
        float* sSurr = (float*)(smem + SM_SURR + bufc * 4096);

        const float4 s0 = ((const float4*)sSurr)[r * 2];
        const float4 s1 = ((const float4*)sSurr)[r * 2 + 1];
        if (tid < 128) {
            float v = 1.0f;
            if (s0.x == -1.f || s0.y == -1.f || s0.z == -1.f || s0.w == -1.f ||
                s1.x == -1.f || s1.y == -1.f || s1.z == -1.f || s1.w == -1.f) v = 0.f;
            sValid[tid] = v;
        }
        const unsigned long long sp0 = packf2(s0.x, s0.x), sp1 = packf2(s0.y, s0.y);
        const unsigned long long sp2 = packf2(s0.z, s0.z), sp3 = packf2(s0.w, s0.w);
        const unsigned long long sp4 = packf2(s1.x, s1.x), sp5 = packf2(s1.y, s1.y);
        const unsigned long long sp6 = packf2(s1.z, s1.z), sp7 = packf2(s1.w, s1.w);

        // kick off surr prefetch for next tile into the other buffer
        const int tn = tt + NCTA;
        if (tid < 256 && tn < NTILE) {
            int e = tid >> 7, j = tid & 127;
            cp_async16(surrBase + (1 - bufc) * 4096 + (e * 128 + j) * 16,
                       s + (size_t)(tn * 2 + e) * SROW + CAR + j * 4);
        }
        asm volatile("cp.async.commit_group;" ::: "memory");

        // ---- H phase (dual fma2 chains) ----
        unsigned long long dot2 = packf2(0.f, 0.f);
        #pragma unroll 4
        for (int jj = 0; jj < 32; jj++) {
            const int kl = sub * 64 + 2 * jj;
            const int kp = kl >> 1;
            ulonglong2 wA = *(const ulonglong2*)(sW1t + kp * 16);
            ulonglong2 wB = *(const ulonglong2*)(sW1t + kp * 16 + 4);
            ulonglong2 wC = *(const ulonglong2*)(sW1t + kp * 16 + 8);
            ulonglong2 wD = *(const ulonglong2*)(sW1t + kp * 16 + 12);
            unsigned long long accA = *(const unsigned long long*)(sB1 + kl);
            unsigned long long accB = packf2(0.f, 0.f);
            fma2(accA, wA.x, sp0); fma2(accB, wA.y, sp1);
            fma2(accA, wB.x, sp2); fma2(accB, wB.y, sp3);
            fma2(accA, wC.x, sp4); fma2(accB, wC.y, sp5);
            fma2(accA, wD.x, sp6); fma2(accB, wD.y, sp7);
            add2(accA, accB);
            float f0, f1;
            unpackf2(f0, f1, accA);
            f0 = fmaxf(f0, 0.f); f1 = fmaxf(f1, 0.f);
            {
                unsigned long long wl = *(const unsigned long long*)(sWlast + kl);
                fma2(dot2, packf2(f0, f1), wl);
            }
            *(uint32_t*)(smem + SM_HHI + rowbase + kwoff(kl)) = cvt_f16x2(f0, f1);
        }
        __syncthreads();

        // ---- MMA: 16 ksteps ----
        float acc[8][2][4];
        #pragma unroll
        for (int nt = 0; nt < 8; nt++)
            #pragma unroll
            for (int mt = 0; mt < 2; mt++)
                #pragma unroll
                for (int c = 0; c < 4; c++) acc[nt][mt][c] = 0.f;

        #pragma unroll 2
        for (int sg = 0; sg < 16; sg++) {
            uint32_t Ah[2][2][2];
            #pragma unroll
            for (int mt = 0; mt < 2; mt++)
                #pragma unroll
                for (int rr = 0; rr < 2; rr++) {
                    int off = abase[mt][rr] + sg * 32;
                    Ah[mt][rr][0] = *(const uint32_t*)(smem + SM_HHI + off);
                    Ah[mt][rr][1] = *(const uint32_t*)(smem + SM_HHI + off + 4);
                }
            #pragma unroll
            for (int nt = 0; nt < 8; nt++) {
                int n = wc * 64 + nt * 8 + tq;
                uint2 Bh = *(const uint2*)(smem + SM_BHI + n * 544 + sg * 32 + tm * 8);
                #pragma unroll
                for (int mt = 0; mt < 2; mt++) {
                    float* c = acc[nt][mt];
                    mma_f16(c[0], c[1], c[2], c[3],
                            Ah[mt][0][0], Ah[mt][1][0], Ah[mt][0][1], Ah[mt][1][1],
                            Bh.x, Bh.y);
                }
            }
        }
        __syncthreads();

        // ---- epilogue: write sDotp(raw) + sPart partials, one sync ----
        {
            float da, db;
            unpackf2(da, db, dot2);
            sDotp[sub * 128 + r] = da + db;
        }
        {
            const float vA = sValid[wr * 32 + tq];
            const float vB = sValid[wr * 32 + tq + 8];
            const float vC = sValid[wr * 32 + tq + 16];
            const float vD = sValid[wr * 32 + tq + 24];
            #pragma unroll
            for (int nt = 0; nt < 8; nt++) {
                int c0 = wc * 64 + nt * 8 + tm * 2;
                float e0 = sB2[c0], e1 = sB2[c0 + 1];
                float* a0 = acc[nt][0];
                float* a1 = acc[nt][1];
                float p0 = fmaxf(a0[0] + e0, 0.f) * vA + fmaxf(a0[2] + e0, 0.f) * vB
                         + fmaxf(a1[0] + e0, 0.f) * vC + fmaxf(a1[2] + e0, 0.f) * vD;
                float p1 = fmaxf(a0[1] + e1, 0.f) * vA + fmaxf(a0[3] + e1, 0.f) * vB
                         + fmaxf(a1[1] + e1, 0.f) * vC + fmaxf(a1[3] + e1, 0.f) * vD;
                p0 += __shfl_down_sync(0xffffffffu, p0, 16);
                p0 += __shfl_down_sync(0xffffffffu, p0, 8);
                p0 += __shfl_down_sync(0xffffffffu, p0, 4);
                p1 += __shfl_down_sync(0xffffffffu, p1, 16);
                p1 += __shfl_down_sync(0xffffffffu, p1, 8);
                p1 += __shfl_down_sync(0xffffffffu, p1, 4);
                if (tq == 0) {
                    sPart[wr * 256 + c0]     = p0;
                    sPart[wr * 256 + c0 + 1] = p1;
                }
            }
        }
        __syncthreads();

        // col-256 stage 1 + named barrier among warps 0-3, overlapping g_x stores
        if (tid < 128) {
            float dsum = sDotp[tid] + sDotp[128 + tid]
                       + sDotp[256 + tid] + sDotp[384 + tid];
            sDotp[tid] = fmaxf(dsum + sB2[256], 0.f) * sValid[tid];
        }
        // enc-col x words -> g_xA main (k<256) or g_xAux (k>=256)  [warps 4-15 + 0-3 later]
        if (tid >= 256) {
            int i = tid - 256;
            int e = i >> 7, j = i & 127;
            int c = 2 * j, k = 8 + c;
            float v0 = sPart[(2 * e) * 256 + c]     + sPart[(2 * e + 1) * 256 + c];
            float v1 = sPart[(2 * e) * 256 + c + 1] + sPart[(2 * e + 1) * 256 + c + 1];
            int b = b0 + e;
            int R = b & 127;
            uint32_t word = cvt_f16x2(v0, v1);
            if (k < 256) {
                *(uint32_t*)((char*)g_xA + (size_t)(b >> 7) * 69632
                             + R * 544 + ((R >> 2) & 7) * 4 + kwoff(k)) = word;
            } else {
                *(uint32_t*)((char*)g_xAux + (size_t)(b >> 7) * 5120
                             + R * 40 + (kwoff(k) - 512)) = word;
            }
        }
        if (tid < 128) {
            asm volatile("bar.sync 1, 128;" ::: "memory");
            if (w < 2) {
                float tt2 = sDotp[w * 64 + lane] + sDotp[w * 64 + 32 + lane];
                #pragma unroll
                for (int off = 16; off > 0; off >>= 1)
                    tt2 += __shfl_down_sync(0xffffffffu, tt2, off);
                if (lane == 0) sX264[w] = tt2;
            }
            asm volatile("bar.sync 1, 128;" ::: "memory");
            // remaining x words for this thread range
            int i = tid;
            int e = i >> 6, j = i & 63;       // e in 0..1, j in 0..63
            int c = 128 + 2 * j, k = 8 + c;   // cols 128..255
            float v0 = sPart[(2 * e) * 256 + c]     + sPart[(2 * e + 1) * 256 + c];
            float v1 = sPart[(2 * e) * 256 + c + 1] + sPart[(2 * e + 1) * 256 + c + 1];
            int b = b0 + e;
            int R = b & 127;
            uint32_t word = cvt_f16x2(v0, v1);
            if (k < 256) {
                *(uint32_t*)((char*)g_xA + (size_t)(b >> 7) * 69632
                             + R * 544 + ((R >> 2) & 7) * 4 + kwoff(k)) = word;
            } else {
                *(uint32_t*)((char*)g_xAux + (size_t)(b >> 7) * 5120
                             + R * 40 + (kwoff(k) - 512)) = word;
            }
        } else if (tid >= 128 && tid < 256) {
            int i = tid - 128;
            int e = i >> 6, j = i & 63;
            int c = 2 * j, k = 8 + c;         // cols 0..127
            float v0 = sPart[(2 * e) * 256 + c]     + sPart[(2 * e + 1) * 256 + c];
            float v1 = sPart[(2 * e) * 256 + c + 1] + sPart[(2 * e + 1) * 256 + c + 1];
            int b = b0 + e;
            int R = b & 127;
            *(uint32_t*)((char*)g_xA + (size_t)(b >> 7) * 69632
                         + R * 544 + ((R >> 2) & 7) * 4 + kwoff(k)) = cvt_f16x2(v0, v1);
        }
        __syncthreads();   // sX264 + all sPart reads done
        // special x words: self pairs + (x264,0) aux word
        if (tid >= 256 && tid < 266) {
            int e = (tid - 256) >= 5 ? 1 : 0;
            int idx = (tid - 256) - e * 5;
            int b = b0 + e;
            int R = b & 127;
            if (idx < 4) {
                int kl = 2 * idx;
                float v0 = s[(size_t)b * SROW + kl];
                float v1 = s[(size_t)b * SROW + kl + 1];
                *(uint32_t*)((char*)g_xA + (size_t)(b >> 7) * 69632
                             + R * 544 + ((R >> 2) & 7) * 4 + kwoff(kl)) = cvt_f16x2(v0, v1);
            } else {
                *(uint32_t*)((char*)g_xAux + (size_t)(b >> 7) * 5120 + R * 40 + 4) =
                    cvt_f16x2(sX264[e], 0.f);
            }
        }
        asm volatile("cp.async.wait_group 0;" ::: "memory");
        __syncthreads();   // H-alias scratch free + next surr buffer ready
        bufc ^= 1;
    }
}

// ---------------------------------------------------------------------------
// Q head v4 (mma, R13, measured 28us): 64 CTAs x 128 rows, 512 threads.
// ---------------------------------------------------------------------------
__global__ void __launch_bounds__(512, 1) qhead_kernel(
    const float* __restrict__ Qw1, const float* __restrict__ Qb1,
    const float* __restrict__ Qw2, const float* __restrict__ Qb2,
    float* __restrict__ out)
{
    extern __shared__ char smem[];
    const int tid = threadIdx.x;
    const int w    = tid >> 5, lane = tid & 31;
    const int wr   = w & 3,   wc   = w >> 2;
    const int tq   = lane >> 2, tm = lane & 3;

    {
        const int n0 = tid >> 1, half = tid & 1;
        char* dst = smem + QSM_B1 + n0 * 544 + half * 68 * 4;
        #pragma unroll 4
        for (int ww = 0; ww < 68; ww++) {
            int wd = half * 68 + ww;
            int sL = wd >> 3, rem = wd & 7, q = rem >> 1, h2 = rem & 1;
            int k0 = sL * 16 + 2 * (h2 * 4 + q);
            float f0 = (k0 < QIN)     ? Qw1[(size_t)k0 * HID + n0]       : 0.f;
            float f1 = (k0 + 1 < QIN) ? Qw1[(size_t)(k0 + 1) * HID + n0] : 0.f;
            *(uint32_t*)(dst + ww * 4) = cvt_f16x2(f0, f1);
        }
    }
    {
        const uint4* src = (const uint4*)((const char*)g_xA + (size_t)blockIdx.x * 69632);
        uint4* dst = (uint4*)(smem + QSM_A);
        #pragma unroll
        for (int i = tid; i < 4352; i += 512) dst[i] = src[i];
        const uint4* srcX = (const uint4*)((const char*)g_xAux + (size_t)blockIdx.x * 5120);
        uint4* dstX = (uint4*)(smem + QSM_AUX);
        if (tid < 320) dstX[tid] = srcX[tid];
    }
    for (int i = tid; i < 31 * 128; i += 512) {
        int n = i >> 7, wd = i & 127;
        int sL = wd >> 3, rem = wd & 7, q = rem >> 1, h2 = rem & 1;
        int k0 = sL * 16 + 2 * (h2 * 4 + q);
        float f0 = 0.f, f1 = 0.f;
        if (n < ADIM) {
            f0 = Qw2[(size_t)k0 * ADIM + n];
            f1 = Qw2[(size_t)(k0 + 1) * ADIM + n];
        }
        *(uint32_t*)(smem + QSM_B2 + n * 544 + wd * 4) = cvt_f16x2(f0, f1);
    }
    if (tid < 256) ((float*)(smem + QSM_QB1))[tid] = Qb1[tid];
    if (tid < 32)  ((float*)(smem + QSM_QB2))[tid] = (tid < ADIM) ? Qb2[tid] : 0.f;
    __syncthreads();

    int abase[2][2];
    #pragma unroll
    for (int mt = 0; mt < 2; mt++)
        #pragma unroll
        for (int rr = 0; rr < 2; rr++) {
            int row = wr * 32 + mt * 16 + rr * 8 + tq;
            abase[mt][rr] = row * 544 + ((row >> 2) & 7) * 4 + tm * 8;
        }

    float acc[8][2][4];
    #pragma unroll
    for (int nt = 0; nt < 8; nt++)
        #pragma unroll
        for (int mt = 0; mt < 2; mt++)
            #pragma unroll
            for (int c = 0; c < 4; c++) acc[nt][mt][c] = 0.f;

    #pragma unroll 2
    for (int sg = 0; sg < 16; sg++) {
        uint32_t Ah[2][2][2];
        #pragma unroll
        for (int mt = 0; mt < 2; mt++)
            #pragma unroll
            for (int rr = 0; rr < 2; rr++) {
                int off = abase[mt][rr] + sg * 32;
                Ah[mt][rr][0] = *(const uint32_t*)(smem + QSM_A + off);
                Ah[mt][rr][1] = *(const uint32_t*)(smem + QSM_A + off + 4);
            }
        #pragma unroll
        for (int nt = 0; nt < 8; nt++) {
            int n = wc * 64 + nt * 8 + tq;
            uint2 Bh = *(const uint2*)(smem + QSM_B1 + n * 544 + sg * 32 + tm * 8);
            #pragma unroll
            for (int mt = 0; mt < 2; mt++) {
                float* c = acc[nt][mt];
                mma_f16(c[0], c[1], c[2], c[3],
                        Ah[mt][0][0], Ah[mt][1][0], Ah[mt][0][1], Ah[mt][1][1],
                        Bh.x, Bh.y);
            }
        }
    }
    {   // aux kstep
        uint32_t Ah[2][2][2];
        #pragma unroll
        for (int mt = 0; mt < 2; mt++)
            #pragma unroll
            for (int rr = 0; rr < 2; rr++) {
                int row = wr * 32 + mt * 16 + rr * 8 + tq;
                int off = row * 40 + tm * 8;
                Ah[mt][rr][0] = *(const uint32_t*)(smem + QSM_AUX + off);
                Ah[mt][rr][1] = *(const uint32_t*)(smem + QSM_AUX + off + 4);
            }
        #pragma unroll
        for (int nt = 0; nt < 8; nt++) {
            int n = wc * 64 + nt * 8 + tq;
            uint2 Bh = *(const uint2*)(smem + QSM_B1 + n * 544 + 16 * 32 + tm * 8);
            #pragma unroll
            for (int mt = 0; mt < 2; mt++) {
                float* c = acc[nt][mt];
                mma_f16(c[0], c[1], c[2], c[3],
                        Ah[mt][0][0], Ah[mt][1][0], Ah[mt][0][1], Ah[mt][1][1],
                        Bh.x, Bh.y);
            }
        }
    }
    __syncthreads();

    {
        const float* qb1 = (const float*)(smem + QSM_QB1);
        #pragma unroll
        for (int nt = 0; nt < 8; nt++)
            #pragma unroll
            for (int mt = 0; mt < 2; mt++) {
                int c0 = wc * 64 + nt * 8 + tm * 2;
                float e0 = qb1[c0], e1 = qb1[c0 + 1];
                int R0 = wr * 32 + mt * 16 + tq;
                int R1 = R0 + 8;
                int wo = kwoff(c0);
                float* a = acc[nt][mt];
                *(uint32_t*)(smem + QSM_A + R0 * 544 + ((R0 >> 2) & 7) * 4 + wo) =
                    cvt_f16x2(fmaxf(a[0] + e0, 0.f), fmaxf(a[1] + e1, 0.f));
                *(uint32_t*)(smem + QSM_A + R1 * 544 + ((R1 >> 2) & 7) * 4 + wo) =
                    cvt_f16x2(fmaxf(a[2] + e0, 0.f), fmaxf(a[3] + e1, 0.f));
            }
    }
    __syncthreads();

    float a2[2][4];
    #pragma unroll
    for (int mt = 0; mt < 2; mt++)
        #pragma unroll
        for (int c = 0; c < 4; c++) a2[mt][c] = 0.f;

    #pragma unroll 4
    for (int sg = 0; sg < 16; sg++) {
        uint32_t Ah[2][2][2];
        #pragma unroll
        for (int mt = 0; mt < 2; mt++)
            #pragma unroll
            for (int rr = 0; rr < 2; rr++) {
                int off = abase[mt][rr] + sg * 32;
                Ah[mt][rr][0] = *(const uint32_t*)(smem + QSM_A + off);
                Ah[mt][rr][1] = *(const uint32_t*)(smem + QSM_A + off + 4);
            }
        int n2 = wc * 8 + tq;
        uint2 Bh = *(const uint2*)(smem + QSM_B2 + n2 * 544 + sg * 32 + tm * 8);
        #pragma unroll
        for (int mt = 0; mt < 2; mt++) {
            float* c = a2[mt];
            mma_f16(c[0], c[1], c[2], c[3],
                    Ah[mt][0][0], Ah[mt][1][0], Ah[mt][0][1], Ah[mt][1][1],
                    Bh.x, Bh.y);
        }
    }

    {
        const float* qb2 = (const float*)(smem + QSM_QB2);
        const int cg = wc * 8 + tm * 2;
        const size_t gb = (size_t)blockIdx.x * 128;
        #pragma unroll
        for (int mt = 0; mt < 2; mt++) {
            int row = wr * 32 + mt * 16 + tq;
            if (cg < ADIM) {
                out[(gb + row) * ADIM + cg]     = a2[mt][0] + qb2[cg];
                out[(gb + row + 8) * ADIM + cg] = a2[mt][2] + qb2[cg];
            }
            if (cg + 1 < ADIM) {
                out[(gb + row) * ADIM + cg + 1]     = a2[mt][1] + qb2[cg + 1];
                out[(gb + row + 8) * ADIM + cg + 1] = a2[mt][3] + qb2[cg + 1];
            }
        }
    }
}

// ---------------------------------------------------------------------------
extern "C" void kernel_launch(void* const* d_in, const int* in_sizes, int n_in,
                              void* d_out, int out_size)
{
    const float* s   = (const float*)d_in[0];
    const float* W1  = (const float*)d_in[1];
    const float* b1  = (const float*)d_in[2];
    const float* W2  = (const float*)d_in[3];
    const float* b2  = (const float*)d_in[4];
    const float* Qw1 = (const float*)d_in[5];
    const float* Qb1 = (const float*)d_in[6];
    const float* Qw2 = (const float*)d_in[7];
    const float* Qb2 = (const float*)d_in[8];
    float* out = (float*)d_out;

    cudaFuncSetAttribute(enc_kernel,
                         cudaFuncAttributeMaxDynamicSharedMemorySize, SM_TOTAL);
    cudaFuncSetAttribute(qhead_kernel,
                         cudaFuncAttributeMaxDynamicSharedMemorySize, QSM_TOT);

    enc_kernel<<<NCTA, 512, SM_TOTAL>>>(s, W1, b1, W2, b2);
    qhead_kernel<<<BATCH / 128, 512, QSM_TOT>>>(Qw1, Qb1, Qw2, Qb2, out);
}

// round 15
// speedup vs baseline: 11.0541x; 1.2266x over previous
#include <cuda_runtime.h>
#include <cuda_fp16.h>
#include <cstdint>

#define BATCH 8192
#define CAR   8
#define HID   256
#define QIN   265
#define ADIM  30
#define SROW  520
#define NCTA  152
#define NTILE 4096

// ---- enc smem offsets (bytes) ----
#define SM_BHI   0         // 256n x 544B fp16 W2 B slab = 139264
#define SM_HHI   139264    // 128r x 544B fp16 H, rotated rows = 69632
#define SM_W1B   208896    // 256n x 32B fp16 W1 B slab (k0..7 + bias@k8) = 8192
#define SM_B2    217088    // 257 floats -> pad 1040
#define SM_WLAST 218128    // 1024
#define SM_SURR  219152    // 2 bufs x 4096 = 8192 (16B-aligned)
#define SM_VALID 227344    // 512
#define SM_X264  227856    // 16
#define SM_DOTP  227872    // 4 groups x 128 rows = 2048
#define SM_TOTAL 229920
// alias after main MMA: sPart = SM_HHI + 2048 (4096B)

// ---- qhead smem offsets (bytes) ----
#define QSM_B1   0         // 256n x 544B fp16 Qw1 slab (17 ksteps) = 139264
#define QSM_A    139264    // 128r x 544B fp16 x main slab (k 0..255) = 69632
#define QSM_AUX  208896    // 128r x 40B fp16 x aux (k 256..271)     = 5120
#define QSM_B2   214016    // 31n x 544B fp16 Qw2 slab               = 16864
#define QSM_QB1  230880    // 1024
#define QSM_QB2  231904    // 128
#define QSM_TOT  232032

__device__ __align__(16) uint32_t g_xA[64 * 128 * 136];
__device__ __align__(16) uint32_t g_xAux[64 * 128 * 10];

// ---------------------------------------------------------------------------
__device__ __forceinline__ uint32_t cvt_f16x2(float lo, float hi) {
    uint32_t u;
    asm("cvt.rn.f16x2.f32 %0, %1, %2;" : "=r"(u) : "f"(hi), "f"(lo));
    return u;
}
__device__ __forceinline__ void mma_f16(float& c0, float& c1, float& c2, float& c3,
                                        uint32_t a0, uint32_t a1, uint32_t a2, uint32_t a3,
                                        uint32_t b0, uint32_t b1) {
    asm volatile(
        "mma.sync.aligned.m16n8k16.row.col.f32.f16.f16.f32 "
        "{%0,%1,%2,%3}, {%4,%5,%6,%7}, {%8,%9}, {%0,%1,%2,%3};"
        : "+f"(c0), "+f"(c1), "+f"(c2), "+f"(c3)
        : "r"(a0), "r"(a1), "r"(a2), "r"(a3), "r"(b0), "r"(b1));
}
__device__ __forceinline__ int kwoff(int kl) {
    int sL = kl >> 4, j8 = (kl & 15) >> 1;
    return (sL * 8 + (j8 & 3) * 2 + (j8 >> 2)) * 4;
}
__device__ __forceinline__ void cp_async16(uint32_t smem_addr, const void* gptr) {
    asm volatile("cp.async.ca.shared.global [%0], [%1], 16;"
                 :: "r"(smem_addr), "l"(gptr) : "memory");
}
__device__ __forceinline__ uint32_t smem_u32(const void* p) {
    uint32_t a;
    asm("{ .reg .u64 t; cvta.to.shared.u64 t, %1; cvt.u32.u64 %0, t; }"
        : "=r"(a) : "l"(p));
    return a;
}

// ---------------------------------------------------------------------------
// encoder: CTA owns full N=256, grid-stride over 4096 tiles (2 elems each).
// H computed via one fp16 MMA kstep (bias folded as k=8 input of 1.0).
// ---------------------------------------------------------------------------
__global__ void __launch_bounds__(512, 1) enc_kernel(
    const float* __restrict__ s, const float* __restrict__ W1,
    const float* __restrict__ b1, const float* __restrict__ W2,
    const float* __restrict__ b2)
{
    extern __shared__ char smem[];
    const int tid = threadIdx.x;
    const int w    = tid >> 5, lane = tid & 31;
    const int wr   = w & 3,   wc   = w >> 2;
    const int tq   = lane >> 2, tm = lane & 3;
    const int r    = tid & 127;

    float* sB2    = (float*)(smem + SM_B2);
    float* sWlast = (float*)(smem + SM_WLAST);
    float* sValid = (float*)(smem + SM_VALID);
    float* sX264  = (float*)(smem + SM_X264);
    float* sDotp  = (float*)(smem + SM_DOTP);
    float* sPart  = (float*)(smem + SM_HHI + 2048);
    const uint32_t surrBase = smem_u32(smem + SM_SURR);

    // ---- prologue: W2 B slab ----
    for (int i = tid; i < 32768; i += 512) {
        int word = i >> 8, n = i & 255;
        int sL = word >> 3, rem = word & 7, q = rem >> 1, h2 = rem & 1;
        int k0 = sL * 16 + 2 * (h2 * 4 + q);
        float f0 = W2[(size_t)k0 * 257 + n];
        float f1 = W2[(size_t)(k0 + 1) * 257 + n];
        *(uint32_t*)(smem + SM_BHI + n * 544 + word * 4) = cvt_f16x2(f0, f1);
    }
    // W1 B slab: word0=(k0,k1) w2=(k2,k3) w4=(k4,k5) w6=(k6,k7) w1=(b1,0) w3=w5=w7=0
    if (tid < 256) {
        int n = tid;
        uint32_t wv[8];
        wv[0] = cvt_f16x2(W1[0 * HID + n], W1[1 * HID + n]);
        wv[2] = cvt_f16x2(W1[2 * HID + n], W1[3 * HID + n]);
        wv[4] = cvt_f16x2(W1[4 * HID + n], W1[5 * HID + n]);
        wv[6] = cvt_f16x2(W1[6 * HID + n], W1[7 * HID + n]);
        wv[1] = cvt_f16x2(b1[n], 0.f);
        wv[3] = wv[5] = wv[7] = 0u;
        uint4* dst = (uint4*)(smem + SM_W1B + n * 32);
        dst[0] = make_uint4(wv[0], wv[1], wv[2], wv[3]);
        dst[1] = make_uint4(wv[4], wv[5], wv[6], wv[7]);
        sWlast[n] = W2[(size_t)n * 257 + 256];
    }
    for (int i = tid; i < 257; i += 512) sB2[i] = b2[i];

    // prefetch surr for first tile into buffer 0
    const int t0 = blockIdx.x;
    if (tid < 256 && t0 < NTILE) {
        int e = tid >> 7, j = tid & 127;
        cp_async16(surrBase + (e * 128 + j) * 16,
                   s + (size_t)(t0 * 2 + e) * SROW + CAR + j * 4);
    }
    asm volatile("cp.async.commit_group;" ::: "memory");
    asm volatile("cp.async.wait_group 0;" ::: "memory");
    __syncthreads();

    int abase[2][2];
    #pragma unroll
    for (int mt = 0; mt < 2; mt++)
        #pragma unroll
        for (int rr = 0; rr < 2; rr++) {
            int row = wr * 32 + mt * 16 + rr * 8 + tq;
            abase[mt][rr] = row * 544 + ((row >> 2) & 7) * 4 + tm * 8;
        }

    int bufc = 0;
    for (int tt = blockIdx.x; tt < NTILE; tt += NCTA) {
        const int b0 = tt * 2;
        float* sSurr = (float*)(smem + SM_SURR + bufc * 4096);

        if (tid < 128) {
            float4 q0 = ((const float4*)sSurr)[tid * 2];
            float4 q1 = ((const float4*)sSurr)[tid * 2 + 1];
            float v = 1.0f;
            if (q0.x == -1.f || q0.y == -1.f || q0.z == -1.f || q0.w == -1.f ||
                q1.x == -1.f || q1.y == -1.f || q1.z == -1.f || q1.w == -1.f) v = 0.f;
            sValid[tid] = v;
        }

        // kick off surr prefetch for next tile
        const int tn = tt + NCTA;
        if (tid < 256 && tn < NTILE) {
            int e = tid >> 7, j = tid & 127;
            cp_async16(surrBase + (1 - bufc) * 4096 + (e * 128 + j) * 16,
                       s + (size_t)(tn * 2 + e) * SROW + CAR + j * 4);
        }
        asm volatile("cp.async.commit_group;" ::: "memory");

        // ---- H phase via MMA (one kstep: 8 surr k + bias@k8) ----
        {
            uint32_t A0[2], A1[2];
            #pragma unroll
            for (int mt = 0; mt < 2; mt++) {
                int row0 = wr * 32 + mt * 16 + tq;
                float2 v0 = *(const float2*)(sSurr + row0 * 8 + tm * 2);
                float2 v1 = *(const float2*)(sSurr + (row0 + 8) * 8 + tm * 2);
                A0[mt] = cvt_f16x2(v0.x, v0.y);
                A1[mt] = cvt_f16x2(v1.x, v1.y);
            }
            const uint32_t A23 = (tm == 0) ? 0x00003C00u : 0u;  // (1.0, 0) fp16

            float hacc[8][2][4];
            #pragma unroll
            for (int nt = 0; nt < 8; nt++)
                #pragma unroll
                for (int mt = 0; mt < 2; mt++)
                    #pragma unroll
                    for (int c = 0; c < 4; c++) hacc[nt][mt][c] = 0.f;

            #pragma unroll
            for (int nt = 0; nt < 8; nt++) {
                int n = wc * 64 + nt * 8 + tq;
                uint2 Bh = *(const uint2*)(smem + SM_W1B + n * 32 + tm * 8);
                #pragma unroll
                for (int mt = 0; mt < 2; mt++) {
                    float* c = hacc[nt][mt];
                    mma_f16(c[0], c[1], c[2], c[3],
                            A0[mt], A1[mt], A23, A23, Bh.x, Bh.y);
                }
            }

            // relu -> store fp16 H fragments + col-256 dot partials
            float dotr[4] = {0.f, 0.f, 0.f, 0.f};
            #pragma unroll
            for (int nt = 0; nt < 8; nt++) {
                int kb = wc * 64 + nt * 8 + tm * 2;
                float2 wl = *(const float2*)(sWlast + kb);
                int wo = kwoff(kb);
                #pragma unroll
                for (int mt = 0; mt < 2; mt++) {
                    float h0 = fmaxf(hacc[nt][mt][0], 0.f);
                    float h1 = fmaxf(hacc[nt][mt][1], 0.f);
                    float h2 = fmaxf(hacc[nt][mt][2], 0.f);
                    float h3 = fmaxf(hacc[nt][mt][3], 0.f);
                    dotr[mt * 2]     = fmaf(h0, wl.x, fmaf(h1, wl.y, dotr[mt * 2]));
                    dotr[mt * 2 + 1] = fmaf(h2, wl.x, fmaf(h3, wl.y, dotr[mt * 2 + 1]));
                    int R0 = wr * 32 + mt * 16 + tq, R1 = R0 + 8;
                    *(uint32_t*)(smem + SM_HHI + R0 * 544 + ((R0 >> 2) & 7) * 4 + wo) =
                        cvt_f16x2(h0, h1);
                    *(uint32_t*)(smem + SM_HHI + R1 * 544 + ((R1 >> 2) & 7) * 4 + wo) =
                        cvt_f16x2(h2, h3);
                }
            }
            #pragma unroll
            for (int i = 0; i < 4; i++) {
                dotr[i] += __shfl_xor_sync(0xffffffffu, dotr[i], 1);
                dotr[i] += __shfl_xor_sync(0xffffffffu, dotr[i], 2);
            }
            if (tm == 0) {
                #pragma unroll
                for (int mt = 0; mt < 2; mt++) {
                    int R0 = wr * 32 + mt * 16 + tq;
                    sDotp[wc * 128 + R0]     = dotr[mt * 2];
                    sDotp[wc * 128 + R0 + 8] = dotr[mt * 2 + 1];
                }
            }
        }
        __syncthreads();

        // ---- main MMA: 16 ksteps ----
        float acc[8][2][4];
        #pragma unroll
        for (int nt = 0; nt < 8; nt++)
            #pragma unroll
            for (int mt = 0; mt < 2; mt++)
                #pragma unroll
                for (int c = 0; c < 4; c++) acc[nt][mt][c] = 0.f;

        #pragma unroll 2
        for (int sg = 0; sg < 16; sg++) {
            uint32_t Ah[2][2][2];
            #pragma unroll
            for (int mt = 0; mt < 2; mt++)
                #pragma unroll
                for (int rr = 0; rr < 2; rr++) {
                    int off = abase[mt][rr] + sg * 32;
                    Ah[mt][rr][0] = *(const uint32_t*)(smem + SM_HHI + off);
                    Ah[mt][rr][1] = *(const uint32_t*)(smem + SM_HHI + off + 4);
                }
            #pragma unroll
            for (int nt = 0; nt < 8; nt++) {
                int n = wc * 64 + nt * 8 + tq;
                uint2 Bh = *(const uint2*)(smem + SM_BHI + n * 544 + sg * 32 + tm * 8);
                #pragma unroll
                for (int mt = 0; mt < 2; mt++) {
                    float* c = acc[nt][mt];
                    mma_f16(c[0], c[1], c[2], c[3],
                            Ah[mt][0][0], Ah[mt][1][0], Ah[mt][0][1], Ah[mt][1][1],
                            Bh.x, Bh.y);
                }
            }
        }
        __syncthreads();   // H reads done; H area (sPart alias) reusable

        // ---- epilogue: bias -> relu -> mask -> row sums ----
        {
            const float vA = sValid[wr * 32 + tq];
            const float vB = sValid[wr * 32 + tq + 8];
            const float vC = sValid[wr * 32 + tq + 16];
            const float vD = sValid[wr * 32 + tq + 24];
            #pragma unroll
            for (int nt = 0; nt < 8; nt++) {
                int c0 = wc * 64 + nt * 8 + tm * 2;
                float e0 = sB2[c0], e1 = sB2[c0 + 1];
                float* a0 = acc[nt][0];
                float* a1 = acc[nt][1];
                float p0 = fmaxf(a0[0] + e0, 0.f) * vA + fmaxf(a0[2] + e0, 0.f) * vB
                         + fmaxf(a1[0] + e0, 0.f) * vC + fmaxf(a1[2] + e0, 0.f) * vD;
                float p1 = fmaxf(a0[1] + e1, 0.f) * vA + fmaxf(a0[3] + e1, 0.f) * vB
                         + fmaxf(a1[1] + e1, 0.f) * vC + fmaxf(a1[3] + e1, 0.f) * vD;
                p0 += __shfl_down_sync(0xffffffffu, p0, 16);
                p0 += __shfl_down_sync(0xffffffffu, p0, 8);
                p0 += __shfl_down_sync(0xffffffffu, p0, 4);
                p1 += __shfl_down_sync(0xffffffffu, p1, 16);
                p1 += __shfl_down_sync(0xffffffffu, p1, 8);
                p1 += __shfl_down_sync(0xffffffffu, p1, 4);
                if (tq == 0) {
                    sPart[wr * 256 + c0]     = p0;
                    sPart[wr * 256 + c0 + 1] = p1;
                }
            }
        }
        __syncthreads();

        // col-256 stage 1 + x-word stores (overlapped)
        if (tid < 128) {
            float dsum = sDotp[tid] + sDotp[128 + tid]
                       + sDotp[256 + tid] + sDotp[384 + tid];
            sDotp[tid] = fmaxf(dsum + sB2[256], 0.f) * sValid[tid];
        }
        if (tid >= 256) {
            int i = tid - 256;
            int e = i >> 7, j = i & 127;
            int c = 2 * j, k = 8 + c;
            float v0 = sPart[(2 * e) * 256 + c]     + sPart[(2 * e + 1) * 256 + c];
            float v1 = sPart[(2 * e) * 256 + c + 1] + sPart[(2 * e + 1) * 256 + c + 1];
            int b = b0 + e;
            int R = b & 127;
            uint32_t word = cvt_f16x2(v0, v1);
            if (k < 256) {
                *(uint32_t*)((char*)g_xA + (size_t)(b >> 7) * 69632
                             + R * 544 + ((R >> 2) & 7) * 4 + kwoff(k)) = word;
            } else {
                *(uint32_t*)((char*)g_xAux + (size_t)(b >> 7) * 5120
                             + R * 40 + (kwoff(k) - 512)) = word;
            }
        }
        if (tid < 128) {
            asm volatile("bar.sync 1, 128;" ::: "memory");
            if (w < 2) {
                float tt2 = sDotp[w * 64 + lane] + sDotp[w * 64 + 32 + lane];
                #pragma unroll
                for (int off = 16; off > 0; off >>= 1)
                    tt2 += __shfl_down_sync(0xffffffffu, tt2, off);
                if (lane == 0) sX264[w] = tt2;
            }
            asm volatile("bar.sync 1, 128;" ::: "memory");
            int e = tid >> 6, j = tid & 63;
            int c = 128 + 2 * j, k = 8 + c;
            float v0 = sPart[(2 * e) * 256 + c]     + sPart[(2 * e + 1) * 256 + c];
            float v1 = sPart[(2 * e) * 256 + c + 1] + sPart[(2 * e + 1) * 256 + c + 1];
            int b = b0 + e;
            int R = b & 127;
            uint32_t word = cvt_f16x2(v0, v1);
            if (k < 256) {
                *(uint32_t*)((char*)g_xA + (size_t)(b >> 7) * 69632
                             + R * 544 + ((R >> 2) & 7) * 4 + kwoff(k)) = word;
            } else {
                *(uint32_t*)((char*)g_xAux + (size_t)(b >> 7) * 5120
                             + R * 40 + (kwoff(k) - 512)) = word;
            }
        } else if (tid >= 128 && tid < 256) {
            int i = tid - 128;
            int e = i >> 6, j = i & 63;
            int c = 2 * j, k = 8 + c;
            float v0 = sPart[(2 * e) * 256 + c]     + sPart[(2 * e + 1) * 256 + c];
            float v1 = sPart[(2 * e) * 256 + c + 1] + sPart[(2 * e + 1) * 256 + c + 1];
            int b = b0 + e;
            int R = b & 127;
            *(uint32_t*)((char*)g_xA + (size_t)(b >> 7) * 69632
                         + R * 544 + ((R >> 2) & 7) * 4 + kwoff(k)) = cvt_f16x2(v0, v1);
        }
        __syncthreads();
        if (tid >= 256 && tid < 266) {
            int e = (tid - 256) >= 5 ? 1 : 0;
            int idx = (tid - 256) - e * 5;
            int b = b0 + e;
            int R = b & 127;
            if (idx < 4) {
                int kl = 2 * idx;
                float v0 = s[(size_t)b * SROW + kl];
                float v1 = s[(size_t)b * SROW + kl + 1];
                *(uint32_t*)((char*)g_xA + (size_t)(b >> 7) * 69632
                             + R * 544 + ((R >> 2) & 7) * 4 + kwoff(kl)) = cvt_f16x2(v0, v1);
            } else {
                *(uint32_t*)((char*)g_xAux + (size_t)(b >> 7) * 5120 + R * 40 + 4) =
                    cvt_f16x2(sX264[e], 0.f);
            }
        }
        asm volatile("cp.async.wait_group 0;" ::: "memory");
        __syncthreads();
        bufc ^= 1;
    }
}

// ---------------------------------------------------------------------------
// Q head v4 (mma, R13, measured 28us): 64 CTAs x 128 rows, 512 threads.
// ---------------------------------------------------------------------------
__global__ void __launch_bounds__(512, 1) qhead_kernel(
    const float* __restrict__ Qw1, const float* __restrict__ Qb1,
    const float* __restrict__ Qw2, const float* __restrict__ Qb2,
    float* __restrict__ out)
{
    extern __shared__ char smem[];
    const int tid = threadIdx.x;
    const int w    = tid >> 5, lane = tid & 31;
    const int wr   = w & 3,   wc   = w >> 2;
    const int tq   = lane >> 2, tm = lane & 3;

    {
        const int n0 = tid >> 1, half = tid & 1;
        char* dst = smem + QSM_B1 + n0 * 544 + half * 68 * 4;
        #pragma unroll 4
        for (int ww = 0; ww < 68; ww++) {
            int wd = half * 68 + ww;
            int sL = wd >> 3, rem = wd & 7, q = rem >> 1, h2 = rem & 1;
            int k0 = sL * 16 + 2 * (h2 * 4 + q);
            float f0 = (k0 < QIN)     ? Qw1[(size_t)k0 * HID + n0]       : 0.f;
            float f1 = (k0 + 1 < QIN) ? Qw1[(size_t)(k0 + 1) * HID + n0] : 0.f;
            *(uint32_t*)(dst + ww * 4) = cvt_f16x2(f0, f1);
        }
    }
    {
        const uint4* src = (const uint4*)((const char*)g_xA + (size_t)blockIdx.x * 69632);
        uint4* dst = (uint4*)(smem + QSM_A);
        #pragma unroll
        for (int i = tid; i < 4352; i += 512) dst[i] = src[i];
        const uint4* srcX = (const uint4*)((const char*)g_xAux + (size_t)blockIdx.x * 5120);
        uint4* dstX = (uint4*)(smem + QSM_AUX);
        if (tid < 320) dstX[tid] = srcX[tid];
    }
    for (int i = tid; i < 31 * 128; i += 512) {
        int n = i >> 7, wd = i & 127;
        int sL = wd >> 3, rem = wd & 7, q = rem >> 1, h2 = rem & 1;
        int k0 = sL * 16 + 2 * (h2 * 4 + q);
        float f0 = 0.f, f1 = 0.f;
        if (n < ADIM) {
            f0 = Qw2[(size_t)k0 * ADIM + n];
            f1 = Qw2[(size_t)(k0 + 1) * ADIM + n];
        }
        *(uint32_t*)(smem + QSM_B2 + n * 544 + wd * 4) = cvt_f16x2(f0, f1);
    }
    if (tid < 256) ((float*)(smem + QSM_QB1))[tid] = Qb1[tid];
    if (tid < 32)  ((float*)(smem + QSM_QB2))[tid] = (tid < ADIM) ? Qb2[tid] : 0.f;
    __syncthreads();

    int abase[2][2];
    #pragma unroll
    for (int mt = 0; mt < 2; mt++)
        #pragma unroll
        for (int rr = 0; rr < 2; rr++) {
            int row = wr * 32 + mt * 16 + rr * 8 + tq;
            abase[mt][rr] = row * 544 + ((row >> 2) & 7) * 4 + tm * 8;
        }

    float acc[8][2][4];
    #pragma unroll
    for (int nt = 0; nt < 8; nt++)
        #pragma unroll
        for (int mt = 0; mt < 2; mt++)
            #pragma unroll
            for (int c = 0; c < 4; c++) acc[nt][mt][c] = 0.f;

    #pragma unroll 2
    for (int sg = 0; sg < 16; sg++) {
        uint32_t Ah[2][2][2];
        #pragma unroll
        for (int mt = 0; mt < 2; mt++)
            #pragma unroll
            for (int rr = 0; rr < 2; rr++) {
                int off = abase[mt][rr] + sg * 32;
                Ah[mt][rr][0] = *(const uint32_t*)(smem + QSM_A + off);
                Ah[mt][rr][1] = *(const uint32_t*)(smem + QSM_A + off + 4);
            }
        #pragma unroll
        for (int nt = 0; nt < 8; nt++) {
            int n = wc * 64 + nt * 8 + tq;
            uint2 Bh = *(const uint2*)(smem + QSM_B1 + n * 544 + sg * 32 + tm * 8);
            #pragma unroll
            for (int mt = 0; mt < 2; mt++) {
                float* c = acc[nt][mt];
                mma_f16(c[0], c[1], c[2], c[3],
                        Ah[mt][0][0], Ah[mt][1][0], Ah[mt][0][1], Ah[mt][1][1],
                        Bh.x, Bh.y);
            }
        }
    }
    {   // aux kstep
        uint32_t Ah[2][2][2];
        #pragma unroll
        for (int mt = 0; mt < 2; mt++)
            #pragma unroll
            for (int rr = 0; rr < 2; rr++) {
                int row = wr * 32 + mt * 16 + rr * 8 + tq;
                int off = row * 40 + tm * 8;
                Ah[mt][rr][0] = *(const uint32_t*)(smem + QSM_AUX + off);
                Ah[mt][rr][1] = *(const uint32_t*)(smem + QSM_AUX + off + 4);
            }
        #pragma unroll
        for (int nt = 0; nt < 8; nt++) {
            int n = wc * 64 + nt * 8 + tq;
            uint2 Bh = *(const uint2*)(smem + QSM_B1 + n * 544 + 16 * 32 + tm * 8);
            #pragma unroll
            for (int mt = 0; mt < 2; mt++) {
                float* c = acc[nt][mt];
                mma_f16(c[0], c[1], c[2], c[3],
                        Ah[mt][0][0], Ah[mt][1][0], Ah[mt][0][1], Ah[mt][1][1],
                        Bh.x, Bh.y);
            }
        }
    }
    __syncthreads();

    {
        const float* qb1 = (const float*)(smem + QSM_QB1);
        #pragma unroll
        for (int nt = 0; nt < 8; nt++)
            #pragma unroll
            for (int mt = 0; mt < 2; mt++) {
                int c0 = wc * 64 + nt * 8 + tm * 2;
                float e0 = qb1[c0], e1 = qb1[c0 + 1];
                int R0 = wr * 32 + mt * 16 + tq;
                int R1 = R0 + 8;
                int wo = kwoff(c0);
                float* a = acc[nt][mt];
                *(uint32_t*)(smem + QSM_A + R0 * 544 + ((R0 >> 2) & 7) * 4 + wo) =
                    cvt_f16x2(fmaxf(a[0] + e0, 0.f), fmaxf(a[1] + e1, 0.f));
                *(uint32_t*)(smem + QSM_A + R1 * 544 + ((R1 >> 2) & 7) * 4 + wo) =
                    cvt_f16x2(fmaxf(a[2] + e0, 0.f), fmaxf(a[3] + e1, 0.f));
            }
    }
    __syncthreads();

    float a2[2][4];
    #pragma unroll
    for (int mt = 0; mt < 2; mt++)
        #pragma unroll
        for (int c = 0; c < 4; c++) a2[mt][c] = 0.f;

    #pragma unroll 4
    for (int sg = 0; sg < 16; sg++) {
        uint32_t Ah[2][2][2];
        #pragma unroll
        for (int mt = 0; mt < 2; mt++)
            #pragma unroll
            for (int rr = 0; rr < 2; rr++) {
                int off = abase[mt][rr] + sg * 32;
                Ah[mt][rr][0] = *(const uint32_t*)(smem + QSM_A + off);
                Ah[mt][rr][1] = *(const uint32_t*)(smem + QSM_A + off + 4);
            }
        int n2 = wc * 8 + tq;
        uint2 Bh = *(const uint2*)(smem + QSM_B2 + n2 * 544 + sg * 32 + tm * 8);
        #pragma unroll
        for (int mt = 0; mt < 2; mt++) {
            float* c = a2[mt];
            mma_f16(c[0], c[1], c[2], c[3],
                    Ah[mt][0][0], Ah[mt][1][0], Ah[mt][0][1], Ah[mt][1][1],
                    Bh.x, Bh.y);
        }
    }

    {
        const float* qb2 = (const float*)(smem + QSM_QB2);
        const int cg = wc * 8 + tm * 2;
        const size_t gb = (size_t)blockIdx.x * 128;
        #pragma unroll
        for (int mt = 0; mt < 2; mt++) {
            int row = wr * 32 + mt * 16 + tq;
            if (cg < ADIM) {
                out[(gb + row) * ADIM + cg]     = a2[mt][0] + qb2[cg];
                out[(gb + row + 8) * ADIM + cg] = a2[mt][2] + qb2[cg];
            }
            if (cg + 1 < ADIM) {
                out[(gb + row) * ADIM + cg + 1]     = a2[mt][1] + qb2[cg + 1];
                out[(gb + row + 8) * ADIM + cg + 1] = a2[mt][3] + qb2[cg + 1];
            }
        }
    }
}

// ---------------------------------------------------------------------------
extern "C" void kernel_launch(void* const* d_in, const int* in_sizes, int n_in,
                              void* d_out, int out_size)
{
    const float* s   = (const float*)d_in[0];
    const float* W1  = (const float*)d_in[1];
    const float* b1  = (const float*)d_in[2];
    const float* W2  = (const float*)d_in[3];
    const float* b2  = (const float*)d_in[4];
    const float* Qw1 = (const float*)d_in[5];
    const float* Qb1 = (const float*)d_in[6];
    const float* Qw2 = (const float*)d_in[7];
    const float* Qb2 = (const float*)d_in[8];
    float* out = (float*)d_out;

    cudaFuncSetAttribute(enc_kernel,
                         cudaFuncAttributeMaxDynamicSharedMemorySize, SM_TOTAL);
    cudaFuncSetAttribute(qhead_kernel,
                         cudaFuncAttributeMaxDynamicSharedMemorySize, QSM_TOT);

    enc_kernel<<<NCTA, 512, SM_TOTAL>>>(s, W1, b1, W2, b2);
    qhead_kernel<<<BATCH / 128, 512, QSM_TOT>>>(Qw1, Qb1, Qw2, Qb2, out);
}

// round 16
// speedup vs baseline: 11.9896x; 1.0846x over previous
#include <cuda_runtime.h>
#include <cuda_fp16.h>
#include <cstdint>

#define BATCH 8192
#define CAR   8
#define HID   256
#define QIN   265
#define ADIM  30
#define SROW  520
#define NCTA  152
#define NTILE 4096

// ---- enc smem offsets (bytes) ----
#define SM_BHI   0         // 256n x 544B fp16 W2 B slab = 139264
#define SM_HHI   139264    // 128r x 544B fp16 H, rotated rows = 69632
#define SM_W1B   208896    // 256n x 32B fp16 W1 B slab (k0..7 + bias@k8) = 8192
#define SM_B2    217088    // 257 floats -> pad 1040
#define SM_WLAST 218128    // 1024
#define SM_SURR  219152    // 2 bufs x 4096 (16B-aligned); consumed buf doubles as sPart
#define SM_VALID 227344    // 512
#define SM_X264  227856    // 16
#define SM_DOTP  227872    // 4 groups x 128 rows = 2048
#define SM_TOTAL 229920

// ---- qhead smem offsets (bytes) ----
#define QSM_B1   0         // 256n x 544B fp16 Qw1 slab (17 ksteps) = 139264
#define QSM_A    139264    // 64r x 544B fp16 x main slab            = 34816
#define QSM_AUX  174080    // 64r x 40B fp16 x aux                   = 2560
#define QSM_B2   176640    // 31n x 544B fp16 Qw2 slab               = 16864
#define QSM_QB1  193504    // 1024
#define QSM_QB2  194528    // 128
#define QSM_TOT  194656

__device__ __align__(16) uint32_t g_xA[64 * 128 * 136];
__device__ __align__(16) uint32_t g_xAux[64 * 128 * 10];
__device__ __align__(16) uint32_t g_B1img[256 * 136];   // fp16 permuted Qw1 slab image

// ---------------------------------------------------------------------------
__device__ __forceinline__ uint32_t cvt_f16x2(float lo, float hi) {
    uint32_t u;
    asm("cvt.rn.f16x2.f32 %0, %1, %2;" : "=r"(u) : "f"(hi), "f"(lo));
    return u;
}
__device__ __forceinline__ void mma_f16(float& c0, float& c1, float& c2, float& c3,
                                        uint32_t a0, uint32_t a1, uint32_t a2, uint32_t a3,
                                        uint32_t b0, uint32_t b1) {
    asm volatile(
        "mma.sync.aligned.m16n8k16.row.col.f32.f16.f16.f32 "
        "{%0,%1,%2,%3}, {%4,%5,%6,%7}, {%8,%9}, {%0,%1,%2,%3};"
        : "+f"(c0), "+f"(c1), "+f"(c2), "+f"(c3)
        : "r"(a0), "r"(a1), "r"(a2), "r"(a3), "r"(b0), "r"(b1));
}
__device__ __forceinline__ int kwoff(int kl) {
    int sL = kl >> 4, j8 = (kl & 15) >> 1;
    return (sL * 8 + (j8 & 3) * 2 + (j8 >> 2)) * 4;
}
__device__ __forceinline__ void cp_async16(uint32_t smem_addr, const void* gptr) {
    asm volatile("cp.async.ca.shared.global [%0], [%1], 16;"
                 :: "r"(smem_addr), "l"(gptr) : "memory");
}
__device__ __forceinline__ uint32_t smem_u32(const void* p) {
    uint32_t a;
    asm("{ .reg .u64 t; cvta.to.shared.u64 t, %1; cvt.u32.u64 %0, t; }"
        : "=r"(a) : "l"(p));
    return a;
}

// ---------------------------------------------------------------------------
// prep: build fp16 permuted Qw1 B-slab image (17 ksteps, k>=265 zero)
// ---------------------------------------------------------------------------
__global__ void qprep_kernel(const float* __restrict__ Qw1) {
    int n = blockIdx.x, wd = threadIdx.x;
    if (wd >= 136) return;
    int sL = wd >> 3, rem = wd & 7, q = rem >> 1, h2 = rem & 1;
    int k0 = sL * 16 + 2 * (h2 * 4 + q);
    float f0 = (k0 < QIN)     ? Qw1[(size_t)k0 * HID + n]       : 0.f;
    float f1 = (k0 + 1 < QIN) ? Qw1[(size_t)(k0 + 1) * HID + n] : 0.f;
    g_B1img[n * 136 + wd] = cvt_f16x2(f0, f1);
}

// ---------------------------------------------------------------------------
// encoder: CTA owns full N=256, grid-stride. H(t+1) overlapped with stores(t).
// ---------------------------------------------------------------------------
__global__ void __launch_bounds__(512, 1) enc_kernel(
    const float* __restrict__ s, const float* __restrict__ W1,
    const float* __restrict__ b1, const float* __restrict__ W2,
    const float* __restrict__ b2)
{
    extern __shared__ char smem[];
    const int tid = threadIdx.x;
    const int w    = tid >> 5, lane = tid & 31;
    const int wr   = w & 3,   wc   = w >> 2;
    const int tq   = lane >> 2, tm = lane & 3;

    float* sB2    = (float*)(smem + SM_B2);
    float* sWlast = (float*)(smem + SM_WLAST);
    float* sValid = (float*)(smem + SM_VALID);
    float* sX264  = (float*)(smem + SM_X264);
    float* sDotp  = (float*)(smem + SM_DOTP);
    const uint32_t surrBase = smem_u32(smem + SM_SURR);

    // ---- prologue ----
    for (int i = tid; i < 32768; i += 512) {
        int word = i >> 8, n = i & 255;
        int sL = word >> 3, rem = word & 7, q = rem >> 1, h2 = rem & 1;
        int k0 = sL * 16 + 2 * (h2 * 4 + q);
        float f0 = W2[(size_t)k0 * 257 + n];
        float f1 = W2[(size_t)(k0 + 1) * 257 + n];
        *(uint32_t*)(smem + SM_BHI + n * 544 + word * 4) = cvt_f16x2(f0, f1);
    }
    if (tid < 256) {
        int n = tid;
        uint32_t wv[8];
        wv[0] = cvt_f16x2(W1[0 * HID + n], W1[1 * HID + n]);
        wv[2] = cvt_f16x2(W1[2 * HID + n], W1[3 * HID + n]);
        wv[4] = cvt_f16x2(W1[4 * HID + n], W1[5 * HID + n]);
        wv[6] = cvt_f16x2(W1[6 * HID + n], W1[7 * HID + n]);
        wv[1] = cvt_f16x2(b1[n], 0.f);
        wv[3] = wv[5] = wv[7] = 0u;
        uint4* dst = (uint4*)(smem + SM_W1B + n * 32);
        dst[0] = make_uint4(wv[0], wv[1], wv[2], wv[3]);
        dst[1] = make_uint4(wv[4], wv[5], wv[6], wv[7]);
        sWlast[n] = W2[(size_t)n * 257 + 256];
    }
    for (int i = tid; i < 257; i += 512) sB2[i] = b2[i];

    // first surr prefetch -> buf0
    if (tid < 256) {
        int e = tid >> 7, j = tid & 127;
        cp_async16(surrBase + (e * 128 + j) * 16,
                   s + (size_t)(blockIdx.x * 2 + e) * SROW + CAR + j * 4);
    }
    asm volatile("cp.async.commit_group;" ::: "memory");
    asm volatile("cp.async.wait_group 0;" ::: "memory");
    __syncthreads();

    int abase[2][2];
    #pragma unroll
    for (int mt = 0; mt < 2; mt++)
        #pragma unroll
        for (int rr = 0; rr < 2; rr++) {
            int row = wr * 32 + mt * 16 + rr * 8 + tq;
            abase[mt][rr] = row * 544 + ((row >> 2) & 7) * 4 + tm * 8;
        }

    // H phase (valid + H-MMA + col-256 dot partials) from given surr buffer
    auto do_H = [&](const float* sS) {
        if (tid < 128) {
            float4 q0 = ((const float4*)sS)[tid * 2];
            float4 q1 = ((const float4*)sS)[tid * 2 + 1];
            float v = 1.0f;
            if (q0.x == -1.f || q0.y == -1.f || q0.z == -1.f || q0.w == -1.f ||
                q1.x == -1.f || q1.y == -1.f || q1.z == -1.f || q1.w == -1.f) v = 0.f;
            sValid[tid] = v;
        }
        uint32_t A0[2], A1[2];
        #pragma unroll
        for (int mt = 0; mt < 2; mt++) {
            int row0 = wr * 32 + mt * 16 + tq;
            float2 v0 = *(const float2*)(sS + row0 * 8 + tm * 2);
            float2 v1 = *(const float2*)(sS + (row0 + 8) * 8 + tm * 2);
            A0[mt] = cvt_f16x2(v0.x, v0.y);
            A1[mt] = cvt_f16x2(v1.x, v1.y);
        }
        const uint32_t A23 = (tm == 0) ? 0x00003C00u : 0u;  // (1.0, 0) fp16

        float hacc[8][2][4];
        #pragma unroll
        for (int nt = 0; nt < 8; nt++)
            #pragma unroll
            for (int mt = 0; mt < 2; mt++)
                #pragma unroll
                for (int c = 0; c < 4; c++) hacc[nt][mt][c] = 0.f;
        #pragma unroll
        for (int nt = 0; nt < 8; nt++) {
            int n = wc * 64 + nt * 8 + tq;
            uint2 Bh = *(const uint2*)(smem + SM_W1B + n * 32 + tm * 8);
            #pragma unroll
            for (int mt = 0; mt < 2; mt++) {
                float* c = hacc[nt][mt];
                mma_f16(c[0], c[1], c[2], c[3], A0[mt], A1[mt], A23, A23, Bh.x, Bh.y);
            }
        }
        float dotr[4] = {0.f, 0.f, 0.f, 0.f};
        #pragma unroll
        for (int nt = 0; nt < 8; nt++) {
            int kb = wc * 64 + nt * 8 + tm * 2;
            float2 wl = *(const float2*)(sWlast + kb);
            int wo = kwoff(kb);
            #pragma unroll
            for (int mt = 0; mt < 2; mt++) {
                float h0 = fmaxf(hacc[nt][mt][0], 0.f);
                float h1 = fmaxf(hacc[nt][mt][1], 0.f);
                float h2 = fmaxf(hacc[nt][mt][2], 0.f);
                float h3 = fmaxf(hacc[nt][mt][3], 0.f);
                dotr[mt * 2]     = fmaf(h0, wl.x, fmaf(h1, wl.y, dotr[mt * 2]));
                dotr[mt * 2 + 1] = fmaf(h2, wl.x, fmaf(h3, wl.y, dotr[mt * 2 + 1]));
                int R0 = wr * 32 + mt * 16 + tq, R1 = R0 + 8;
                *(uint32_t*)(smem + SM_HHI + R0 * 544 + ((R0 >> 2) & 7) * 4 + wo) =
                    cvt_f16x2(h0, h1);
                *(uint32_t*)(smem + SM_HHI + R1 * 544 + ((R1 >> 2) & 7) * 4 + wo) =
                    cvt_f16x2(h2, h3);
            }
        }
        #pragma unroll
        for (int i = 0; i < 4; i++) {
            dotr[i] += __shfl_xor_sync(0xffffffffu, dotr[i], 1);
            dotr[i] += __shfl_xor_sync(0xffffffffu, dotr[i], 2);
        }
        if (tm == 0) {
            #pragma unroll
            for (int mt = 0; mt < 2; mt++) {
                int R0 = wr * 32 + mt * 16 + tq;
                sDotp[wc * 128 + R0]     = dotr[mt * 2];
                sDotp[wc * 128 + R0 + 8] = dotr[mt * 2 + 1];
            }
        }
    };

    // preloop: H for first tile
    do_H((const float*)(smem + SM_SURR));
    __syncthreads();

    int cur = 0;   // buffer holding current tile's (consumed) surr -> sPart
    for (int tt = blockIdx.x; tt < NTILE; tt += NCTA) {
        const int b0 = tt * 2;
        const int tn = tt + NCTA;

        // prefetch surr(t+1) -> other buffer
        if (tid < 256 && tn < NTILE) {
            int e = tid >> 7, j = tid & 127;
            cp_async16(surrBase + (1 - cur) * 4096 + (e * 128 + j) * 16,
                       s + (size_t)(tn * 2 + e) * SROW + CAR + j * 4);
        }
        asm volatile("cp.async.commit_group;" ::: "memory");

        // ---- main MMA: 16 ksteps ----
        float acc[8][2][4];
        #pragma unroll
        for (int nt = 0; nt < 8; nt++)
            #pragma unroll
            for (int mt = 0; mt < 2; mt++)
                #pragma unroll
                for (int c = 0; c < 4; c++) acc[nt][mt][c] = 0.f;

        #pragma unroll 2
        for (int sg = 0; sg < 16; sg++) {
            uint32_t Ah[2][2][2];
            #pragma unroll
            for (int mt = 0; mt < 2; mt++)
                #pragma unroll
                for (int rr = 0; rr < 2; rr++) {
                    int off = abase[mt][rr] + sg * 32;
                    Ah[mt][rr][0] = *(const uint32_t*)(smem + SM_HHI + off);
                    Ah[mt][rr][1] = *(const uint32_t*)(smem + SM_HHI + off + 4);
                }
            #pragma unroll
            for (int nt = 0; nt < 8; nt++) {
                int n = wc * 64 + nt * 8 + tq;
                uint2 Bh = *(const uint2*)(smem + SM_BHI + n * 544 + sg * 32 + tm * 8);
                #pragma unroll
                for (int mt = 0; mt < 2; mt++) {
                    float* c = acc[nt][mt];
                    mma_f16(c[0], c[1], c[2], c[3],
                            Ah[mt][0][0], Ah[mt][1][0], Ah[mt][0][1], Ah[mt][1][1],
                            Bh.x, Bh.y);
                }
            }
        }
        __syncthreads();   // sync1: H(t) reads done

        // ---- snapshot (reads that H(t+1) will clobber) ----
        const float vA = sValid[wr * 32 + tq];
        const float vB = sValid[wr * 32 + tq + 8];
        const float vC = sValid[wr * 32 + tq + 16];
        const float vD = sValid[wr * 32 + tq + 24];
        float dval = 0.f;
        if (tid < 128) {
            float dsum = sDotp[tid] + sDotp[128 + tid]
                       + sDotp[256 + tid] + sDotp[384 + tid];
            dval = fmaxf(dsum + sB2[256], 0.f) * sValid[tid];
        }

        // ---- compress acc -> sPart (aliases consumed surr buffer) ----
        float* sPart = (float*)(smem + SM_SURR + cur * 4096);
        #pragma unroll
        for (int nt = 0; nt < 8; nt++) {
            int c0 = wc * 64 + nt * 8 + tm * 2;
            float e0 = sB2[c0], e1 = sB2[c0 + 1];
            float* a0 = acc[nt][0];
            float* a1 = acc[nt][1];
            float p0 = fmaxf(a0[0] + e0, 0.f) * vA + fmaxf(a0[2] + e0, 0.f) * vB
                     + fmaxf(a1[0] + e0, 0.f) * vC + fmaxf(a1[2] + e0, 0.f) * vD;
            float p1 = fmaxf(a0[1] + e1, 0.f) * vA + fmaxf(a0[3] + e1, 0.f) * vB
                     + fmaxf(a1[1] + e1, 0.f) * vC + fmaxf(a1[3] + e1, 0.f) * vD;
            p0 += __shfl_down_sync(0xffffffffu, p0, 16);
            p0 += __shfl_down_sync(0xffffffffu, p0, 8);
            p0 += __shfl_down_sync(0xffffffffu, p0, 4);
            p1 += __shfl_down_sync(0xffffffffu, p1, 16);
            p1 += __shfl_down_sync(0xffffffffu, p1, 8);
            p1 += __shfl_down_sync(0xffffffffu, p1, 4);
            if (tq == 0) {
                sPart[wr * 256 + c0]     = p0;
                sPart[wr * 256 + c0 + 1] = p1;
            }
        }
        // col-256: full warp reduce (warps 0-3 hold rows w*32+lane)
        if (w < 4) {
            float t2 = dval;
            #pragma unroll
            for (int off = 16; off > 0; off >>= 1)
                t2 += __shfl_down_sync(0xffffffffu, t2, off);
            if (lane == 0) sX264[w] = t2;
        }
        asm volatile("cp.async.wait_group 0;" ::: "memory");
        __syncthreads();   // sync2: sPart/sX264 visible; surr(t+1) ready

        // ---- x-stores(t) ----
        if (tid < 256) {
            int e = tid >> 7, j = tid & 127;
            int c = 2 * j, k = 8 + c;
            float v0 = sPart[(2 * e) * 256 + c]     + sPart[(2 * e + 1) * 256 + c];
            float v1 = sPart[(2 * e) * 256 + c + 1] + sPart[(2 * e + 1) * 256 + c + 1];
            int b = b0 + e;
            int R = b & 127;
            uint32_t word = cvt_f16x2(v0, v1);
            if (k < 256) {
                *(uint32_t*)((char*)g_xA + (size_t)(b >> 7) * 69632
                             + R * 544 + ((R >> 2) & 7) * 4 + kwoff(k)) = word;
            } else {
                *(uint32_t*)((char*)g_xAux + (size_t)(b >> 7) * 5120
                             + R * 40 + (kwoff(k) - 512)) = word;
            }
        } else if (tid < 266) {
            int e = (tid - 256) >= 5 ? 1 : 0;
            int idx = (tid - 256) - e * 5;
            int b = b0 + e;
            int R = b & 127;
            if (idx < 4) {
                int kl = 2 * idx;
                float v0 = s[(size_t)b * SROW + kl];
                float v1 = s[(size_t)b * SROW + kl + 1];
                *(uint32_t*)((char*)g_xA + (size_t)(b >> 7) * 69632
                             + R * 544 + ((R >> 2) & 7) * 4 + kwoff(kl)) = cvt_f16x2(v0, v1);
            } else {
                float x264 = sX264[2 * e] + sX264[2 * e + 1];
                *(uint32_t*)((char*)g_xAux + (size_t)(b >> 7) * 5120 + R * 40 + 4) =
                    cvt_f16x2(x264, 0.f);
            }
        }
        // ---- H(t+1), overlapped with the stores above ----
        if (tn < NTILE)
            do_H((const float*)(smem + SM_SURR + (1 - cur) * 4096));
        __syncthreads();   // sync3
        cur ^= 1;
    }
}

// ---------------------------------------------------------------------------
// Q head v5 (mma): 128 CTAs x 64 rows, 512 threads, warp grid 2M x 8N.
// ---------------------------------------------------------------------------
__global__ void __launch_bounds__(512, 1) qhead_kernel(
    const float* __restrict__ Qb1, const float* __restrict__ Qw2,
    const float* __restrict__ Qb2, float* __restrict__ out)
{
    extern __shared__ char smem[];
    const int tid = threadIdx.x;
    const int w    = tid >> 5, lane = tid & 31;
    const int wr   = w & 1,   wc   = w >> 1;
    const int tq   = lane >> 2, tm = lane & 3;
    const int blk  = blockIdx.x >> 1;
    const int half = blockIdx.x & 1;

    // B1 slab: linear copy of pre-permuted image
    {
        const uint4* src = (const uint4*)g_B1img;
        uint4* dst = (uint4*)(smem + QSM_B1);
        #pragma unroll
        for (int i = tid; i < 8704; i += 512) dst[i] = src[i];
    }
    // A main + aux: this CTA's 64-row half
    {
        const uint4* src = (const uint4*)((const char*)g_xA
                          + (size_t)blk * 69632 + half * 34816);
        uint4* dst = (uint4*)(smem + QSM_A);
        #pragma unroll
        for (int i = tid; i < 2176; i += 512) dst[i] = src[i];
        const uint4* srcX = (const uint4*)((const char*)g_xAux
                           + (size_t)blk * 5120 + half * 2560);
        uint4* dstX = (uint4*)(smem + QSM_AUX);
        if (tid < 160) dstX[tid] = srcX[tid];
    }
    // B2 slab
    for (int i = tid; i < 31 * 128; i += 512) {
        int n = i >> 7, wd = i & 127;
        int sL = wd >> 3, rem = wd & 7, q = rem >> 1, h2 = rem & 1;
        int k0 = sL * 16 + 2 * (h2 * 4 + q);
        float f0 = 0.f, f1 = 0.f;
        if (n < ADIM) {
            f0 = Qw2[(size_t)k0 * ADIM + n];
            f1 = Qw2[(size_t)(k0 + 1) * ADIM + n];
        }
        *(uint32_t*)(smem + QSM_B2 + n * 544 + wd * 4) = cvt_f16x2(f0, f1);
    }
    if (tid < 256) ((float*)(smem + QSM_QB1))[tid] = Qb1[tid];
    if (tid < 32)  ((float*)(smem + QSM_QB2))[tid] = (tid < ADIM) ? Qb2[tid] : 0.f;
    __syncthreads();

    int abase[2][2];
    #pragma unroll
    for (int mt = 0; mt < 2; mt++)
        #pragma unroll
        for (int rr = 0; rr < 2; rr++) {
            int row = wr * 32 + mt * 16 + rr * 8 + tq;
            abase[mt][rr] = row * 544 + ((row >> 2) & 7) * 4 + tm * 8;
        }

    // ---- layer 1: 16 main + 1 aux ksteps; warp = 32 rows x 32 cols ----
    float acc[4][2][4];
    #pragma unroll
    for (int nt = 0; nt < 4; nt++)
        #pragma unroll
        for (int mt = 0; mt < 2; mt++)
            #pragma unroll
            for (int c = 0; c < 4; c++) acc[nt][mt][c] = 0.f;

    #pragma unroll 2
    for (int sg = 0; sg < 16; sg++) {
        uint32_t Ah[2][2][2];
        #pragma unroll
        for (int mt = 0; mt < 2; mt++)
            #pragma unroll
            for (int rr = 0; rr < 2; rr++) {
                int off = abase[mt][rr] + sg * 32;
                Ah[mt][rr][0] = *(const uint32_t*)(smem + QSM_A + off);
                Ah[mt][rr][1] = *(const uint32_t*)(smem + QSM_A + off + 4);
            }
        #pragma unroll
        for (int nt = 0; nt < 4; nt++) {
            int n = wc * 32 + nt * 8 + tq;
            uint2 Bh = *(const uint2*)(smem + QSM_B1 + n * 544 + sg * 32 + tm * 8);
            #pragma unroll
            for (int mt = 0; mt < 2; mt++) {
                float* c = acc[nt][mt];
                mma_f16(c[0], c[1], c[2], c[3],
                        Ah[mt][0][0], Ah[mt][1][0], Ah[mt][0][1], Ah[mt][1][1],
                        Bh.x, Bh.y);
            }
        }
    }
    {   // aux kstep
        uint32_t Ah[2][2][2];
        #pragma unroll
        for (int mt = 0; mt < 2; mt++)
            #pragma unroll
            for (int rr = 0; rr < 2; rr++) {
                int row = wr * 32 + mt * 16 + rr * 8 + tq;
                int off = row * 40 + tm * 8;
                Ah[mt][rr][0] = *(const uint32_t*)(smem + QSM_AUX + off);
                Ah[mt][rr][1] = *(const uint32_t*)(smem + QSM_AUX + off + 4);
            }
        #pragma unroll
        for (int nt = 0; nt < 4; nt++) {
            int n = wc * 32 + nt * 8 + tq;
            uint2 Bh = *(const uint2*)(smem + QSM_B1 + n * 544 + 512 + tm * 8);
            #pragma unroll
            for (int mt = 0; mt < 2; mt++) {
                float* c = acc[nt][mt];
                mma_f16(c[0], c[1], c[2], c[3],
                        Ah[mt][0][0], Ah[mt][1][0], Ah[mt][0][1], Ah[mt][1][1],
                        Bh.x, Bh.y);
            }
        }
    }
    __syncthreads();   // A reads done; slab reusable as A2

    // ---- bias + relu -> fp16 A2 (in place) ----
    {
        const float* qb1 = (const float*)(smem + QSM_QB1);
        #pragma unroll
        for (int nt = 0; nt < 4; nt++)
            #pragma unroll
            for (int mt = 0; mt < 2; mt++) {
                int c0 = wc * 32 + nt * 8 + tm * 2;
                float e0 = qb1[c0], e1 = qb1[c0 + 1];
                int R0 = wr * 32 + mt * 16 + tq;
                int R1 = R0 + 8;
                int wo = kwoff(c0);
                float* a = acc[nt][mt];
                *(uint32_t*)(smem + QSM_A + R0 * 544 + ((R0 >> 2) & 7) * 4 + wo) =
                    cvt_f16x2(fmaxf(a[0] + e0, 0.f), fmaxf(a[1] + e1, 0.f));
                *(uint32_t*)(smem + QSM_A + R1 * 544 + ((R1 >> 2) & 7) * 4 + wo) =
                    cvt_f16x2(fmaxf(a[2] + e0, 0.f), fmaxf(a[3] + e1, 0.f));
            }
    }
    __syncthreads();

    // ---- layer 2: warps wc<4, 32 rows x 8 cols, 16 ksteps ----
    if (wc < 4) {
        float a2[2][4];
        #pragma unroll
        for (int mt = 0; mt < 2; mt++)
            #pragma unroll
            for (int c = 0; c < 4; c++) a2[mt][c] = 0.f;

        #pragma unroll 4
        for (int sg = 0; sg < 16; sg++) {
            uint32_t Ah[2][2][2];
            #pragma unroll
            for (int mt = 0; mt < 2; mt++)
                #pragma unroll
                for (int rr = 0; rr < 2; rr++) {
                    int off = abase[mt][rr] + sg * 32;
                    Ah[mt][rr][0] = *(const uint32_t*)(smem + QSM_A + off);
                    Ah[mt][rr][1] = *(const uint32_t*)(smem + QSM_A + off + 4);
                }
            int n2 = wc * 8 + tq;
            uint2 Bh = *(const uint2*)(smem + QSM_B2 + n2 * 544 + sg * 32 + tm * 8);
            #pragma unroll
            for (int mt = 0; mt < 2; mt++) {
                float* c = a2[mt];
                mma_f16(c[0], c[1], c[2], c[3],
                        Ah[mt][0][0], Ah[mt][1][0], Ah[mt][0][1], Ah[mt][1][1],
                        Bh.x, Bh.y);
            }
        }
        const float* qb2 = (const float*)(smem + QSM_QB2);
        const int cg = wc * 8 + tm * 2;
        const size_t gb = (size_t)blockIdx.x * 64;
        #pragma unroll
        for (int mt = 0; mt < 2; mt++) {
            int row = wr * 32 + mt * 16 + tq;
            if (cg < ADIM) {
                out[(gb + row) * ADIM + cg]     = a2[mt][0] + qb2[cg];
                out[(gb + row + 8) * ADIM + cg] = a2[mt][2] + qb2[cg];
            }
            if (cg + 1 < ADIM) {
                out[(gb + row) * ADIM + cg + 1]     = a2[mt][1] + qb2[cg + 1];
                out[(gb + row + 8) * ADIM + cg + 1] = a2[mt][3] + qb2[cg + 1];
            }
        }
    }
}

// ---------------------------------------------------------------------------
extern "C" void kernel_launch(void* const* d_in, const int* in_sizes, int n_in,
                              void* d_out, int out_size)
{
    const float* s   = (const float*)d_in[0];
    const float* W1  = (const float*)d_in[1];
    const float* b1  = (const float*)d_in[2];
    const float* W2  = (const float*)d_in[3];
    const float* b2  = (const float*)d_in[4];
    const float* Qw1 = (const float*)d_in[5];
    const float* Qb1 = (const float*)d_in[6];
    const float* Qw2 = (const float*)d_in[7];
    const float* Qb2 = (const float*)d_in[8];
    float* out = (float*)d_out;

    cudaFuncSetAttribute(enc_kernel,
                         cudaFuncAttributeMaxDynamicSharedMemorySize, SM_TOTAL);
    cudaFuncSetAttribute(qhead_kernel,
                         cudaFuncAttributeMaxDynamicSharedMemorySize, QSM_TOT);

    qprep_kernel<<<256, 160>>>(Qw1);
    enc_kernel<<<NCTA, 512, SM_TOTAL>>>(s, W1, b1, W2, b2);
    qhead_kernel<<<BATCH / 64, 512, QSM_TOT>>>(Qb1, Qw2, Qb2, out);
}

// round 17
// speedup vs baseline: 12.1190x; 1.0108x over previous
#include <cuda_runtime.h>
#include <cuda_fp16.h>
#include <cstdint>

#define BATCH 8192
#define CAR   8
#define HID   256
#define QIN   265
#define ADIM  30
#define SROW  520
#define NCTA  152
#define NTILE 4096

// ---- enc smem offsets (bytes) ----
#define SM_BHI   0         // 256n x 544B fp16 W2 B slab = 139264
#define SM_HHI   139264    // 128r x 544B fp16 H, rotated rows = 69632
#define SM_W1B   208896    // 256n x 32B fp16 W1 B slab (k0..7 + bias@k8) = 8192
#define SM_B2    217088    // 257 floats -> pad 1040
#define SM_WLAST 218128    // 1024
#define SM_SURR  219152    // 2 bufs x 4096 (16B-aligned); consumed buf doubles as sPart
#define SM_VALID 227344    // 512
#define SM_X264  227856    // 16
#define SM_DOTP  227872    // 4 groups x 128 rows = 2048
#define SM_TOTAL 229920

// ---- qhead smem offsets (bytes) ----
#define QSM_B1   0         // 256n x 544B fp16 Qw1 slab (17 ksteps) = 139264
#define QSM_A    139264    // 64r x 544B fp16 x main slab            = 34816
#define QSM_AUX  174080    // 64r x 40B fp16 x aux                   = 2560
#define QSM_B2   176640    // 31n x 544B fp16 Qw2 slab               = 16864
#define QSM_QB1  193504    // 1024
#define QSM_QB2  194528    // 128
#define QSM_TOT  194656

__device__ __align__(16) uint32_t g_xA[64 * 128 * 136];
__device__ __align__(16) uint32_t g_xAux[64 * 128 * 10];
__device__ __align__(16) uint32_t g_B1img[256 * 136];   // fp16 permuted Qw1 slab image

// ---------------------------------------------------------------------------
__device__ __forceinline__ uint32_t cvt_f16x2(float lo, float hi) {
    uint32_t u;
    asm("cvt.rn.f16x2.f32 %0, %1, %2;" : "=r"(u) : "f"(hi), "f"(lo));
    return u;
}
__device__ __forceinline__ void mma_f16(float& c0, float& c1, float& c2, float& c3,
                                        uint32_t a0, uint32_t a1, uint32_t a2, uint32_t a3,
                                        uint32_t b0, uint32_t b1) {
    asm volatile(
        "mma.sync.aligned.m16n8k16.row.col.f32.f16.f16.f32 "
        "{%0,%1,%2,%3}, {%4,%5,%6,%7}, {%8,%9}, {%0,%1,%2,%3};"
        : "+f"(c0), "+f"(c1), "+f"(c2), "+f"(c3)
        : "r"(a0), "r"(a1), "r"(a2), "r"(a3), "r"(b0), "r"(b1));
}
__device__ __forceinline__ int kwoff(int kl) {
    int sL = kl >> 4, j8 = (kl & 15) >> 1;
    return (sL * 8 + (j8 & 3) * 2 + (j8 >> 2)) * 4;
}
__device__ __forceinline__ void cp_async16(uint32_t smem_addr, const void* gptr) {
    asm volatile("cp.async.ca.shared.global [%0], [%1], 16;"
                 :: "r"(smem_addr), "l"(gptr) : "memory");
}
__device__ __forceinline__ uint32_t smem_u32(const void* p) {
    uint32_t a;
    asm("{ .reg .u64 t; cvta.to.shared.u64 t, %1; cvt.u32.u64 %0, t; }"
        : "=r"(a) : "l"(p));
    return a;
}

// ---------------------------------------------------------------------------
// encoder: CTA owns full N=256, grid-stride. H(t+1) overlapped with stores(t).
// CTAs 0-63 also build the qhead Qw1 slab image (4 rows each).
// ---------------------------------------------------------------------------
__global__ void __launch_bounds__(512, 1) enc_kernel(
    const float* __restrict__ s, const float* __restrict__ W1,
    const float* __restrict__ b1, const float* __restrict__ W2,
    const float* __restrict__ b2, const float* __restrict__ Qw1)
{
    extern __shared__ char smem[];
    const int tid = threadIdx.x;
    const int w    = tid >> 5, lane = tid & 31;
    const int wr   = w & 3,   wc   = w >> 2;
    const int tq   = lane >> 2, tm = lane & 3;

    float* sB2    = (float*)(smem + SM_B2);
    float* sWlast = (float*)(smem + SM_WLAST);
    float* sValid = (float*)(smem + SM_VALID);
    float* sX264  = (float*)(smem + SM_X264);
    float* sDotp  = (float*)(smem + SM_DOTP);
    const uint32_t surrBase = smem_u32(smem + SM_SURR);

    // ---- prologue ----
    for (int i = tid; i < 32768; i += 512) {
        int word = i >> 8, n = i & 255;
        int sL = word >> 3, rem = word & 7, q = rem >> 1, h2 = rem & 1;
        int k0 = sL * 16 + 2 * (h2 * 4 + q);
        float f0 = W2[(size_t)k0 * 257 + n];
        float f1 = W2[(size_t)(k0 + 1) * 257 + n];
        *(uint32_t*)(smem + SM_BHI + n * 544 + word * 4) = cvt_f16x2(f0, f1);
    }
    if (tid < 256) {
        int n = tid;
        uint32_t wv[8];
        wv[0] = cvt_f16x2(W1[0 * HID + n], W1[1 * HID + n]);
        wv[2] = cvt_f16x2(W1[2 * HID + n], W1[3 * HID + n]);
        wv[4] = cvt_f16x2(W1[4 * HID + n], W1[5 * HID + n]);
        wv[6] = cvt_f16x2(W1[6 * HID + n], W1[7 * HID + n]);
        wv[1] = cvt_f16x2(b1[n], 0.f);
        wv[3] = wv[5] = wv[7] = 0u;
        uint4* dst = (uint4*)(smem + SM_W1B + n * 32);
        dst[0] = make_uint4(wv[0], wv[1], wv[2], wv[3]);
        dst[1] = make_uint4(wv[4], wv[5], wv[6], wv[7]);
        sWlast[n] = W2[(size_t)n * 257 + 256];
    }
    for (int i = tid; i < 257; i += 512) sB2[i] = b2[i];

    // build qhead Qw1 slab image (CTAs 0-63, 4 rows each; qhead runs after enc)
    if (blockIdx.x < 64) {
        for (int i = tid; i < 544; i += 512) {
            int n = blockIdx.x * 4 + i / 136;
            int wd = i % 136;
            int sL = wd >> 3, rem = wd & 7, q = rem >> 1, h2 = rem & 1;
            int k0 = sL * 16 + 2 * (h2 * 4 + q);
            float f0 = (k0 < QIN)     ? Qw1[(size_t)k0 * HID + n]       : 0.f;
            float f1 = (k0 + 1 < QIN) ? Qw1[(size_t)(k0 + 1) * HID + n] : 0.f;
            g_B1img[n * 136 + wd] = cvt_f16x2(f0, f1);
        }
    }

    // first surr prefetch -> buf0
    if (tid < 256) {
        int e = tid >> 7, j = tid & 127;
        cp_async16(surrBase + (e * 128 + j) * 16,
                   s + (size_t)(blockIdx.x * 2 + e) * SROW + CAR + j * 4);
    }
    asm volatile("cp.async.commit_group;" ::: "memory");
    asm volatile("cp.async.wait_group 0;" ::: "memory");
    __syncthreads();

    int abase[2][2];
    #pragma unroll
    for (int mt = 0; mt < 2; mt++)
        #pragma unroll
        for (int rr = 0; rr < 2; rr++) {
            int row = wr * 32 + mt * 16 + rr * 8 + tq;
            abase[mt][rr] = row * 544 + ((row >> 2) & 7) * 4 + tm * 8;
        }

    // H phase (valid + H-MMA + col-256 dot partials) from given surr buffer
    auto do_H = [&](const float* sS) {
        if (tid < 128) {
            float4 q0 = ((const float4*)sS)[tid * 2];
            float4 q1 = ((const float4*)sS)[tid * 2 + 1];
            float v = 1.0f;
            if (q0.x == -1.f || q0.y == -1.f || q0.z == -1.f || q0.w == -1.f ||
                q1.x == -1.f || q1.y == -1.f || q1.z == -1.f || q1.w == -1.f) v = 0.f;
            sValid[tid] = v;
        }
        uint32_t A0[2], A1[2];
        #pragma unroll
        for (int mt = 0; mt < 2; mt++) {
            int row0 = wr * 32 + mt * 16 + tq;
            float2 v0 = *(const float2*)(sS + row0 * 8 + tm * 2);
            float2 v1 = *(const float2*)(sS + (row0 + 8) * 8 + tm * 2);
            A0[mt] = cvt_f16x2(v0.x, v0.y);
            A1[mt] = cvt_f16x2(v1.x, v1.y);
        }
        const uint32_t A23 = (tm == 0) ? 0x00003C00u : 0u;  // (1.0, 0) fp16

        float hacc[8][2][4];
        #pragma unroll
        for (int nt = 0; nt < 8; nt++)
            #pragma unroll
            for (int mt = 0; mt < 2; mt++)
                #pragma unroll
                for (int c = 0; c < 4; c++) hacc[nt][mt][c] = 0.f;
        #pragma unroll
        for (int nt = 0; nt < 8; nt++) {
            int n = wc * 64 + nt * 8 + tq;
            uint2 Bh = *(const uint2*)(smem + SM_W1B + n * 32 + tm * 8);
            #pragma unroll
            for (int mt = 0; mt < 2; mt++) {
                float* c = hacc[nt][mt];
                mma_f16(c[0], c[1], c[2], c[3], A0[mt], A1[mt], A23, A23, Bh.x, Bh.y);
            }
        }
        float dotr[4] = {0.f, 0.f, 0.f, 0.f};
        #pragma unroll
        for (int nt = 0; nt < 8; nt++) {
            int kb = wc * 64 + nt * 8 + tm * 2;
            float2 wl = *(const float2*)(sWlast + kb);
            int wo = kwoff(kb);
            #pragma unroll
            for (int mt = 0; mt < 2; mt++) {
                float h0 = fmaxf(hacc[nt][mt][0], 0.f);
                float h1 = fmaxf(hacc[nt][mt][1], 0.f);
                float h2 = fmaxf(hacc[nt][mt][2], 0.f);
                float h3 = fmaxf(hacc[nt][mt][3], 0.f);
                dotr[mt * 2]     = fmaf(h0, wl.x, fmaf(h1, wl.y, dotr[mt * 2]));
                dotr[mt * 2 + 1] = fmaf(h2, wl.x, fmaf(h3, wl.y, dotr[mt * 2 + 1]));
                int R0 = wr * 32 + mt * 16 + tq, R1 = R0 + 8;
                *(uint32_t*)(smem + SM_HHI + R0 * 544 + ((R0 >> 2) & 7) * 4 + wo) =
                    cvt_f16x2(h0, h1);
                *(uint32_t*)(smem + SM_HHI + R1 * 544 + ((R1 >> 2) & 7) * 4 + wo) =
                    cvt_f16x2(h2, h3);
            }
        }
        #pragma unroll
        for (int i = 0; i < 4; i++) {
            dotr[i] += __shfl_xor_sync(0xffffffffu, dotr[i], 1);
            dotr[i] += __shfl_xor_sync(0xffffffffu, dotr[i], 2);
        }
        if (tm == 0) {
            #pragma unroll
            for (int mt = 0; mt < 2; mt++) {
                int R0 = wr * 32 + mt * 16 + tq;
                sDotp[wc * 128 + R0]     = dotr[mt * 2];
                sDotp[wc * 128 + R0 + 8] = dotr[mt * 2 + 1];
            }
        }
    };

    // preloop: H for first tile
    do_H((const float*)(smem + SM_SURR));
    __syncthreads();

    int cur = 0;
    for (int tt = blockIdx.x; tt < NTILE; tt += NCTA) {
        const int b0 = tt * 2;
        const int tn = tt + NCTA;

        // prefetch surr(t+1) -> other buffer
        if (tid < 256 && tn < NTILE) {
            int e = tid >> 7, j = tid & 127;
            cp_async16(surrBase + (1 - cur) * 4096 + (e * 128 + j) * 16,
                       s + (size_t)(tn * 2 + e) * SROW + CAR + j * 4);
        }
        asm volatile("cp.async.commit_group;" ::: "memory");

        // ---- main MMA: 16 ksteps ----
        float acc[8][2][4];
        #pragma unroll
        for (int nt = 0; nt < 8; nt++)
            #pragma unroll
            for (int mt = 0; mt < 2; mt++)
                #pragma unroll
                for (int c = 0; c < 4; c++) acc[nt][mt][c] = 0.f;

        #pragma unroll 4
        for (int sg = 0; sg < 16; sg++) {
            uint32_t Ah[2][2][2];
            #pragma unroll
            for (int mt = 0; mt < 2; mt++)
                #pragma unroll
                for (int rr = 0; rr < 2; rr++) {
                    int off = abase[mt][rr] + sg * 32;
                    Ah[mt][rr][0] = *(const uint32_t*)(smem + SM_HHI + off);
                    Ah[mt][rr][1] = *(const uint32_t*)(smem + SM_HHI + off + 4);
                }
            #pragma unroll
            for (int nt = 0; nt < 8; nt++) {
                int n = wc * 64 + nt * 8 + tq;
                uint2 Bh = *(const uint2*)(smem + SM_BHI + n * 544 + sg * 32 + tm * 8);
                #pragma unroll
                for (int mt = 0; mt < 2; mt++) {
                    float* c = acc[nt][mt];
                    mma_f16(c[0], c[1], c[2], c[3],
                            Ah[mt][0][0], Ah[mt][1][0], Ah[mt][0][1], Ah[mt][1][1],
                            Bh.x, Bh.y);
                }
            }
        }
        __syncthreads();   // sync1: H(t) reads done

        // ---- snapshot (reads that H(t+1) will clobber) ----
        const float vA = sValid[wr * 32 + tq];
        const float vB = sValid[wr * 32 + tq + 8];
        const float vC = sValid[wr * 32 + tq + 16];
        const float vD = sValid[wr * 32 + tq + 24];
        float dval = 0.f;
        if (tid < 128) {
            float dsum = sDotp[tid] + sDotp[128 + tid]
                       + sDotp[256 + tid] + sDotp[384 + tid];
            dval = fmaxf(dsum + sB2[256], 0.f) * sValid[tid];
        }

        // ---- compress acc -> sPart (aliases consumed surr buffer) ----
        float* sPart = (float*)(smem + SM_SURR + cur * 4096);
        #pragma unroll
        for (int nt = 0; nt < 8; nt++) {
            int c0 = wc * 64 + nt * 8 + tm * 2;
            float e0 = sB2[c0], e1 = sB2[c0 + 1];
            float* a0 = acc[nt][0];
            float* a1 = acc[nt][1];
            float p0 = fmaxf(a0[0] + e0, 0.f) * vA + fmaxf(a0[2] + e0, 0.f) * vB
                     + fmaxf(a1[0] + e0, 0.f) * vC + fmaxf(a1[2] + e0, 0.f) * vD;
            float p1 = fmaxf(a0[1] + e1, 0.f) * vA + fmaxf(a0[3] + e1, 0.f) * vB
                     + fmaxf(a1[1] + e1, 0.f) * vC + fmaxf(a1[3] + e1, 0.f) * vD;
            p0 += __shfl_down_sync(0xffffffffu, p0, 16);
            p0 += __shfl_down_sync(0xffffffffu, p0, 8);
            p0 += __shfl_down_sync(0xffffffffu, p0, 4);
            p1 += __shfl_down_sync(0xffffffffu, p1, 16);
            p1 += __shfl_down_sync(0xffffffffu, p1, 8);
            p1 += __shfl_down_sync(0xffffffffu, p1, 4);
            if (tq == 0) {
                sPart[wr * 256 + c0]     = p0;
                sPart[wr * 256 + c0 + 1] = p1;
            }
        }
        if (w < 4) {
            float t2 = dval;
            #pragma unroll
            for (int off = 16; off > 0; off >>= 1)
                t2 += __shfl_down_sync(0xffffffffu, t2, off);
            if (lane == 0) sX264[w] = t2;
        }
        asm volatile("cp.async.wait_group 0;" ::: "memory");
        __syncthreads();   // sync2: sPart/sX264 visible; surr(t+1) ready

        // ---- x-stores(t) ----
        if (tid < 256) {
            int e = tid >> 7, j = tid & 127;
            int c = 2 * j, k = 8 + c;
            float v0 = sPart[(2 * e) * 256 + c]     + sPart[(2 * e + 1) * 256 + c];
            float v1 = sPart[(2 * e) * 256 + c + 1] + sPart[(2 * e + 1) * 256 + c + 1];
            int b = b0 + e;
            int R = b & 127;
            uint32_t word = cvt_f16x2(v0, v1);
            if (k < 256) {
                *(uint32_t*)((char*)g_xA + (size_t)(b >> 7) * 69632
                             + R * 544 + ((R >> 2) & 7) * 4 + kwoff(k)) = word;
            } else {
                *(uint32_t*)((char*)g_xAux + (size_t)(b >> 7) * 5120
                             + R * 40 + (kwoff(k) - 512)) = word;
            }
        } else if (tid < 266) {
            int e = (tid - 256) >= 5 ? 1 : 0;
            int idx = (tid - 256) - e * 5;
            int b = b0 + e;
            int R = b & 127;
            if (idx < 4) {
                int kl = 2 * idx;
                float v0 = s[(size_t)b * SROW + kl];
                float v1 = s[(size_t)b * SROW + kl + 1];
                *(uint32_t*)((char*)g_xA + (size_t)(b >> 7) * 69632
                             + R * 544 + ((R >> 2) & 7) * 4 + kwoff(kl)) = cvt_f16x2(v0, v1);
            } else {
                float x264 = sX264[2 * e] + sX264[2 * e + 1];
                *(uint32_t*)((char*)g_xAux + (size_t)(b >> 7) * 5120 + R * 40 + 4) =
                    cvt_f16x2(x264, 0.f);
            }
        }
        // ---- H(t+1), overlapped with the stores above ----
        if (tn < NTILE)
            do_H((const float*)(smem + SM_SURR + (1 - cur) * 4096));
        __syncthreads();   // sync3
        cur ^= 1;
    }
}

// ---------------------------------------------------------------------------
// Q head v5 (mma): 128 CTAs x 64 rows, 512 threads, warp grid 2M x 8N.
// ---------------------------------------------------------------------------
__global__ void __launch_bounds__(512, 1) qhead_kernel(
    const float* __restrict__ Qb1, const float* __restrict__ Qw2,
    const float* __restrict__ Qb2, float* __restrict__ out)
{
    extern __shared__ char smem[];
    const int tid = threadIdx.x;
    const int w    = tid >> 5, lane = tid & 31;
    const int wr   = w & 1,   wc   = w >> 1;
    const int tq   = lane >> 2, tm = lane & 3;
    const int blk  = blockIdx.x >> 1;
    const int half = blockIdx.x & 1;

    {
        const uint4* src = (const uint4*)g_B1img;
        uint4* dst = (uint4*)(smem + QSM_B1);
        #pragma unroll
        for (int i = tid; i < 8704; i += 512) dst[i] = src[i];
    }
    {
        const uint4* src = (const uint4*)((const char*)g_xA
                          + (size_t)blk * 69632 + half * 34816);
        uint4* dst = (uint4*)(smem + QSM_A);
        #pragma unroll
        for (int i = tid; i < 2176; i += 512) dst[i] = src[i];
        const uint4* srcX = (const uint4*)((const char*)g_xAux
                           + (size_t)blk * 5120 + half * 2560);
        uint4* dstX = (uint4*)(smem + QSM_AUX);
        if (tid < 160) dstX[tid] = srcX[tid];
    }
    for (int i = tid; i < 31 * 128; i += 512) {
        int n = i >> 7, wd = i & 127;
        int sL = wd >> 3, rem = wd & 7, q = rem >> 1, h2 = rem & 1;
        int k0 = sL * 16 + 2 * (h2 * 4 + q);
        float f0 = 0.f, f1 = 0.f;
        if (n < ADIM) {
            f0 = Qw2[(size_t)k0 * ADIM + n];
            f1 = Qw2[(size_t)(k0 + 1) * ADIM + n];
        }
        *(uint32_t*)(smem + QSM_B2 + n * 544 + wd * 4) = cvt_f16x2(f0, f1);
    }
    if (tid < 256) ((float*)(smem + QSM_QB1))[tid] = Qb1[tid];
    if (tid < 32)  ((float*)(smem + QSM_QB2))[tid] = (tid < ADIM) ? Qb2[tid] : 0.f;
    __syncthreads();

    int abase[2][2];
    #pragma unroll
    for (int mt = 0; mt < 2; mt++)
        #pragma unroll
        for (int rr = 0; rr < 2; rr++) {
            int row = wr * 32 + mt * 16 + rr * 8 + tq;
            abase[mt][rr] = row * 544 + ((row >> 2) & 7) * 4 + tm * 8;
        }

    float acc[4][2][4];
    #pragma unroll
    for (int nt = 0; nt < 4; nt++)
        #pragma unroll
        for (int mt = 0; mt < 2; mt++)
            #pragma unroll
            for (int c = 0; c < 4; c++) acc[nt][mt][c] = 0.f;

    #pragma unroll 4
    for (int sg = 0; sg < 16; sg++) {
        uint32_t Ah[2][2][2];
        #pragma unroll
        for (int mt = 0; mt < 2; mt++)
            #pragma unroll
            for (int rr = 0; rr < 2; rr++) {
                int off = abase[mt][rr] + sg * 32;
                Ah[mt][rr][0] = *(const uint32_t*)(smem + QSM_A + off);
                Ah[mt][rr][1] = *(const uint32_t*)(smem + QSM_A + off + 4);
            }
        #pragma unroll
        for (int nt = 0; nt < 4; nt++) {
            int n = wc * 32 + nt * 8 + tq;
            uint2 Bh = *(const uint2*)(smem + QSM_B1 + n * 544 + sg * 32 + tm * 8);
            #pragma unroll
            for (int mt = 0; mt < 2; mt++) {
                float* c = acc[nt][mt];
                mma_f16(c[0], c[1], c[2], c[3],
                        Ah[mt][0][0], Ah[mt][1][0], Ah[mt][0][1], Ah[mt][1][1],
                        Bh.x, Bh.y);
            }
        }
    }
    {   // aux kstep
        uint32_t Ah[2][2][2];
        #pragma unroll
        for (int mt = 0; mt < 2; mt++)
            #pragma unroll
            for (int rr = 0; rr < 2; rr++) {
                int row = wr * 32 + mt * 16 + rr * 8 + tq;
                int off = row * 40 + tm * 8;
                Ah[mt][rr][0] = *(const uint32_t*)(smem + QSM_AUX + off);
                Ah[mt][rr][1] = *(const uint32_t*)(smem + QSM_AUX + off + 4);
            }
        #pragma unroll
        for (int nt = 0; nt < 4; nt++) {
            int n = wc * 32 + nt * 8 + tq;
            uint2 Bh = *(const uint2*)(smem + QSM_B1 + n * 544 + 512 + tm * 8);
            #pragma unroll
            for (int mt = 0; mt < 2; mt++) {
                float* c = acc[nt][mt];
                mma_f16(c[0], c[1], c[2], c[3],
                        Ah[mt][0][0], Ah[mt][1][0], Ah[mt][0][1], Ah[mt][1][1],
                        Bh.x, Bh.y);
            }
        }
    }
    __syncthreads();

    {
        const float* qb1 = (const float*)(smem + QSM_QB1);
        #pragma unroll
        for (int nt = 0; nt < 4; nt++)
            #pragma unroll
            for (int mt = 0; mt < 2; mt++) {
                int c0 = wc * 32 + nt * 8 + tm * 2;
                float e0 = qb1[c0], e1 = qb1[c0 + 1];
                int R0 = wr * 32 + mt * 16 + tq;
                int R1 = R0 + 8;
                int wo = kwoff(c0);
                float* a = acc[nt][mt];
                *(uint32_t*)(smem + QSM_A + R0 * 544 + ((R0 >> 2) & 7) * 4 + wo) =
                    cvt_f16x2(fmaxf(a[0] + e0, 0.f), fmaxf(a[1] + e1, 0.f));
                *(uint32_t*)(smem + QSM_A + R1 * 544 + ((R1 >> 2) & 7) * 4 + wo) =
                    cvt_f16x2(fmaxf(a[2] + e0, 0.f), fmaxf(a[3] + e1, 0.f));
            }
    }
    __syncthreads();

    if (wc < 4) {
        float a2[2][4];
        #pragma unroll
        for (int mt = 0; mt < 2; mt++)
            #pragma unroll
            for (int c = 0; c < 4; c++) a2[mt][c] = 0.f;

        #pragma unroll 4
        for (int sg = 0; sg < 16; sg++) {
            uint32_t Ah[2][2][2];
            #pragma unroll
            for (int mt = 0; mt < 2; mt++)
                #pragma unroll
                for (int rr = 0; rr < 2; rr++) {
                    int off = abase[mt][rr] + sg * 32;
                    Ah[mt][rr][0] = *(const uint32_t*)(smem + QSM_A + off);
                    Ah[mt][rr][1] = *(const uint32_t*)(smem + QSM_A + off + 4);
                }
            int n2 = wc * 8 + tq;
            uint2 Bh = *(const uint2*)(smem + QSM_B2 + n2 * 544 + sg * 32 + tm * 8);
            #pragma unroll
            for (int mt = 0; mt < 2; mt++) {
                float* c = a2[mt];
                mma_f16(c[0], c[1], c[2], c[3],
                        Ah[mt][0][0], Ah[mt][1][0], Ah[mt][0][1], Ah[mt][1][1],
                        Bh.x, Bh.y);
            }
        }
        const float* qb2 = (const float*)(smem + QSM_QB2);
        const int cg = wc * 8 + tm * 2;
        const size_t gb = (size_t)blockIdx.x * 64;
        #pragma unroll
        for (int mt = 0; mt < 2; mt++) {
            int row = wr * 32 + mt * 16 + tq;
            if (cg < ADIM) {
                out[(gb + row) * ADIM + cg]     = a2[mt][0] + qb2[cg];
                out[(gb + row + 8) * ADIM + cg] = a2[mt][2] + qb2[cg];
            }
            if (cg + 1 < ADIM) {
                out[(gb + row) * ADIM + cg + 1]     = a2[mt][1] + qb2[cg + 1];
                out[(gb + row + 8) * ADIM + cg + 1] = a2[mt][3] + qb2[cg + 1];
            }
        }
    }
}

// ---------------------------------------------------------------------------
extern "C" void kernel_launch(void* const* d_in, const int* in_sizes, int n_in,
                              void* d_out, int out_size)
{
    const float* s   = (const float*)d_in[0];
    const float* W1  = (const float*)d_in[1];
    const float* b1  = (const float*)d_in[2];
    const float* W2  = (const float*)d_in[3];
    const float* b2  = (const float*)d_in[4];
    const float* Qw1 = (const float*)d_in[5];
    const float* Qb1 = (const float*)d_in[6];
    const float* Qw2 = (const float*)d_in[7];
    const float* Qb2 = (const float*)d_in[8];
    float* out = (float*)d_out;

    cudaFuncSetAttribute(enc_kernel,
                         cudaFuncAttributeMaxDynamicSharedMemorySize, SM_TOTAL);
    cudaFuncSetAttribute(qhead_kernel,
                         cudaFuncAttributeMaxDynamicSharedMemorySize, QSM_TOT);

    enc_kernel<<<NCTA, 512, SM_TOTAL>>>(s, W1, b1, W2, b2, Qw1);
    qhead_kernel<<<BATCH / 64, 512, QSM_TOT>>>(Qb1, Qw2, Qb2, out);
}